// round 4
// baseline (speedup 1.0000x reference)
#include <cuda_runtime.h>
#include <cuda_bf16.h>
#include <math.h>
#include <stdint.h>

#define NN 50000
#define EE 800000
#define BB 64
#define HH 128
#define TILES 391   // ceil(50000/128)

// ---------------- scratch (device globals) ----------------
__device__ float g_x   [NN * HH];
__device__ float g_x2  [NN * HH];
__device__ float g_v   [NN * HH];
__device__ float g_scores[NN * 4];
__device__ float g_pooled[BB * HH];
__device__ float g_U[HH * 4];
__device__ float g_cvec[4];
__device__ int   g_deg[NN];
__device__ int   g_off[NN + 1];
__device__ int   g_cur[NN];
__device__ int   g_col[EE];
__device__ int   g_gstart[BB + 1];
// bf16 hi/lo weight planes: 8 matrices x 64KB (hi 32KB then lo 32KB), row-major [n][k]
__device__ uint4 g_wbuf[8 * 4096];

// ---------------- helpers ----------------
__device__ __forceinline__ void hilo(float v, uint32_t& h, uint32_t& l) {
    __nv_bfloat16 hb = __float2bfloat16(v);
    __nv_bfloat16 lb = __float2bfloat16(v - __bfloat162float(hb));
    h = (uint32_t)__bfloat16_as_ushort(hb);
    l = (uint32_t)__bfloat16_as_ushort(lb);
}
__device__ __forceinline__ float2 bf2f(uint32_t u) {
    __nv_bfloat162 h;
    *reinterpret_cast<uint32_t*>(&h) = u;
    return __bfloat1622float2(h);
}
__device__ __forceinline__ uint32_t smem_u32(const void* p) {
    uint32_t a;
    asm("{ .reg .u64 t; cvta.to.shared.u64 t, %1; cvt.u32.u64 %0, t; }" : "=r"(a) : "l"(p));
    return a;
}
__device__ __forceinline__ float warp_sum(float v) {
#pragma unroll
    for (int o = 16; o > 0; o >>= 1) v += __shfl_xor_sync(0xffffffffu, v, o);
    return v;
}

#define HMMA(C, A0, A1, A2, A3, B0, B1) \
    asm volatile("mma.sync.aligned.m16n8k16.row.col.f32.bf16.bf16.f32 " \
                 "{%0,%1,%2,%3}, {%4,%5,%6,%7}, {%8,%9}, {%0,%1,%2,%3};" \
                 : "+f"((C)[0]), "+f"((C)[1]), "+f"((C)[2]), "+f"((C)[3]) \
                 : "r"(A0), "r"(A1), "r"(A2), "r"(A3), "r"(B0), "r"(B1))

#define LDSM4(D0, D1, D2, D3, A) \
    asm volatile("ldmatrix.sync.aligned.m8n8.x4.shared.b16 {%0,%1,%2,%3}, [%4];" \
                 : "=r"(D0), "=r"(D1), "=r"(D2), "=r"(D3) : "r"(A))

// ---------------- weight pre-conversion ----------------
__global__ void k_wconv(const float* w0, const float* w1, const float* w2, const float* w3,
                        const float* w4, const float* w5, const float* w6, const float* w7) {
    int m = blockIdx.x >> 4;
    const float* W;
    switch (m) {
        case 0: W = w0; break; case 1: W = w1; break; case 2: W = w2; break;
        case 3: W = w3; break; case 4: W = w4; break; case 5: W = w5; break;
        case 6: W = w6; break; default: W = w7; break;
    }
    int i = (blockIdx.x & 15) * 256 + threadIdx.x;
    int row = i >> 5, q = i & 31;
    float4 v = *reinterpret_cast<const float4*>(W + (size_t)row * 128 + q * 4);
    uint32_t h0, l0, h1, l1, h2, l2, h3, l3;
    hilo(v.x, h0, l0); hilo(v.y, h1, l1); hilo(v.z, h2, l2); hilo(v.w, h3, l3);
    uint2 uh, ul;
    uh.x = h0 | (h1 << 16); uh.y = h2 | (h3 << 16);
    ul.x = l0 | (l1 << 16); ul.y = l2 | (l3 << 16);
    char* base = (char*)g_wbuf + (size_t)m * 65536;
    int sw = row * 256 + q * 8;
    *reinterpret_cast<uint2*>(base + sw)         = uh;
    *reinterpret_cast<uint2*>(base + 32768 + sw) = ul;
}

// ---------------- SMEM layout ----------------
#define ROWB    272
#define OFF_AH  0
#define OFF_AL  34816
#define OFF_WH  69632
#define OFF_WL  104448
#define OFF_BIAS 139264
#define OFF_G    139776
#define OFF_BETA 140288
#define OFF_MEAN 140800
#define OFF_RSTD 141312
#define OFF_U    141824
#define OFF_CV   143872
#define SMEM_BYTES 143904
// C spill: 128 x 129 floats at OFF_WH (66048 <= 69632)

__device__ __forceinline__ void fill_A(const float* __restrict__ A, char* smem,
                                       int tile0, int nrows, int t) {
    char* ah = smem + OFF_AH;
    char* al = smem + OFF_AL;
    for (int i = t; i < 4096; i += 256) {
        int row = i >> 5, q = i & 31;
        int grow = tile0 + row;
        float4 v = make_float4(0.f, 0.f, 0.f, 0.f);
        if (grow < nrows) v = *reinterpret_cast<const float4*>(A + (size_t)grow * HH + q * 4);
        uint32_t h0, l0, h1, l1, h2, l2, h3, l3;
        hilo(v.x, h0, l0); hilo(v.y, h1, l1); hilo(v.z, h2, l2); hilo(v.w, h3, l3);
        uint2 uh, ul;
        uh.x = h0 | (h1 << 16); uh.y = h2 | (h3 << 16);
        ul.x = l0 | (l1 << 16); ul.y = l2 | (l3 << 16);
        int d = row * ROWB + q * 8;
        *reinterpret_cast<uint2*>(ah + d) = uh;
        *reinterpret_cast<uint2*>(al + d) = ul;
    }
}

// gather neighbor-mean directly into A planes (bf16 hi/lo)
__device__ __forceinline__ void fill_A_gather(const float* __restrict__ x, char* smem,
                                              int tile0, int nrows, int wid, int lane) {
    char* ah = smem + OFF_AH;
    char* al = smem + OFF_AL;
    for (int rr = 0; rr < 16; ++rr) {
        int row = wid * 16 + rr;
        int node = tile0 + row;
        int s0 = 0, s1 = 0;
        if (node < nrows) { s0 = g_off[node]; s1 = g_off[node + 1]; }
        float4 a = make_float4(0.f, 0.f, 0.f, 0.f);
        for (int i = s0; i < s1; ++i) {
            int nb = __ldg(&g_col[i]);
            float4 xv = __ldg(reinterpret_cast<const float4*>(x + (size_t)nb * HH) + lane);
            a.x += xv.x; a.y += xv.y; a.z += xv.z; a.w += xv.w;
        }
        float inv = 1.f / fmaxf((float)(s1 - s0), 1.f);
        a.x *= inv; a.y *= inv; a.z *= inv; a.w *= inv;
        uint32_t h0, l0, h1, l1, h2, l2, h3, l3;
        hilo(a.x, h0, l0); hilo(a.y, h1, l1); hilo(a.z, h2, l2); hilo(a.w, h3, l3);
        uint2 uh, ul;
        uh.x = h0 | (h1 << 16); uh.y = h2 | (h3 << 16);
        ul.x = l0 | (l1 << 16); ul.y = l2 | (l3 << 16);
        int d = row * ROWB + lane * 8;
        *reinterpret_cast<uint2*>(ah + d) = uh;
        *reinterpret_cast<uint2*>(al + d) = ul;
    }
}

__device__ __forceinline__ void fill_W(int slot, char* smem, int t) {
    const char* src = (const char*)g_wbuf + (size_t)slot * 65536;
    for (int i = t; i < 2048; i += 256) {
        int row = i >> 4, q = i & 15;
        int d = row * ROWB + q * 16;
        *reinterpret_cast<uint4*>(smem + OFF_WH + d) =
            *reinterpret_cast<const uint4*>(src + i * 16);
        *reinterpret_cast<uint4*>(smem + OFF_WL + d) =
            *reinterpret_cast<const uint4*>(src + 32768 + i * 16);
    }
}

// MODE: 0 = input proj (bias+relu), 1 = SAGE (gather pass + root pass, LN+relu+residual),
//       2 = V proj (bias) + fused attention scores
template <int MODE>
__global__ void __launch_bounds__(256) k_mma(
    const float* __restrict__ A1, int wslot,
    const float* __restrict__ bias,
    const float* __restrict__ lng, const float* __restrict__ lnb,
    float* __restrict__ out, int nrows)
{
    extern __shared__ char smem[];
    uint32_t sb = smem_u32(smem);
    int t = threadIdx.x, wid = t >> 5, lane = t & 31;
    int tile0 = blockIdx.x * 128;
    int wm = wid & 1, wn = wid >> 1;
    const int NPASS = (MODE == 1) ? 2 : 1;

    if (t < 128) {
        ((float*)(smem + OFF_BIAS))[t] = bias[t];
        if (MODE == 1) {
            ((float*)(smem + OFF_G))[t]    = lng[t];
            ((float*)(smem + OFF_BETA))[t] = lnb[t];
        }
    }
    if (MODE == 2) {
        for (int i = t; i < 512; i += 256) ((float*)(smem + OFF_U))[i] = g_U[i];
        if (t < 4) ((float*)(smem + OFF_CV))[t] = g_cvec[t];
    }

    float c[4][4][4];
#pragma unroll
    for (int mb = 0; mb < 4; ++mb)
#pragma unroll
        for (int nb = 0; nb < 4; ++nb)
#pragma unroll
            for (int j = 0; j < 4; ++j) c[mb][nb][j] = 0.f;

    // ldmatrix lane addresses
    uint32_t aA = sb + OFF_AH + (uint32_t)(wm * 64 + (lane & 15)) * ROWB + ((lane >> 4) * 16);
    uint32_t aB = sb + OFF_WH + (uint32_t)(wn * 32 + lane) * ROWB;

#pragma unroll
    for (int p = 0; p < NPASS; ++p) {
        if (MODE == 1 && p == 0)
            fill_A_gather(A1, smem, tile0, nrows, wid, lane);
        else
            fill_A(A1, smem, tile0, nrows, t);
        fill_W(wslot + p, smem, t);
        __syncthreads();

#pragma unroll
        for (int ks = 0; ks < 8; ++ks) {
            uint32_t k2 = ks * 32;  // bytes
            uint32_t bh0[4], bh1[4], bl0[4], bl1[4];
            LDSM4(bh0[0], bh0[1], bh0[2], bh0[3], aB + k2);
            LDSM4(bh1[0], bh1[1], bh1[2], bh1[3], aB + k2 + 16);
            LDSM4(bl0[0], bl0[1], bl0[2], bl0[3], aB + (OFF_WL - OFF_WH) + k2);
            LDSM4(bl1[0], bl1[1], bl1[2], bl1[3], aB + (OFF_WL - OFF_WH) + k2 + 16);
#pragma unroll
            for (int mb = 0; mb < 4; ++mb) {
                uint32_t ah0, ah1, ah2, ah3, al0, al1, al2, al3;
                uint32_t am = aA + (uint32_t)(mb * 16) * ROWB + k2;
                LDSM4(ah0, ah1, ah2, ah3, am);
                LDSM4(al0, al1, al2, al3, am + (OFF_AL - OFF_AH));
#pragma unroll
                for (int nb = 0; nb < 4; ++nb) {
                    HMMA(c[mb][nb], ah0, ah1, ah2, ah3, bh0[nb], bh1[nb]);
                    HMMA(c[mb][nb], ah0, ah1, ah2, ah3, bl0[nb], bl1[nb]);
                    HMMA(c[mb][nb], al0, al1, al2, al3, bh0[nb], bh1[nb]);
                }
            }
        }
        __syncthreads();
    }

    // spill C into the W region (preserve A planes), stride 129 floats
    float* Csm = (float*)(smem + OFF_WH);
    int g = lane >> 2, tt = lane & 3;
#pragma unroll
    for (int mb = 0; mb < 4; ++mb) {
        int r0 = wm * 64 + mb * 16 + g;
#pragma unroll
        for (int nb = 0; nb < 4; ++nb) {
            int col = wn * 32 + nb * 8 + tt * 2;
            Csm[r0 * 129 + col]           = c[mb][nb][0];
            Csm[r0 * 129 + col + 1]       = c[mb][nb][1];
            Csm[(r0 + 8) * 129 + col]     = c[mb][nb][2];
            Csm[(r0 + 8) * 129 + col + 1] = c[mb][nb][3];
        }
    }
    __syncthreads();

    const float* bs = (const float*)(smem + OFF_BIAS);
    if (MODE == 1) {
        if (t < 128) {
            const float* crow = Csm + t * 129;
            float sum = 0.f, sq = 0.f;
#pragma unroll
            for (int j = 0; j < 128; ++j) {
                float x = crow[j] + bs[j];
                sum += x; sq += x * x;
            }
            float mean = sum * (1.f / 128.f);
            float var  = sq * (1.f / 128.f) - mean * mean;
            ((float*)(smem + OFF_MEAN))[t] = mean;
            ((float*)(smem + OFF_RSTD))[t] = rsqrtf(var + 1e-5f);
        }
        __syncthreads();
    }

    const float* gg = (const float*)(smem + OFF_G);
    const float* bb = (const float*)(smem + OFF_BETA);
    const float* mn = (const float*)(smem + OFF_MEAN);
    const float* rs = (const float*)(smem + OFF_RSTD);
    for (int i = t; i < 4096; i += 256) {
        int row = i >> 5, q = i & 31;
        int grow = tile0 + row;
        if (grow >= nrows) continue;
        int base = row * 129 + q * 4;
        float x0 = Csm[base + 0] + bs[q * 4 + 0];
        float x1 = Csm[base + 1] + bs[q * 4 + 1];
        float x2 = Csm[base + 2] + bs[q * 4 + 2];
        float x3 = Csm[base + 3] + bs[q * 4 + 3];
        float4 o;
        if (MODE == 1) {
            float mean = mn[row], rstd = rs[row];
            // residual reconstructed from A planes (pass-2 tile == cur rows)
            int d = row * ROWB + q * 8;
            uint2 uh = *reinterpret_cast<const uint2*>(smem + OFF_AH + d);
            uint2 ul = *reinterpret_cast<const uint2*>(smem + OFF_AL + d);
            float2 hxy = bf2f(uh.x), hzw = bf2f(uh.y);
            float2 lxy = bf2f(ul.x), lzw = bf2f(ul.y);
            o.x = fmaxf((x0 - mean) * rstd * gg[q*4+0] + bb[q*4+0], 0.f) + (hxy.x + lxy.x);
            o.y = fmaxf((x1 - mean) * rstd * gg[q*4+1] + bb[q*4+1], 0.f) + (hxy.y + lxy.y);
            o.z = fmaxf((x2 - mean) * rstd * gg[q*4+2] + bb[q*4+2], 0.f) + (hzw.x + lzw.x);
            o.w = fmaxf((x3 - mean) * rstd * gg[q*4+3] + bb[q*4+3], 0.f) + (hzw.y + lzw.y);
        } else if (MODE == 0) {
            o.x = fmaxf(x0, 0.f); o.y = fmaxf(x1, 0.f);
            o.z = fmaxf(x2, 0.f); o.w = fmaxf(x3, 0.f);
        } else {
            o.x = x0; o.y = x1; o.z = x2; o.w = x3;
        }
        *reinterpret_cast<float4*>(out + (size_t)grow * HH + q * 4) = o;
    }

    if (MODE == 2) {
        // fused attention scores from A planes: scores = x @ U + cvec
        if (t < 128) {
            int grow = tile0 + t;
            if (grow < nrows) {
                const uint32_t* pa = (const uint32_t*)(smem + OFF_AH + t * ROWB);
                const uint32_t* pl = (const uint32_t*)(smem + OFF_AL + t * ROWB);
                const float4* U4 = (const float4*)(smem + OFF_U);
                const float* cv = (const float*)(smem + OFF_CV);
                float a0 = cv[0], a1 = cv[1], a2 = cv[2], a3 = cv[3];
#pragma unroll
                for (int kk = 0; kk < 64; ++kk) {
                    float2 h = bf2f(pa[kk]);
                    float2 l = bf2f(pl[kk]);
                    float x0 = h.x + l.x, x1 = h.y + l.y;
                    float4 u0 = U4[2 * kk];
                    float4 u1 = U4[2 * kk + 1];
                    a0 += x0 * u0.x + x1 * u1.x;
                    a1 += x0 * u0.y + x1 * u1.y;
                    a2 += x0 * u0.z + x1 * u1.z;
                    a3 += x0 * u0.w + x1 * u1.w;
                }
                float4 r; r.x = a0; r.y = a1; r.z = a2; r.w = a3;
                reinterpret_cast<float4*>(g_scores)[grow] = r;
            }
        }
    }
}

// ---------------- CSR build ----------------
__global__ void k_init() {
    int i = blockIdx.x * blockDim.x + threadIdx.x;
    if (i < NN) { g_deg[i] = 0; g_cur[i] = 0; }
}
__global__ void k_deg(const int* __restrict__ ei) {
    int e = blockIdx.x * blockDim.x + threadIdx.x;
    if (e < EE) atomicAdd(&g_deg[ei[EE + e]], 1);
}
__global__ void k_scan() {
    __shared__ int sm[1024];
    const int n = NN;
    const int chunk = (n + 1023) / 1024;
    int t = threadIdx.x;
    int base = t * chunk;
    int s = 0;
    for (int i = 0; i < chunk; ++i) {
        int idx = base + i;
        if (idx < n) s += g_deg[idx];
    }
    sm[t] = s;
    __syncthreads();
    for (int d = 1; d < 1024; d <<= 1) {
        int add = (t >= d) ? sm[t - d] : 0;
        __syncthreads();
        sm[t] += add;
        __syncthreads();
    }
    int run = sm[t] - s;
    for (int i = 0; i < chunk; ++i) {
        int idx = base + i;
        if (idx < n) { g_off[idx] = run; run += g_deg[idx]; }
    }
    if (t == 1023) g_off[n] = sm[1023];
}
__global__ void k_fill(const int* __restrict__ ei) {
    int e = blockIdx.x * blockDim.x + threadIdx.x;
    if (e < EE) {
        int s = ei[e];
        int d = ei[EE + e];
        int slot = atomicAdd(&g_cur[d], 1);
        g_col[g_off[d] + slot] = s;
    }
}

// ---------------- attention prep ----------------
__global__ void k_prep(const float* __restrict__ in_proj_W,
                       const float* __restrict__ in_proj_b,
                       const float* __restrict__ query) {
    __shared__ float qv[128];
    int t = threadIdx.x;
    float s = in_proj_b[t];
    for (int k = 0; k < 128; ++k) s = fmaf(in_proj_W[t * 128 + k], query[k], s);
    qv[t] = s;
    __syncthreads();
    const float inv = 1.0f / sqrtf(32.0f);
    float u[4] = {0.f, 0.f, 0.f, 0.f};
    for (int r = 0; r < 128; ++r) {
        float w = in_proj_W[(128 + r) * 128 + t];
        u[r >> 5] = fmaf(qv[r], w, u[r >> 5]);
    }
#pragma unroll
    for (int h = 0; h < 4; ++h) g_U[t * 4 + h] = u[h] * inv;
    if (t < 4) {
        float cc = 0.f;
        for (int d = 0; d < 32; ++d) cc = fmaf(qv[t * 32 + d], in_proj_b[128 + t * 32 + d], cc);
        g_cvec[t] = cc * inv;
    }
}

// ---------------- graph boundaries ----------------
__global__ void k_gbounds(const int* __restrict__ batch) {
    int i = blockIdx.x * blockDim.x + threadIdx.x;
    if (i >= NN) return;
    int bi = batch[i];
    if (i == 0) {
        for (int g = 0; g <= bi; ++g) g_gstart[g] = 0;
    } else {
        int bp = batch[i - 1];
        for (int g = bp + 1; g <= bi; ++g) g_gstart[g] = i;
    }
    if (i == NN - 1) {
        for (int g = bi + 1; g <= BB; ++g) g_gstart[g] = NN;
    }
}

// ---------------- per-graph softmax pool ----------------
__global__ void __launch_bounds__(256) k_pool() {
    int b = blockIdx.x;
    int s0 = g_gstart[b], s1 = g_gstart[b + 1];
    int t = threadIdx.x;
    __shared__ float4 red[256];
    __shared__ float smax[4];
    __shared__ float pbuf[256];
    __shared__ float dbuf[8];

    float4 mx = make_float4(-1e30f, -1e30f, -1e30f, -1e30f);
    for (int n = s0 + t; n < s1; n += 256) {
        float4 f = reinterpret_cast<const float4*>(g_scores)[n];
        mx.x = fmaxf(mx.x, f.x); mx.y = fmaxf(mx.y, f.y);
        mx.z = fmaxf(mx.z, f.z); mx.w = fmaxf(mx.w, f.w);
    }
    red[t] = mx;
    __syncthreads();
    for (int s = 128; s > 0; s >>= 1) {
        if (t < s) {
            float4 a = red[t], c = red[t + s];
            a.x = fmaxf(a.x, c.x); a.y = fmaxf(a.y, c.y);
            a.z = fmaxf(a.z, c.z); a.w = fmaxf(a.w, c.w);
            red[t] = a;
        }
        __syncthreads();
    }
    if (t == 0) { smax[0] = red[0].x; smax[1] = red[0].y; smax[2] = red[0].z; smax[3] = red[0].w; }
    __syncthreads();

    int tau = t >> 7, j = t & 127, h = j >> 5;
    float m = smax[h];
    float pl = 0.f, den = 0.f;
    for (int n = s0 + tau; n < s1; n += 2) {
        float e = expf(g_scores[n * 4 + h] - m);
        pl = fmaf(e, g_v[(size_t)n * HH + j], pl);
        den += e;
    }
    pbuf[t] = pl;
    if ((j & 31) == 0) dbuf[tau * 4 + h] = den;
    __syncthreads();
    if (t < 128) {
        float d = dbuf[h] + dbuf[4 + h];
        float p = pbuf[t] + pbuf[128 + t];
        g_pooled[b * HH + t] = (d > 0.f) ? p / d : 0.f;
    }
}

// ---------------- tail ----------------
__device__ __forceinline__ float block_ln128(float v, float gamma, float beta,
                                             float* ws, float* wq) {
    float s = warp_sum(v);
    float q = warp_sum(v * v);
    int wid = threadIdx.x >> 5, lane = threadIdx.x & 31;
    if (lane == 0) { ws[wid] = s; wq[wid] = q; }
    __syncthreads();
    float ts = ws[0] + ws[1] + ws[2] + ws[3];
    float tq = wq[0] + wq[1] + wq[2] + wq[3];
    __syncthreads();
    float mean = ts * (1.f / 128.f);
    float var  = tq * (1.f / 128.f) - mean * mean;
    return (v - mean) * rsqrtf(var + 1e-5f) * gamma + beta;
}

__global__ void __launch_bounds__(128) k_tail(
    const float* __restrict__ out_W, const float* __restrict__ out_b,
    const float* __restrict__ symfeat,
    const float* __restrict__ sym_W, const float* __restrict__ sym_b,
    const float* __restrict__ symf_W, const float* __restrict__ symf_b,
    const float* __restrict__ symf_g, const float* __restrict__ symf_beta,
    const float* __restrict__ fus_W, const float* __restrict__ fus_b,
    const float* __restrict__ fus_g, const float* __restrict__ fus_beta,
    const float* __restrict__ hW1, const float* __restrict__ hb1,
    const float* __restrict__ hW2, const float* __restrict__ hb2,
    float* __restrict__ outp)
{
    int b = blockIdx.x;
    int t = threadIdx.x;
    __shared__ float p[128];
    __shared__ float cat[256];
    __shared__ float buf[128];
    __shared__ float hh[192];
    __shared__ float ws[4], wq[4];

    p[t] = g_pooled[b * HH + t];
    __syncthreads();
    {
        float acc = out_b[t];
        for (int k = 0; k < 128; ++k) acc = fmaf(out_W[t * 128 + k], p[k], acc);
        cat[t] = acc;
    }
    {
        int f = t >> 5, o = t & 31;
        const float* sf = symfeat + b * 64 + f * 16;
        const float* w  = sym_W + (f * 32 + o) * 16;
        float s = sym_b[f * 32 + o];
#pragma unroll
        for (int i = 0; i < 16; ++i) s = fmaf(w[i], sf[i], s);
        buf[t] = fmaxf(s, 0.f);
    }
    __syncthreads();
    {
        float s2 = symf_b[t];
        for (int k = 0; k < 128; ++k) s2 = fmaf(symf_W[t * 128 + k], buf[k], s2);
        s2 = fmaxf(s2, 0.f);
        float v = block_ln128(s2, symf_g[t], symf_beta[t], ws, wq);
        cat[128 + t] = v;
    }
    __syncthreads();
    {
        float f = fus_b[t];
        for (int k = 0; k < 256; ++k) f = fmaf(fus_W[t * 256 + k], cat[k], f);
        f = fmaxf(f, 0.f);
        float v = block_ln128(f, fus_g[t], fus_beta[t], ws, wq);
        p[t] = v;
    }
    __syncthreads();
    for (int idx = t; idx < 192; idx += 128) {
        int k = idx >> 6, o = idx & 63;
        const float* w = hW1 + (size_t)(k * 64 + o) * 128;
        float acc = hb1[k * 64 + o];
        for (int j = 0; j < 128; ++j) acc = fmaf(w[j], p[j], acc);
        hh[idx] = fmaxf(acc, 0.f);
    }
    __syncthreads();
    if (t < 3) {
        float z = hb2[t];
        for (int o = 0; o < 64; ++o) z = fmaf(hW2[t * 64 + o], hh[t * 64 + o], z);
        outp[t * BB + b] = 1.f / (1.f + expf(-z));
    }
}

// ---------------- host ----------------
extern "C" void kernel_launch(void* const* d_in, const int* in_sizes, int n_in,
                              void* d_out, int out_size) {
    const float* nf = nullptr;
    const float* symf = nullptr;
    const int* ei = nullptr;
    const int* batch = nullptr;
    const float* P[26];
    int pi = 0;
    for (int i = 0; i < n_in; ++i) {
        int sz = in_sizes[i];
        if (sz == NN * HH)       nf    = (const float*)d_in[i];
        else if (sz == BB * 64)  symf  = (const float*)d_in[i];
        else if (sz == 2 * EE)   ei    = (const int*)d_in[i];
        else if (sz == NN)       batch = (const int*)d_in[i];
        else if (pi < 26)        P[pi++] = (const float*)d_in[i];
    }
    const float *W_in = P[0], *b_in = P[1], *sage_Wl = P[2], *sage_bl = P[3],
                *sage_Wr = P[4], *ln_g = P[5], *ln_b = P[6], *query = P[7],
                *in_proj_W = P[8], *in_proj_b = P[9], *out_W = P[10], *out_b = P[11],
                *sym_W = P[12], *sym_b = P[13], *symf_W = P[14], *symf_b = P[15],
                *symf_g = P[16], *symf_beta = P[17], *fus_W = P[18], *fus_b = P[19],
                *fus_g = P[20], *fus_beta = P[21], *hW1 = P[22], *hb1 = P[23],
                *hW2 = P[24], *hb2 = P[25];

    float *px, *px2, *pv;
    cudaGetSymbolAddress((void**)&px,  g_x);
    cudaGetSymbolAddress((void**)&px2, g_x2);
    cudaGetSymbolAddress((void**)&pv,  g_v);

    cudaFuncSetAttribute((const void*)k_mma<0>, cudaFuncAttributeMaxDynamicSharedMemorySize, SMEM_BYTES);
    cudaFuncSetAttribute((const void*)k_mma<1>, cudaFuncAttributeMaxDynamicSharedMemorySize, SMEM_BYTES);
    cudaFuncSetAttribute((const void*)k_mma<2>, cudaFuncAttributeMaxDynamicSharedMemorySize, SMEM_BYTES);

    // weight slots: 0=W_in, 1=Wl0, 2=Wr0, 3=Wl1, 4=Wr1, 5=Wl2, 6=Wr2, 7=Wv
    k_wconv<<<128, 256>>>(W_in,
                          sage_Wl + 0 * 16384, sage_Wr + 0 * 16384,
                          sage_Wl + 1 * 16384, sage_Wr + 1 * 16384,
                          sage_Wl + 2 * 16384, sage_Wr + 2 * 16384,
                          in_proj_W + 256 * 128);
    k_init<<<(NN + 255) / 256, 256>>>();
    k_deg<<<(EE + 255) / 256, 256>>>(ei);
    // index 3: input-proj GEMM (profiled sample slot)
    k_mma<0><<<TILES, 256, SMEM_BYTES>>>(nf, 0, b_in, nullptr, nullptr, px, NN);
    k_scan<<<1, 1024>>>();
    k_fill<<<(EE + 255) / 256, 256>>>(ei);
    k_prep<<<1, 128>>>(in_proj_W, in_proj_b, query);
    k_gbounds<<<(NN + 255) / 256, 256>>>(batch);

    float* cur = px;
    float* nxt = px2;
    for (int l = 0; l < 3; ++l) {
        // fused: gather-mean pass (Wl) + root pass (Wr) + bias + LN + relu + residual
        k_mma<1><<<TILES, 256, SMEM_BYTES>>>(cur, 1 + 2 * l, sage_bl + l * 128,
                                             ln_g + l * 128, ln_b + l * 128, nxt, NN);
        float* tmp = cur; cur = nxt; nxt = tmp;
    }

    // v = x @ Wv^T + bv, fused with attention scores
    k_mma<2><<<TILES, 256, SMEM_BYTES>>>(cur, 7, in_proj_b + 256,
                                         nullptr, nullptr, pv, NN);

    k_pool<<<BB, 256>>>();
    k_tail<<<BB, 128>>>(out_W, out_b, symf, sym_W, sym_b,
                        symf_W, symf_b, symf_g, symf_beta,
                        fus_W, fus_b, fus_g, fus_beta,
                        hW1, hb1, hW2, hb2, (float*)d_out);
    (void)out_size;
}

// round 5
// speedup vs baseline: 1.2269x; 1.2269x over previous
#include <cuda_runtime.h>
#include <cuda_bf16.h>
#include <math.h>
#include <stdint.h>

#define NN 50000
#define EE 800000
#define BB 64
#define HH 128
#define TILES 391   // ceil(50000/128)

// ---------------- scratch (device globals) ----------------
// x as bf16 hi/lo planes: [node][64] uint32 (bf16x2)
__device__ uint32_t g_xh [NN * 64];
__device__ uint32_t g_xl [NN * 64];
__device__ uint32_t g_xh2[NN * 64];
__device__ uint32_t g_xl2[NN * 64];
__device__ uint32_t g_aggh[NN * 64];
__device__ uint32_t g_aggl[NN * 64];
__device__ float g_v   [NN * HH];
__device__ float g_scores[NN * 4];
__device__ float g_pooled[BB * HH];
__device__ float g_U[HH * 4];
__device__ float g_cvec[4];
__device__ int   g_deg[NN];
__device__ int   g_off[NN + 1];
__device__ int   g_cur[NN];
__device__ int   g_col[EE];
__device__ int   g_gstart[BB + 1];
// bf16 hi/lo weight planes: 8 matrices x 64KB (hi 32KB then lo 32KB), row-major 256B rows
__device__ uint4 g_wbuf[8 * 4096];

// ---------------- helpers ----------------
__device__ __forceinline__ void hilo(float v, uint32_t& h, uint32_t& l) {
    __nv_bfloat16 hb = __float2bfloat16(v);
    __nv_bfloat16 lb = __float2bfloat16(v - __bfloat162float(hb));
    h = (uint32_t)__bfloat16_as_ushort(hb);
    l = (uint32_t)__bfloat16_as_ushort(lb);
}
__device__ __forceinline__ float2 bf2f(uint32_t u) {
    __nv_bfloat162 h;
    *reinterpret_cast<uint32_t*>(&h) = u;
    return __bfloat1622float2(h);
}
__device__ __forceinline__ uint32_t smem_u32(const void* p) {
    uint32_t a;
    asm("{ .reg .u64 t; cvta.to.shared.u64 t, %1; cvt.u32.u64 %0, t; }" : "=r"(a) : "l"(p));
    return a;
}
__device__ __forceinline__ float warp_sum(float v) {
#pragma unroll
    for (int o = 16; o > 0; o >>= 1) v += __shfl_xor_sync(0xffffffffu, v, o);
    return v;
}

#define HMMA(C, A0, A1, A2, A3, B0, B1) \
    asm volatile("mma.sync.aligned.m16n8k16.row.col.f32.bf16.bf16.f32 " \
                 "{%0,%1,%2,%3}, {%4,%5,%6,%7}, {%8,%9}, {%0,%1,%2,%3};" \
                 : "+f"((C)[0]), "+f"((C)[1]), "+f"((C)[2]), "+f"((C)[3]) \
                 : "r"(A0), "r"(A1), "r"(A2), "r"(A3), "r"(B0), "r"(B1))

#define LDSM4(D0, D1, D2, D3, A) \
    asm volatile("ldmatrix.sync.aligned.m8n8.x4.shared.b16 {%0,%1,%2,%3}, [%4];" \
                 : "=r"(D0), "=r"(D1), "=r"(D2), "=r"(D3) : "r"(A))

// ---------------- SMEM layout ----------------
// swizzled 256B rows; chunk(16B) index XOR (row&7)
#define OFF_A1H 0
#define OFF_A1L 32768
#define OFF_WH  65536
#define OFF_WL  98304
#define OFF_A2H 131072
#define OFF_A2L 163840
#define OFF_MISC 196608
#define OFF_BIAS (OFF_MISC)
#define OFF_G    (OFF_MISC + 512)
#define OFF_BETA (OFF_MISC + 1024)
#define OFF_MEAN (OFF_MISC + 1536)
#define OFF_RSTD (OFF_MISC + 2048)
#define OFF_U    (OFF_MISC + 2560)
#define OFF_CV   (OFF_MISC + 4608)
#define SMEM_BYTES (OFF_MISC + 4640)
// C spill: 128 rows x 512B (fp32, chunk-swizzled), aliases A1 region [0, 65536)

// float index of C[row][col] with chunk swizzle
__device__ __forceinline__ int CIDX(int row, int col) {
    return row * 128 + (((col >> 2) ^ (row & 7)) << 2) + (col & 3);
}
// uint32 index within a bf16 plane tile for (row, cp) cp=0..63
__device__ __forceinline__ int PIDX(int row, int cp) {
    return row * 64 + (((cp >> 2) ^ (row & 7)) << 2) + (cp & 3);
}

// ---------------- weight pre-conversion ----------------
__global__ void k_wconv(const float* w0, const float* w1, const float* w2, const float* w3,
                        const float* w4, const float* w5, const float* w6, const float* w7) {
    int m = blockIdx.x >> 4;
    const float* W;
    switch (m) {
        case 0: W = w0; break; case 1: W = w1; break; case 2: W = w2; break;
        case 3: W = w3; break; case 4: W = w4; break; case 5: W = w5; break;
        case 6: W = w6; break; default: W = w7; break;
    }
    int i = (blockIdx.x & 15) * 256 + threadIdx.x;
    int row = i >> 5, q = i & 31;
    float4 v = *reinterpret_cast<const float4*>(W + (size_t)row * 128 + q * 4);
    uint32_t h0, l0, h1, l1, h2, l2, h3, l3;
    hilo(v.x, h0, l0); hilo(v.y, h1, l1); hilo(v.z, h2, l2); hilo(v.w, h3, l3);
    uint2 uh, ul;
    uh.x = h0 | (h1 << 16); uh.y = h2 | (h3 << 16);
    ul.x = l0 | (l1 << 16); ul.y = l2 | (l3 << 16);
    char* base = (char*)g_wbuf + (size_t)m * 65536;
    int sw = row * 256 + q * 8;
    *reinterpret_cast<uint2*>(base + sw)         = uh;
    *reinterpret_cast<uint2*>(base + 32768 + sw) = ul;
}

// ---------------- GEMM fills ----------------
// copy planes (global linear 256B rows) -> swizzled smem tile (hi+lo)
__device__ __forceinline__ void fill_copy(const uint32_t* __restrict__ gh,
                                          const uint32_t* __restrict__ gl,
                                          char* smem, uint32_t dstoff,
                                          int tile0, int nrows, int t) {
    const uint4* gh4 = reinterpret_cast<const uint4*>(gh);
    const uint4* gl4 = reinterpret_cast<const uint4*>(gl);
    for (int i = t; i < 2048; i += 512) {
        int row = i >> 4, chunk = i & 15;
        int grow = tile0 + row;
        uint4 vh = make_uint4(0, 0, 0, 0), vl = make_uint4(0, 0, 0, 0);
        if (grow < nrows) { vh = gh4[grow * 16 + chunk]; vl = gl4[grow * 16 + chunk]; }
        int phys = row * 256 + ((chunk ^ (row & 7)) << 4);
        *reinterpret_cast<uint4*>(smem + dstoff + phys)         = vh;
        *reinterpret_cast<uint4*>(smem + dstoff + 32768 + phys) = vl;
    }
}
// convert fp32 -> hi/lo swizzled smem tile
__device__ __forceinline__ void fill_convert(const float* __restrict__ A, char* smem,
                                             uint32_t dstoff, int tile0, int nrows, int t) {
    for (int i = t; i < 4096; i += 512) {
        int row = i >> 5, q = i & 31;
        int grow = tile0 + row;
        float4 v = make_float4(0.f, 0.f, 0.f, 0.f);
        if (grow < nrows) v = *reinterpret_cast<const float4*>(A + (size_t)grow * HH + q * 4);
        uint32_t h0, l0, h1, l1, h2, l2, h3, l3;
        hilo(v.x, h0, l0); hilo(v.y, h1, l1); hilo(v.z, h2, l2); hilo(v.w, h3, l3);
        uint2 uh, ul;
        uh.x = h0 | (h1 << 16); uh.y = h2 | (h3 << 16);
        ul.x = l0 | (l1 << 16); ul.y = l2 | (l3 << 16);
        int phys = row * 256 + (((q >> 1) ^ (row & 7)) << 4) + (q & 1) * 8;
        *reinterpret_cast<uint2*>(smem + dstoff + phys)         = uh;
        *reinterpret_cast<uint2*>(smem + dstoff + 32768 + phys) = ul;
    }
}
__device__ __forceinline__ void fill_W(int slot, char* smem, int t) {
    const uint4* src = reinterpret_cast<const uint4*>((const char*)g_wbuf + (size_t)slot * 65536);
    for (int i = t; i < 2048; i += 512) {
        int row = i >> 4, chunk = i & 15;
        int phys = row * 256 + ((chunk ^ (row & 7)) << 4);
        *reinterpret_cast<uint4*>(smem + OFF_WH + phys) = src[i];
        *reinterpret_cast<uint4*>(smem + OFF_WL + phys) = src[2048 + i];
    }
}

// ---------------- mainloop: 3-term split-precision HMMA ----------------
__device__ __forceinline__ void mainloop(uint32_t sb, uint32_t Aoff,
                                         float c[2][4][4], int wm, int wn, int lane) {
    uint32_t rowA = wm * 32 + (lane & 15);
    uint32_t swA = rowA & 7;
    uint32_t a0 = sb + Aoff + rowA * 256;
    uint32_t a1 = a0 + 16 * 256;
    uint32_t halfA = lane >> 4;
    uint32_t wrow = sb + OFF_WH + (uint32_t)(wn * 32 + lane) * 256;
    uint32_t swB = lane & 7;
#pragma unroll
    for (int ks = 0; ks < 8; ++ks) {
        uint32_t bh0[4], bh1[4], bl0[4], bl1[4];
        uint32_t cb0 = (uint32_t)(((2 * ks) ^ swB) << 4);
        uint32_t cb1 = (uint32_t)(((2 * ks + 1) ^ swB) << 4);
        LDSM4(bh0[0], bh0[1], bh0[2], bh0[3], wrow + cb0);
        LDSM4(bh1[0], bh1[1], bh1[2], bh1[3], wrow + cb1);
        LDSM4(bl0[0], bl0[1], bl0[2], bl0[3], wrow + 32768 + cb0);
        LDSM4(bl1[0], bl1[1], bl1[2], bl1[3], wrow + 32768 + cb1);
        uint32_t ca = (uint32_t)(((2 * ks + halfA) ^ swA) << 4);
#pragma unroll
        for (int mb = 0; mb < 2; ++mb) {
            uint32_t ab = (mb ? a1 : a0) + ca;
            uint32_t ah0, ah1, ah2, ah3, al0, al1, al2, al3;
            LDSM4(ah0, ah1, ah2, ah3, ab);
            LDSM4(al0, al1, al2, al3, ab + 32768);
#pragma unroll
            for (int nb = 0; nb < 4; ++nb) {
                HMMA(c[mb][nb], ah0, ah1, ah2, ah3, bh0[nb], bh1[nb]);
                HMMA(c[mb][nb], ah0, ah1, ah2, ah3, bl0[nb], bl1[nb]);
                HMMA(c[mb][nb], al0, al1, al2, al3, bh0[nb], bh1[nb]);
            }
        }
    }
}

// MODE: 0 = input proj (convert fill, relu, write planes)
//       1 = SAGE (two copy passes, LN+relu+residual, write planes)
//       2 = V proj (copy fill, fused scores, write fp32 v)
template <int MODE>
__global__ void __launch_bounds__(512, 1) k_mma(
    const float* __restrict__ Afp,
    const uint32_t* __restrict__ p1h, const uint32_t* __restrict__ p1l,
    const uint32_t* __restrict__ p2h, const uint32_t* __restrict__ p2l,
    int wslot, const float* __restrict__ bias,
    const float* __restrict__ lng, const float* __restrict__ lnb,
    uint32_t* __restrict__ outh, uint32_t* __restrict__ outl,
    float* __restrict__ outf, int nrows)
{
    extern __shared__ char smem[];
    uint32_t sb = smem_u32(smem);
    int t = threadIdx.x, wid = t >> 5, lane = t & 31;
    int tile0 = blockIdx.x * 128;
    int wm = wid & 3, wn = wid >> 2;

    if (t < 128) {
        ((float*)(smem + OFF_BIAS))[t] = bias[t];
        if (MODE == 1) {
            ((float*)(smem + OFF_G))[t]    = lng[t];
            ((float*)(smem + OFF_BETA))[t] = lnb[t];
        }
    }
    if (MODE == 2) {
        if (t >= 128 && t < 256) ((float4*)(smem + OFF_U))[t - 128] = ((const float4*)g_U)[t - 128];
        if (t == 256) *((float4*)(smem + OFF_CV)) = *((const float4*)g_cvec);
    }

    float c[2][4][4];
#pragma unroll
    for (int mb = 0; mb < 2; ++mb)
#pragma unroll
        for (int nb = 0; nb < 4; ++nb)
#pragma unroll
            for (int j = 0; j < 4; ++j) c[mb][nb][j] = 0.f;

    // fills
    if (MODE == 0) fill_convert(Afp, smem, OFF_A1H, tile0, nrows, t);
    else           fill_copy(p1h, p1l, smem, OFF_A1H, tile0, nrows, t);
    if (MODE == 1) fill_copy(p2h, p2l, smem, OFF_A2H, tile0, nrows, t);
    fill_W(wslot, smem, t);
    __syncthreads();

    mainloop(sb, OFF_A1H, c, wm, wn, lane);

    if (MODE == 1) {
        __syncthreads();
        fill_W(wslot + 1, smem, t);
        __syncthreads();
        mainloop(sb, OFF_A2H, c, wm, wn, lane);
    }
    __syncthreads();

    // MODE 2: fused attention scores from A1 planes (before C spill destroys them)
    if (MODE == 2) {
        if (t < 128) {
            int grow = tile0 + t;
            if (grow < nrows) {
                const uint32_t* ph = (const uint32_t*)(smem + OFF_A1H);
                const uint32_t* pl = (const uint32_t*)(smem + OFF_A1L);
                const float4* U4 = (const float4*)(smem + OFF_U);
                const float* cv = (const float*)(smem + OFF_CV);
                float a0 = cv[0], a1 = cv[1], a2 = cv[2], a3 = cv[3];
#pragma unroll
                for (int kk = 0; kk < 64; ++kk) {
                    int idx = PIDX(t, kk);
                    float2 h = bf2f(ph[idx]);
                    float2 l = bf2f(pl[idx]);
                    float x0 = h.x + l.x, x1 = h.y + l.y;
                    float4 u0 = U4[2 * kk];
                    float4 u1 = U4[2 * kk + 1];
                    a0 += x0 * u0.x + x1 * u1.x;
                    a1 += x0 * u0.y + x1 * u1.y;
                    a2 += x0 * u0.z + x1 * u1.z;
                    a3 += x0 * u0.w + x1 * u1.w;
                }
                float4 r; r.x = a0; r.y = a1; r.z = a2; r.w = a3;
                reinterpret_cast<float4*>(g_scores)[grow] = r;
            }
        }
        __syncthreads();
    }

    // spill C over A1 region (chunk-swizzled fp32)
    float* Csm = (float*)smem;
    int g = lane >> 2, tt = lane & 3;
#pragma unroll
    for (int mb = 0; mb < 2; ++mb) {
        int r0 = wm * 32 + mb * 16 + g;
        int r1 = r0 + 8;
#pragma unroll
        for (int nb = 0; nb < 4; ++nb) {
            int col = wn * 32 + nb * 8 + tt * 2;
            Csm[CIDX(r0, col)]     = c[mb][nb][0];
            Csm[CIDX(r0, col + 1)] = c[mb][nb][1];
            Csm[CIDX(r1, col)]     = c[mb][nb][2];
            Csm[CIDX(r1, col + 1)] = c[mb][nb][3];
        }
    }
    __syncthreads();

    const float* bs = (const float*)(smem + OFF_BIAS);
    if (MODE == 1) {
        if (t < 128) {
            float sum = 0.f, sq = 0.f;
#pragma unroll
            for (int j = 0; j < 128; ++j) {
                float x = Csm[CIDX(t, j)] + bs[j];
                sum += x; sq += x * x;
            }
            float mean = sum * (1.f / 128.f);
            float var  = sq * (1.f / 128.f) - mean * mean;
            ((float*)(smem + OFF_MEAN))[t] = mean;
            ((float*)(smem + OFF_RSTD))[t] = rsqrtf(var + 1e-5f);
        }
        __syncthreads();
    }

    if (MODE == 2) {
        // write fp32 v
        for (int i = t; i < 4096; i += 512) {
            int row = i >> 5, q = i & 31;
            int grow = tile0 + row;
            if (grow >= nrows) continue;
            int base = row * 128 + ((q ^ (row & 7)) << 2);
            float4 o;
            o.x = Csm[base + 0] + bs[q * 4 + 0];
            o.y = Csm[base + 1] + bs[q * 4 + 1];
            o.z = Csm[base + 2] + bs[q * 4 + 2];
            o.w = Csm[base + 3] + bs[q * 4 + 3];
            *reinterpret_cast<float4*>(outf + (size_t)grow * HH + q * 4) = o;
        }
    } else {
        const float* gg = (const float*)(smem + OFF_G);
        const float* bb = (const float*)(smem + OFF_BETA);
        const float* mn = (const float*)(smem + OFF_MEAN);
        const float* rs = (const float*)(smem + OFF_RSTD);
        const uint32_t* r2h = (const uint32_t*)(smem + OFF_A2H);
        const uint32_t* r2l = (const uint32_t*)(smem + OFF_A2L);
        for (int i = t; i < 8192; i += 512) {
            int row = i >> 6, cp = i & 63;
            int grow = tile0 + row;
            if (grow >= nrows) continue;
            int c0 = cp * 2;
            float x0 = Csm[CIDX(row, c0)]     + bs[c0];
            float x1 = Csm[CIDX(row, c0 + 1)] + bs[c0 + 1];
            float o0, o1;
            if (MODE == 1) {
                float mean = mn[row], rstd = rs[row];
                int idx = PIDX(row, cp);
                float2 rh = bf2f(r2h[idx]);
                float2 rl = bf2f(r2l[idx]);
                o0 = fmaxf((x0 - mean) * rstd * gg[c0]     + bb[c0],     0.f) + (rh.x + rl.x);
                o1 = fmaxf((x1 - mean) * rstd * gg[c0 + 1] + bb[c0 + 1], 0.f) + (rh.y + rl.y);
            } else {
                o0 = fmaxf(x0, 0.f);
                o1 = fmaxf(x1, 0.f);
            }
            uint32_t h0, l0, h1, l1;
            hilo(o0, h0, l0); hilo(o1, h1, l1);
            outh[(size_t)grow * 64 + cp] = h0 | (h1 << 16);
            outl[(size_t)grow * 64 + cp] = l0 | (l1 << 16);
        }
    }
}

// ---------------- CSR build ----------------
__global__ void k_init() {
    int i = blockIdx.x * blockDim.x + threadIdx.x;
    if (i < NN) { g_deg[i] = 0; g_cur[i] = 0; }
}
__global__ void k_deg(const int* __restrict__ ei) {
    int e = blockIdx.x * blockDim.x + threadIdx.x;
    if (e < EE) atomicAdd(&g_deg[ei[EE + e]], 1);
}
__global__ void k_scan() {
    __shared__ int sm[1024];
    const int n = NN;
    const int chunk = (n + 1023) / 1024;
    int t = threadIdx.x;
    int base = t * chunk;
    int s = 0;
    for (int i = 0; i < chunk; ++i) {
        int idx = base + i;
        if (idx < n) s += g_deg[idx];
    }
    sm[t] = s;
    __syncthreads();
    for (int d = 1; d < 1024; d <<= 1) {
        int add = (t >= d) ? sm[t - d] : 0;
        __syncthreads();
        sm[t] += add;
        __syncthreads();
    }
    int run = sm[t] - s;
    for (int i = 0; i < chunk; ++i) {
        int idx = base + i;
        if (idx < n) { g_off[idx] = run; run += g_deg[idx]; }
    }
    if (t == 1023) g_off[n] = sm[1023];
}
__global__ void k_fill(const int* __restrict__ ei) {
    int e = blockIdx.x * blockDim.x + threadIdx.x;
    if (e < EE) {
        int s = ei[e];
        int d = ei[EE + e];
        int slot = atomicAdd(&g_cur[d], 1);
        g_col[g_off[d] + slot] = s;
    }
}

// ---------------- neighbor mean aggregation (warp per node, bf16 planes) ----------------
__global__ void __launch_bounds__(256) k_aggr(const uint32_t* __restrict__ xh,
                                              const uint32_t* __restrict__ xl) {
    int warp = (blockIdx.x * blockDim.x + threadIdx.x) >> 5;
    int lane = threadIdx.x & 31;
    if (warp >= NN) return;
    int s0 = g_off[warp], s1 = g_off[warp + 1];
    float a0 = 0.f, a1 = 0.f, a2 = 0.f, a3 = 0.f;
    for (int i = s0; i < s1; ++i) {
        int nb = __ldg(&g_col[i]);
        uint2 vh = __ldg(reinterpret_cast<const uint2*>(xh + (size_t)nb * 64) + lane);
        uint2 vl = __ldg(reinterpret_cast<const uint2*>(xl + (size_t)nb * 64) + lane);
        float2 h0 = bf2f(vh.x), h1 = bf2f(vh.y);
        float2 l0 = bf2f(vl.x), l1 = bf2f(vl.y);
        a0 += h0.x + l0.x; a1 += h0.y + l0.y;
        a2 += h1.x + l1.x; a3 += h1.y + l1.y;
    }
    float inv = 1.f / fmaxf((float)(s1 - s0), 1.f);
    a0 *= inv; a1 *= inv; a2 *= inv; a3 *= inv;
    uint32_t h0, l0, h1, l1, h2, l2, h3, l3;
    hilo(a0, h0, l0); hilo(a1, h1, l1); hilo(a2, h2, l2); hilo(a3, h3, l3);
    uint2 uh, ul;
    uh.x = h0 | (h1 << 16); uh.y = h2 | (h3 << 16);
    ul.x = l0 | (l1 << 16); ul.y = l2 | (l3 << 16);
    reinterpret_cast<uint2*>(g_aggh + (size_t)warp * 64)[lane] = uh;
    reinterpret_cast<uint2*>(g_aggl + (size_t)warp * 64)[lane] = ul;
}

// ---------------- attention prep ----------------
__global__ void k_prep(const float* __restrict__ in_proj_W,
                       const float* __restrict__ in_proj_b,
                       const float* __restrict__ query) {
    __shared__ float qv[128];
    int t = threadIdx.x;
    float s = in_proj_b[t];
    for (int k = 0; k < 128; ++k) s = fmaf(in_proj_W[t * 128 + k], query[k], s);
    qv[t] = s;
    __syncthreads();
    const float inv = 1.0f / sqrtf(32.0f);
    float u[4] = {0.f, 0.f, 0.f, 0.f};
    for (int r = 0; r < 128; ++r) {
        float w = in_proj_W[(128 + r) * 128 + t];
        u[r >> 5] = fmaf(qv[r], w, u[r >> 5]);
    }
#pragma unroll
    for (int h = 0; h < 4; ++h) g_U[t * 4 + h] = u[h] * inv;
    if (t < 4) {
        float cc = 0.f;
        for (int d = 0; d < 32; ++d) cc = fmaf(qv[t * 32 + d], in_proj_b[128 + t * 32 + d], cc);
        g_cvec[t] = cc * inv;
    }
}

// ---------------- graph boundaries ----------------
__global__ void k_gbounds(const int* __restrict__ batch) {
    int i = blockIdx.x * blockDim.x + threadIdx.x;
    if (i >= NN) return;
    int bi = batch[i];
    if (i == 0) {
        for (int g = 0; g <= bi; ++g) g_gstart[g] = 0;
    } else {
        int bp = batch[i - 1];
        for (int g = bp + 1; g <= bi; ++g) g_gstart[g] = i;
    }
    if (i == NN - 1) {
        for (int g = bi + 1; g <= BB; ++g) g_gstart[g] = NN;
    }
}

// ---------------- per-graph softmax pool ----------------
__global__ void __launch_bounds__(256) k_pool() {
    int b = blockIdx.x;
    int s0 = g_gstart[b], s1 = g_gstart[b + 1];
    int t = threadIdx.x;
    __shared__ float4 red[256];
    __shared__ float smax[4];
    __shared__ float pbuf[256];
    __shared__ float dbuf[8];

    float4 mx = make_float4(-1e30f, -1e30f, -1e30f, -1e30f);
    for (int n = s0 + t; n < s1; n += 256) {
        float4 f = reinterpret_cast<const float4*>(g_scores)[n];
        mx.x = fmaxf(mx.x, f.x); mx.y = fmaxf(mx.y, f.y);
        mx.z = fmaxf(mx.z, f.z); mx.w = fmaxf(mx.w, f.w);
    }
    red[t] = mx;
    __syncthreads();
    for (int s = 128; s > 0; s >>= 1) {
        if (t < s) {
            float4 a = red[t], c = red[t + s];
            a.x = fmaxf(a.x, c.x); a.y = fmaxf(a.y, c.y);
            a.z = fmaxf(a.z, c.z); a.w = fmaxf(a.w, c.w);
            red[t] = a;
        }
        __syncthreads();
    }
    if (t == 0) { smax[0] = red[0].x; smax[1] = red[0].y; smax[2] = red[0].z; smax[3] = red[0].w; }
    __syncthreads();

    int tau = t >> 7, j = t & 127, h = j >> 5;
    float m = smax[h];
    float pl = 0.f, den = 0.f;
    for (int n = s0 + tau; n < s1; n += 2) {
        float e = expf(g_scores[n * 4 + h] - m);
        pl = fmaf(e, g_v[(size_t)n * HH + j], pl);
        den += e;
    }
    pbuf[t] = pl;
    if ((j & 31) == 0) dbuf[tau * 4 + h] = den;
    __syncthreads();
    if (t < 128) {
        float d = dbuf[h] + dbuf[4 + h];
        float p = pbuf[t] + pbuf[128 + t];
        g_pooled[b * HH + t] = (d > 0.f) ? p / d : 0.f;
    }
}

// ---------------- tail ----------------
__device__ __forceinline__ float block_ln128(float v, float gamma, float beta,
                                             float* ws, float* wq) {
    float s = warp_sum(v);
    float q = warp_sum(v * v);
    int wid = threadIdx.x >> 5, lane = threadIdx.x & 31;
    if (lane == 0) { ws[wid] = s; wq[wid] = q; }
    __syncthreads();
    float ts = ws[0] + ws[1] + ws[2] + ws[3];
    float tq = wq[0] + wq[1] + wq[2] + wq[3];
    __syncthreads();
    float mean = ts * (1.f / 128.f);
    float var  = tq * (1.f / 128.f) - mean * mean;
    return (v - mean) * rsqrtf(var + 1e-5f) * gamma + beta;
}

__global__ void __launch_bounds__(128) k_tail(
    const float* __restrict__ out_W, const float* __restrict__ out_b,
    const float* __restrict__ symfeat,
    const float* __restrict__ sym_W, const float* __restrict__ sym_b,
    const float* __restrict__ symf_W, const float* __restrict__ symf_b,
    const float* __restrict__ symf_g, const float* __restrict__ symf_beta,
    const float* __restrict__ fus_W, const float* __restrict__ fus_b,
    const float* __restrict__ fus_g, const float* __restrict__ fus_beta,
    const float* __restrict__ hW1, const float* __restrict__ hb1,
    const float* __restrict__ hW2, const float* __restrict__ hb2,
    float* __restrict__ outp)
{
    int b = blockIdx.x;
    int t = threadIdx.x;
    __shared__ float p[128];
    __shared__ float cat[256];
    __shared__ float buf[128];
    __shared__ float hh[192];
    __shared__ float ws[4], wq[4];

    p[t] = g_pooled[b * HH + t];
    __syncthreads();
    {
        float acc = out_b[t];
        for (int k = 0; k < 128; ++k) acc = fmaf(out_W[t * 128 + k], p[k], acc);
        cat[t] = acc;
    }
    {
        int f = t >> 5, o = t & 31;
        const float* sf = symfeat + b * 64 + f * 16;
        const float* w  = sym_W + (f * 32 + o) * 16;
        float s = sym_b[f * 32 + o];
#pragma unroll
        for (int i = 0; i < 16; ++i) s = fmaf(w[i], sf[i], s);
        buf[t] = fmaxf(s, 0.f);
    }
    __syncthreads();
    {
        float s2 = symf_b[t];
        for (int k = 0; k < 128; ++k) s2 = fmaf(symf_W[t * 128 + k], buf[k], s2);
        s2 = fmaxf(s2, 0.f);
        float v = block_ln128(s2, symf_g[t], symf_beta[t], ws, wq);
        cat[128 + t] = v;
    }
    __syncthreads();
    {
        float f = fus_b[t];
        for (int k = 0; k < 256; ++k) f = fmaf(fus_W[t * 256 + k], cat[k], f);
        f = fmaxf(f, 0.f);
        float v = block_ln128(f, fus_g[t], fus_beta[t], ws, wq);
        p[t] = v;
    }
    __syncthreads();
    for (int idx = t; idx < 192; idx += 128) {
        int k = idx >> 6, o = idx & 63;
        const float* w = hW1 + (size_t)(k * 64 + o) * 128;
        float acc = hb1[k * 64 + o];
        for (int j = 0; j < 128; ++j) acc = fmaf(w[j], p[j], acc);
        hh[idx] = fmaxf(acc, 0.f);
    }
    __syncthreads();
    if (t < 3) {
        float z = hb2[t];
        for (int o = 0; o < 64; ++o) z = fmaf(hW2[t * 64 + o], hh[t * 64 + o], z);
        outp[t * BB + b] = 1.f / (1.f + expf(-z));
    }
}

// ---------------- host ----------------
extern "C" void kernel_launch(void* const* d_in, const int* in_sizes, int n_in,
                              void* d_out, int out_size) {
    const float* nf = nullptr;
    const float* symf = nullptr;
    const int* ei = nullptr;
    const int* batch = nullptr;
    const float* P[26];
    int pi = 0;
    for (int i = 0; i < n_in; ++i) {
        int sz = in_sizes[i];
        if (sz == NN * HH)       nf    = (const float*)d_in[i];
        else if (sz == BB * 64)  symf  = (const float*)d_in[i];
        else if (sz == 2 * EE)   ei    = (const int*)d_in[i];
        else if (sz == NN)       batch = (const int*)d_in[i];
        else if (pi < 26)        P[pi++] = (const float*)d_in[i];
    }
    const float *W_in = P[0], *b_in = P[1], *sage_Wl = P[2], *sage_bl = P[3],
                *sage_Wr = P[4], *ln_g = P[5], *ln_b = P[6], *query = P[7],
                *in_proj_W = P[8], *in_proj_b = P[9], *out_W = P[10], *out_b = P[11],
                *sym_W = P[12], *sym_b = P[13], *symf_W = P[14], *symf_b = P[15],
                *symf_g = P[16], *symf_beta = P[17], *fus_W = P[18], *fus_b = P[19],
                *fus_g = P[20], *fus_beta = P[21], *hW1 = P[22], *hb1 = P[23],
                *hW2 = P[24], *hb2 = P[25];

    uint32_t *pxh, *pxl, *pxh2, *pxl2, *pah, *pal;
    float* pv;
    cudaGetSymbolAddress((void**)&pxh,  g_xh);
    cudaGetSymbolAddress((void**)&pxl,  g_xl);
    cudaGetSymbolAddress((void**)&pxh2, g_xh2);
    cudaGetSymbolAddress((void**)&pxl2, g_xl2);
    cudaGetSymbolAddress((void**)&pah,  g_aggh);
    cudaGetSymbolAddress((void**)&pal,  g_aggl);
    cudaGetSymbolAddress((void**)&pv,   g_v);

    cudaFuncSetAttribute((const void*)k_mma<0>, cudaFuncAttributeMaxDynamicSharedMemorySize, SMEM_BYTES);
    cudaFuncSetAttribute((const void*)k_mma<1>, cudaFuncAttributeMaxDynamicSharedMemorySize, SMEM_BYTES);
    cudaFuncSetAttribute((const void*)k_mma<2>, cudaFuncAttributeMaxDynamicSharedMemorySize, SMEM_BYTES);

    // weight slots: 0=W_in, 1=Wl0, 2=Wr0, 3=Wl1, 4=Wr1, 5=Wl2, 6=Wr2, 7=Wv
    k_wconv<<<128, 256>>>(W_in,
                          sage_Wl + 0 * 16384, sage_Wr + 0 * 16384,
                          sage_Wl + 1 * 16384, sage_Wr + 1 * 16384,
                          sage_Wl + 2 * 16384, sage_Wr + 2 * 16384,
                          in_proj_W + 256 * 128);
    k_init<<<(NN + 255) / 256, 256>>>();
    k_deg<<<(EE + 255) / 256, 256>>>(ei);
    // index 3: input-proj GEMM (profiled sample slot)
    k_mma<0><<<TILES, 512, SMEM_BYTES>>>(nf, nullptr, nullptr, nullptr, nullptr,
                                         0, b_in, nullptr, nullptr, pxh, pxl, nullptr, NN);
    k_scan<<<1, 1024>>>();
    k_fill<<<(EE + 255) / 256, 256>>>(ei);
    k_prep<<<1, 128>>>(in_proj_W, in_proj_b, query);
    k_gbounds<<<(NN + 255) / 256, 256>>>(batch);

    uint32_t *curh = pxh, *curl = pxl, *nxth = pxh2, *nxtl = pxl2;
    for (int l = 0; l < 3; ++l) {
        k_aggr<<<(NN * 32 + 255) / 256, 256>>>(curh, curl);
        // pass1: agg @ Wl ; pass2: x @ Wr ; epilogue LN+relu+residual
        k_mma<1><<<TILES, 512, SMEM_BYTES>>>(nullptr, pah, pal, curh, curl,
                                             1 + 2 * l, sage_bl + l * 128,
                                             ln_g + l * 128, ln_b + l * 128,
                                             nxth, nxtl, nullptr, NN);
        uint32_t* th = curh; curh = nxth; nxth = th;
        uint32_t* tl = curl; curl = nxtl; nxtl = tl;
    }

    // v = x @ Wv^T + bv (fp32) + fused attention scores
    k_mma<2><<<TILES, 512, SMEM_BYTES>>>(nullptr, curh, curl, nullptr, nullptr,
                                         7, in_proj_b + 256, nullptr, nullptr,
                                         nullptr, nullptr, pv, NN);

    k_pool<<<BB, 256>>>();
    k_tail<<<BB, 128>>>(out_W, out_b, symf, sym_W, sym_b,
                        symf_W, symf_b, symf_g, symf_beta,
                        fus_W, fus_b, fus_g, fus_beta,
                        hW1, hb1, hW2, hb2, (float*)d_out);
    (void)out_size;
}

// round 6
// speedup vs baseline: 1.2783x; 1.0419x over previous
#include <cuda_runtime.h>
#include <cuda_bf16.h>
#include <math.h>
#include <stdint.h>

#define NN 50000
#define EE 800000
#define BB 64
#define HH 128
#define TILES64 782   // ceil(50000/64)

// ---------------- scratch (device globals) ----------------
__device__ uint32_t g_xh [NN * 64];
__device__ uint32_t g_xl [NN * 64];
__device__ uint32_t g_xh2[NN * 64];
__device__ uint32_t g_xl2[NN * 64];
__device__ uint32_t g_aggh[NN * 64];
__device__ uint32_t g_aggl[NN * 64];
__device__ float g_v   [NN * HH];
__device__ float g_scores[NN * 4];
__device__ float g_pooled[BB * HH];
__device__ float g_U[HH * 4];
__device__ float g_cvec[4];
__device__ int   g_deg[NN];
__device__ int   g_off[NN + 1];
__device__ int   g_cur[NN];
__device__ int   g_col[EE];
__device__ int   g_gstart[BB + 1];
__device__ uint4 g_wbuf[8 * 4096];

// ---------------- helpers ----------------
__device__ __forceinline__ void hilo(float v, uint32_t& h, uint32_t& l) {
    __nv_bfloat16 hb = __float2bfloat16(v);
    __nv_bfloat16 lb = __float2bfloat16(v - __bfloat162float(hb));
    h = (uint32_t)__bfloat16_as_ushort(hb);
    l = (uint32_t)__bfloat16_as_ushort(lb);
}
__device__ __forceinline__ float2 bf2f(uint32_t u) {
    __nv_bfloat162 h;
    *reinterpret_cast<uint32_t*>(&h) = u;
    return __bfloat1622float2(h);
}
__device__ __forceinline__ uint32_t smem_u32(const void* p) {
    uint32_t a;
    asm("{ .reg .u64 t; cvta.to.shared.u64 t, %1; cvt.u32.u64 %0, t; }" : "=r"(a) : "l"(p));
    return a;
}
__device__ __forceinline__ float warp_sum(float v) {
#pragma unroll
    for (int o = 16; o > 0; o >>= 1) v += __shfl_xor_sync(0xffffffffu, v, o);
    return v;
}

#define HMMA(C, A0, A1, A2, A3, B0, B1) \
    asm volatile("mma.sync.aligned.m16n8k16.row.col.f32.bf16.bf16.f32 " \
                 "{%0,%1,%2,%3}, {%4,%5,%6,%7}, {%8,%9}, {%0,%1,%2,%3};" \
                 : "+f"((C)[0]), "+f"((C)[1]), "+f"((C)[2]), "+f"((C)[3]) \
                 : "r"(A0), "r"(A1), "r"(A2), "r"(A3), "r"(B0), "r"(B1))

#define LDSM4(D0, D1, D2, D3, A) \
    asm volatile("ldmatrix.sync.aligned.m8n8.x4.shared.b16 {%0,%1,%2,%3}, [%4];" \
                 : "=r"(D0), "=r"(D1), "=r"(D2), "=r"(D3) : "r"(A))

// ---------------- SMEM layout (64-row tile) ----------------
#define OFF_AH  0
#define OFF_AL  16384
#define OFF_WH  32768
#define OFF_WL  65536
#define OFF_MISC 98304
#define OFF_BIAS (OFF_MISC)
#define OFF_G    (OFF_MISC + 512)
#define OFF_BETA (OFF_MISC + 1024)
#define OFF_MEAN (OFF_MISC + 1536)
#define OFF_RSTD (OFF_MISC + 1856)
#define OFF_U    (OFF_MISC + 2176)
#define OFF_CV   (OFF_MISC + 4224)
#define SMEM_BYTES (OFF_MISC + 4256)
// C spill: 64 rows x 512B fp32, chunk-swizzled, over W region [OFF_WH, OFF_WH+32768)

__device__ __forceinline__ int CIDX(int row, int col) {
    return row * 128 + (((col >> 2) ^ (row & 7)) << 2) + (col & 3);
}
__device__ __forceinline__ int PIDX(int row, int cp) {
    return row * 64 + (((cp >> 2) ^ (row & 7)) << 2) + (cp & 3);
}

// ---------------- weight pre-conversion ----------------
__global__ void k_wconv(const float* w0, const float* w1, const float* w2, const float* w3,
                        const float* w4, const float* w5, const float* w6, const float* w7) {
    int m = blockIdx.x >> 4;
    const float* W;
    switch (m) {
        case 0: W = w0; break; case 1: W = w1; break; case 2: W = w2; break;
        case 3: W = w3; break; case 4: W = w4; break; case 5: W = w5; break;
        case 6: W = w6; break; default: W = w7; break;
    }
    int i = (blockIdx.x & 15) * 256 + threadIdx.x;
    int row = i >> 5, q = i & 31;
    float4 v = *reinterpret_cast<const float4*>(W + (size_t)row * 128 + q * 4);
    uint32_t h0, l0, h1, l1, h2, l2, h3, l3;
    hilo(v.x, h0, l0); hilo(v.y, h1, l1); hilo(v.z, h2, l2); hilo(v.w, h3, l3);
    uint2 uh, ul;
    uh.x = h0 | (h1 << 16); uh.y = h2 | (h3 << 16);
    ul.x = l0 | (l1 << 16); ul.y = l2 | (l3 << 16);
    char* base = (char*)g_wbuf + (size_t)m * 65536;
    int sw = row * 256 + q * 8;
    *reinterpret_cast<uint2*>(base + sw)         = uh;
    *reinterpret_cast<uint2*>(base + 32768 + sw) = ul;
}

// ---------------- GEMM fills ----------------
__device__ __forceinline__ void fill_copy(const uint32_t* __restrict__ gh,
                                          const uint32_t* __restrict__ gl,
                                          char* smem, int tile0, int nrows, int t) {
    const uint4* gh4 = reinterpret_cast<const uint4*>(gh);
    const uint4* gl4 = reinterpret_cast<const uint4*>(gl);
#pragma unroll
    for (int rep = 0; rep < 2; ++rep) {
        int i = t + rep * 512;
        int row = i >> 4, chunk = i & 15;
        int grow = tile0 + row;
        uint4 vh = make_uint4(0, 0, 0, 0), vl = make_uint4(0, 0, 0, 0);
        if (grow < nrows) { vh = gh4[grow * 16 + chunk]; vl = gl4[grow * 16 + chunk]; }
        int phys = row * 256 + ((chunk ^ (row & 7)) << 4);
        *reinterpret_cast<uint4*>(smem + OFF_AH + phys) = vh;
        *reinterpret_cast<uint4*>(smem + OFF_AL + phys) = vl;
    }
}
__device__ __forceinline__ void fill_convert(const float* __restrict__ A, char* smem,
                                             int tile0, int nrows, int t) {
#pragma unroll
    for (int rep = 0; rep < 4; ++rep) {
        int i = t + rep * 512;
        int row = i >> 5, q = i & 31;
        int grow = tile0 + row;
        float4 v = make_float4(0.f, 0.f, 0.f, 0.f);
        if (grow < nrows) v = *reinterpret_cast<const float4*>(A + (size_t)grow * HH + q * 4);
        uint32_t h0, l0, h1, l1, h2, l2, h3, l3;
        hilo(v.x, h0, l0); hilo(v.y, h1, l1); hilo(v.z, h2, l2); hilo(v.w, h3, l3);
        uint2 uh, ul;
        uh.x = h0 | (h1 << 16); uh.y = h2 | (h3 << 16);
        ul.x = l0 | (l1 << 16); ul.y = l2 | (l3 << 16);
        int phys = row * 256 + (((q >> 1) ^ (row & 7)) << 4) + (q & 1) * 8;
        *reinterpret_cast<uint2*>(smem + OFF_AH + phys) = uh;
        *reinterpret_cast<uint2*>(smem + OFF_AL + phys) = ul;
    }
}
__device__ __forceinline__ void fill_W(int slot, char* smem, int t) {
    const uint4* src = reinterpret_cast<const uint4*>((const char*)g_wbuf + (size_t)slot * 65536);
#pragma unroll
    for (int rep = 0; rep < 4; ++rep) {
        int i = t + rep * 512;
        int row = i >> 4, chunk = i & 15;
        int phys = row * 256 + ((chunk ^ (row & 7)) << 4);
        *reinterpret_cast<uint4*>(smem + OFF_WH + phys) = src[i];
        *reinterpret_cast<uint4*>(smem + OFF_WL + phys) = src[2048 + i];
    }
}

// ---------------- mainloop: 16x32 warp tile, 3-term split ----------------
__device__ __forceinline__ void mainloop(uint32_t sb, float c[4][4], int wm, int wn, int lane) {
    uint32_t rowA = wm * 16 + (lane & 15);
    uint32_t swA = rowA & 7;
    uint32_t aAddr = sb + OFF_AH + rowA * 256;
    uint32_t halfA = lane >> 4;
    uint32_t wrow = sb + OFF_WH + (uint32_t)(wn * 32 + lane) * 256;
    uint32_t swB = lane & 7;
#pragma unroll
    for (int ks = 0; ks < 8; ++ks) {
        uint32_t bh0[4], bh1[4], bl0[4], bl1[4];
        uint32_t cb0 = (uint32_t)(((2 * ks) ^ swB) << 4);
        uint32_t cb1 = (uint32_t)(((2 * ks + 1) ^ swB) << 4);
        LDSM4(bh0[0], bh0[1], bh0[2], bh0[3], wrow + cb0);
        LDSM4(bh1[0], bh1[1], bh1[2], bh1[3], wrow + cb1);
        LDSM4(bl0[0], bl0[1], bl0[2], bl0[3], wrow + 32768 + cb0);
        LDSM4(bl1[0], bl1[1], bl1[2], bl1[3], wrow + 32768 + cb1);
        uint32_t ca = (uint32_t)(((2 * ks + halfA) ^ swA) << 4);
        uint32_t ah0, ah1, ah2, ah3, al0, al1, al2, al3;
        LDSM4(ah0, ah1, ah2, ah3, aAddr + ca);
        LDSM4(al0, al1, al2, al3, aAddr + 16384 + ca);
#pragma unroll
        for (int nb = 0; nb < 4; ++nb) {
            HMMA(c[nb], ah0, ah1, ah2, ah3, bh0[nb], bh1[nb]);
            HMMA(c[nb], ah0, ah1, ah2, ah3, bl0[nb], bl1[nb]);
            HMMA(c[nb], al0, al1, al2, al3, bh0[nb], bh1[nb]);
        }
    }
}

// MODE: 0 = input proj (convert fill, relu, write planes)
//       1 = SAGE (pass1 agg@Wl, refill A with x, pass2 x@Wr; LN+relu+residual)
//       2 = V proj (copy fill, fused scores, write fp32 v)
template <int MODE>
__global__ void __launch_bounds__(512, 2) k_mma(
    const float* __restrict__ Afp,
    const uint32_t* __restrict__ p1h, const uint32_t* __restrict__ p1l,
    const uint32_t* __restrict__ p2h, const uint32_t* __restrict__ p2l,
    int wslot, const float* __restrict__ bias,
    const float* __restrict__ lng, const float* __restrict__ lnb,
    uint32_t* __restrict__ outh, uint32_t* __restrict__ outl,
    float* __restrict__ outf, int nrows)
{
    extern __shared__ char smem[];
    uint32_t sb = smem_u32(smem);
    int t = threadIdx.x, wid = t >> 5, lane = t & 31;
    int tile0 = blockIdx.x * 64;
    int wm = wid & 3, wn = wid >> 2;

    if (t < 128) {
        ((float*)(smem + OFF_BIAS))[t] = bias[t];
        if (MODE == 1) {
            ((float*)(smem + OFF_G))[t]    = lng[t];
            ((float*)(smem + OFF_BETA))[t] = lnb[t];
        }
    }
    if (MODE == 2) {
        if (t >= 128 && t < 256) ((float4*)(smem + OFF_U))[t - 128] = ((const float4*)g_U)[t - 128];
        if (t == 256) *((float4*)(smem + OFF_CV)) = *((const float4*)g_cvec);
    }

    float c[4][4];
#pragma unroll
    for (int nb = 0; nb < 4; ++nb)
#pragma unroll
        for (int j = 0; j < 4; ++j) c[nb][j] = 0.f;

    if (MODE == 0) fill_convert(Afp, smem, tile0, nrows, t);
    else           fill_copy(p1h, p1l, smem, tile0, nrows, t);
    fill_W(wslot, smem, t);
    __syncthreads();

    mainloop(sb, c, wm, wn, lane);

    if (MODE == 1) {
        __syncthreads();
        fill_copy(p2h, p2l, smem, tile0, nrows, t);  // A <- x
        fill_W(wslot + 1, smem, t);                  // W <- Wr
        __syncthreads();
        mainloop(sb, c, wm, wn, lane);
    }
    __syncthreads();

    // MODE 2: fused attention scores from A planes
    if (MODE == 2) {
        if (t < 64) {
            int grow = tile0 + t;
            if (grow < nrows) {
                const uint32_t* ph = (const uint32_t*)(smem + OFF_AH);
                const uint32_t* pl = (const uint32_t*)(smem + OFF_AL);
                const float4* U4 = (const float4*)(smem + OFF_U);
                const float* cv = (const float*)(smem + OFF_CV);
                float a0 = cv[0], a1 = cv[1], a2 = cv[2], a3 = cv[3];
#pragma unroll
                for (int kk = 0; kk < 64; ++kk) {
                    int idx = PIDX(t, kk);
                    float2 h = bf2f(ph[idx]);
                    float2 l = bf2f(pl[idx]);
                    float x0 = h.x + l.x, x1 = h.y + l.y;
                    float4 u0 = U4[2 * kk];
                    float4 u1 = U4[2 * kk + 1];
                    a0 += x0 * u0.x + x1 * u1.x;
                    a1 += x0 * u0.y + x1 * u1.y;
                    a2 += x0 * u0.z + x1 * u1.z;
                    a3 += x0 * u0.w + x1 * u1.w;
                }
                float4 r; r.x = a0; r.y = a1; r.z = a2; r.w = a3;
                reinterpret_cast<float4*>(g_scores)[grow] = r;
            }
        }
        __syncthreads();
    }

    // spill C over W region (chunk-swizzled fp32, 64 rows x 128 cols)
    float* Csm = (float*)(smem + OFF_WH);
    int g = lane >> 2, tt = lane & 3;
    {
        int r0 = wm * 16 + g;
        int r1 = r0 + 8;
#pragma unroll
        for (int nb = 0; nb < 4; ++nb) {
            int col = wn * 32 + nb * 8 + tt * 2;
            Csm[CIDX(r0, col)]     = c[nb][0];
            Csm[CIDX(r0, col + 1)] = c[nb][1];
            Csm[CIDX(r1, col)]     = c[nb][2];
            Csm[CIDX(r1, col + 1)] = c[nb][3];
        }
    }
    __syncthreads();

    const float* bs = (const float*)(smem + OFF_BIAS);
    if (MODE == 1) {
        if (t < 64) {
            float sum = 0.f, sq = 0.f;
#pragma unroll
            for (int j = 0; j < 128; ++j) {
                float x = Csm[CIDX(t, j)] + bs[j];
                sum += x; sq += x * x;
            }
            float mean = sum * (1.f / 128.f);
            float var  = sq * (1.f / 128.f) - mean * mean;
            ((float*)(smem + OFF_MEAN))[t] = mean;
            ((float*)(smem + OFF_RSTD))[t] = rsqrtf(var + 1e-5f);
        }
        __syncthreads();
    }

    if (MODE == 2) {
#pragma unroll
        for (int rep = 0; rep < 4; ++rep) {
            int i = t + rep * 512;
            int row = i >> 5, q = i & 31;
            int grow = tile0 + row;
            if (grow >= nrows) continue;
            int base = row * 128 + ((q ^ (row & 7)) << 2);
            float4 o;
            o.x = Csm[base + 0] + bs[q * 4 + 0];
            o.y = Csm[base + 1] + bs[q * 4 + 1];
            o.z = Csm[base + 2] + bs[q * 4 + 2];
            o.w = Csm[base + 3] + bs[q * 4 + 3];
            *reinterpret_cast<float4*>(outf + (size_t)grow * HH + q * 4) = o;
        }
    } else {
        const float* gg = (const float*)(smem + OFF_G);
        const float* bb = (const float*)(smem + OFF_BETA);
        const float* mn = (const float*)(smem + OFF_MEAN);
        const float* rs = (const float*)(smem + OFF_RSTD);
        const uint32_t* rxh = (const uint32_t*)(smem + OFF_AH);
        const uint32_t* rxl = (const uint32_t*)(smem + OFF_AL);
#pragma unroll
        for (int rep = 0; rep < 8; ++rep) {
            int i = t + rep * 512;
            int row = i >> 6, cp = i & 63;
            int grow = tile0 + row;
            if (grow >= nrows) continue;
            int c0 = cp * 2;
            float x0 = Csm[CIDX(row, c0)]     + bs[c0];
            float x1 = Csm[CIDX(row, c0 + 1)] + bs[c0 + 1];
            float o0, o1;
            if (MODE == 1) {
                float mean = mn[row], rstd = rs[row];
                int idx = PIDX(row, cp);
                float2 rh = bf2f(rxh[idx]);
                float2 rl = bf2f(rxl[idx]);
                o0 = fmaxf((x0 - mean) * rstd * gg[c0]     + bb[c0],     0.f) + (rh.x + rl.x);
                o1 = fmaxf((x1 - mean) * rstd * gg[c0 + 1] + bb[c0 + 1], 0.f) + (rh.y + rl.y);
            } else {
                o0 = fmaxf(x0, 0.f);
                o1 = fmaxf(x1, 0.f);
            }
            uint32_t h0, l0, h1, l1;
            hilo(o0, h0, l0); hilo(o1, h1, l1);
            outh[(size_t)grow * 64 + cp] = h0 | (h1 << 16);
            outl[(size_t)grow * 64 + cp] = l0 | (l1 << 16);
        }
    }
}

// ---------------- CSR build ----------------
__global__ void k_init() {
    int i = blockIdx.x * blockDim.x + threadIdx.x;
    if (i < NN) { g_deg[i] = 0; g_cur[i] = 0; }
}
__global__ void k_deg(const int* __restrict__ ei) {
    int e = blockIdx.x * blockDim.x + threadIdx.x;
    if (e < EE) atomicAdd(&g_deg[ei[EE + e]], 1);
}
__global__ void k_scan() {
    __shared__ int sm[1024];
    const int n = NN;
    const int chunk = (n + 1023) / 1024;
    int t = threadIdx.x;
    int base = t * chunk;
    int s = 0;
    for (int i = 0; i < chunk; ++i) {
        int idx = base + i;
        if (idx < n) s += g_deg[idx];
    }
    sm[t] = s;
    __syncthreads();
    for (int d = 1; d < 1024; d <<= 1) {
        int add = (t >= d) ? sm[t - d] : 0;
        __syncthreads();
        sm[t] += add;
        __syncthreads();
    }
    int run = sm[t] - s;
    for (int i = 0; i < chunk; ++i) {
        int idx = base + i;
        if (idx < n) { g_off[idx] = run; run += g_deg[idx]; }
    }
    if (t == 1023) g_off[n] = sm[1023];
}
__global__ void k_fill(const int* __restrict__ ei) {
    int e = blockIdx.x * blockDim.x + threadIdx.x;
    if (e < EE) {
        int s = ei[e];
        int d = ei[EE + e];
        int slot = atomicAdd(&g_cur[d], 1);
        g_col[g_off[d] + slot] = s;
    }
}

// ---------------- neighbor mean aggregation ----------------
__global__ void __launch_bounds__(256) k_aggr(const uint32_t* __restrict__ xh,
                                              const uint32_t* __restrict__ xl) {
    int warp = (blockIdx.x * blockDim.x + threadIdx.x) >> 5;
    int lane = threadIdx.x & 31;
    if (warp >= NN) return;
    int s0 = g_off[warp], s1 = g_off[warp + 1];
    float a0 = 0.f, a1 = 0.f, a2 = 0.f, a3 = 0.f;
    for (int i = s0; i < s1; ++i) {
        int nb = __ldg(&g_col[i]);
        uint2 vh = __ldg(reinterpret_cast<const uint2*>(xh + (size_t)nb * 64) + lane);
        uint2 vl = __ldg(reinterpret_cast<const uint2*>(xl + (size_t)nb * 64) + lane);
        float2 h0 = bf2f(vh.x), h1 = bf2f(vh.y);
        float2 l0 = bf2f(vl.x), l1 = bf2f(vl.y);
        a0 += h0.x + l0.x; a1 += h0.y + l0.y;
        a2 += h1.x + l1.x; a3 += h1.y + l1.y;
    }
    float inv = 1.f / fmaxf((float)(s1 - s0), 1.f);
    a0 *= inv; a1 *= inv; a2 *= inv; a3 *= inv;
    uint32_t h0, l0, h1, l1, h2, l2, h3, l3;
    hilo(a0, h0, l0); hilo(a1, h1, l1); hilo(a2, h2, l2); hilo(a3, h3, l3);
    uint2 uh, ul;
    uh.x = h0 | (h1 << 16); uh.y = h2 | (h3 << 16);
    ul.x = l0 | (l1 << 16); ul.y = l2 | (l3 << 16);
    reinterpret_cast<uint2*>(g_aggh + (size_t)warp * 64)[lane] = uh;
    reinterpret_cast<uint2*>(g_aggl + (size_t)warp * 64)[lane] = ul;
}

// ---------------- attention prep ----------------
__global__ void k_prep(const float* __restrict__ in_proj_W,
                       const float* __restrict__ in_proj_b,
                       const float* __restrict__ query) {
    __shared__ float qv[128];
    int t = threadIdx.x;
    float s = in_proj_b[t];
    for (int k = 0; k < 128; ++k) s = fmaf(in_proj_W[t * 128 + k], query[k], s);
    qv[t] = s;
    __syncthreads();
    const float inv = 1.0f / sqrtf(32.0f);
    float u[4] = {0.f, 0.f, 0.f, 0.f};
    for (int r = 0; r < 128; ++r) {
        float w = in_proj_W[(128 + r) * 128 + t];
        u[r >> 5] = fmaf(qv[r], w, u[r >> 5]);
    }
#pragma unroll
    for (int h = 0; h < 4; ++h) g_U[t * 4 + h] = u[h] * inv;
    if (t < 4) {
        float cc = 0.f;
        for (int d = 0; d < 32; ++d) cc = fmaf(qv[t * 32 + d], in_proj_b[128 + t * 32 + d], cc);
        g_cvec[t] = cc * inv;
    }
}

// ---------------- graph boundaries ----------------
__global__ void k_gbounds(const int* __restrict__ batch) {
    int i = blockIdx.x * blockDim.x + threadIdx.x;
    if (i >= NN) return;
    int bi = batch[i];
    if (i == 0) {
        for (int g = 0; g <= bi; ++g) g_gstart[g] = 0;
    } else {
        int bp = batch[i - 1];
        for (int g = bp + 1; g <= bi; ++g) g_gstart[g] = i;
    }
    if (i == NN - 1) {
        for (int g = bi + 1; g <= BB; ++g) g_gstart[g] = NN;
    }
}

// ---------------- per-graph softmax pool ----------------
__global__ void __launch_bounds__(256) k_pool() {
    int b = blockIdx.x;
    int s0 = g_gstart[b], s1 = g_gstart[b + 1];
    int t = threadIdx.x;
    __shared__ float4 red[256];
    __shared__ float smax[4];
    __shared__ float pbuf[256];
    __shared__ float dbuf[8];

    float4 mx = make_float4(-1e30f, -1e30f, -1e30f, -1e30f);
    for (int n = s0 + t; n < s1; n += 256) {
        float4 f = reinterpret_cast<const float4*>(g_scores)[n];
        mx.x = fmaxf(mx.x, f.x); mx.y = fmaxf(mx.y, f.y);
        mx.z = fmaxf(mx.z, f.z); mx.w = fmaxf(mx.w, f.w);
    }
    red[t] = mx;
    __syncthreads();
    for (int s = 128; s > 0; s >>= 1) {
        if (t < s) {
            float4 a = red[t], c = red[t + s];
            a.x = fmaxf(a.x, c.x); a.y = fmaxf(a.y, c.y);
            a.z = fmaxf(a.z, c.z); a.w = fmaxf(a.w, c.w);
            red[t] = a;
        }
        __syncthreads();
    }
    if (t == 0) { smax[0] = red[0].x; smax[1] = red[0].y; smax[2] = red[0].z; smax[3] = red[0].w; }
    __syncthreads();

    int tau = t >> 7, j = t & 127, h = j >> 5;
    float m = smax[h];
    float pl = 0.f, den = 0.f;
    for (int n = s0 + tau; n < s1; n += 2) {
        float e = expf(g_scores[n * 4 + h] - m);
        pl = fmaf(e, g_v[(size_t)n * HH + j], pl);
        den += e;
    }
    pbuf[t] = pl;
    if ((j & 31) == 0) dbuf[tau * 4 + h] = den;
    __syncthreads();
    if (t < 128) {
        float d = dbuf[h] + dbuf[4 + h];
        float p = pbuf[t] + pbuf[128 + t];
        g_pooled[b * HH + t] = (d > 0.f) ? p / d : 0.f;
    }
}

// ---------------- tail ----------------
__device__ __forceinline__ float block_ln128(float v, float gamma, float beta,
                                             float* ws, float* wq) {
    float s = warp_sum(v);
    float q = warp_sum(v * v);
    int wid = threadIdx.x >> 5, lane = threadIdx.x & 31;
    if (lane == 0) { ws[wid] = s; wq[wid] = q; }
    __syncthreads();
    float ts = ws[0] + ws[1] + ws[2] + ws[3];
    float tq = wq[0] + wq[1] + wq[2] + wq[3];
    __syncthreads();
    float mean = ts * (1.f / 128.f);
    float var  = tq * (1.f / 128.f) - mean * mean;
    return (v - mean) * rsqrtf(var + 1e-5f) * gamma + beta;
}

__global__ void __launch_bounds__(128) k_tail(
    const float* __restrict__ out_W, const float* __restrict__ out_b,
    const float* __restrict__ symfeat,
    const float* __restrict__ sym_W, const float* __restrict__ sym_b,
    const float* __restrict__ symf_W, const float* __restrict__ symf_b,
    const float* __restrict__ symf_g, const float* __restrict__ symf_beta,
    const float* __restrict__ fus_W, const float* __restrict__ fus_b,
    const float* __restrict__ fus_g, const float* __restrict__ fus_beta,
    const float* __restrict__ hW1, const float* __restrict__ hb1,
    const float* __restrict__ hW2, const float* __restrict__ hb2,
    float* __restrict__ outp)
{
    int b = blockIdx.x;
    int t = threadIdx.x;
    __shared__ float p[128];
    __shared__ float cat[256];
    __shared__ float buf[128];
    __shared__ float hh[192];
    __shared__ float ws[4], wq[4];

    p[t] = g_pooled[b * HH + t];
    __syncthreads();
    {
        float acc = out_b[t];
        for (int k = 0; k < 128; ++k) acc = fmaf(out_W[t * 128 + k], p[k], acc);
        cat[t] = acc;
    }
    {
        int f = t >> 5, o = t & 31;
        const float* sf = symfeat + b * 64 + f * 16;
        const float* w  = sym_W + (f * 32 + o) * 16;
        float s = sym_b[f * 32 + o];
#pragma unroll
        for (int i = 0; i < 16; ++i) s = fmaf(w[i], sf[i], s);
        buf[t] = fmaxf(s, 0.f);
    }
    __syncthreads();
    {
        float s2 = symf_b[t];
        for (int k = 0; k < 128; ++k) s2 = fmaf(symf_W[t * 128 + k], buf[k], s2);
        s2 = fmaxf(s2, 0.f);
        float v = block_ln128(s2, symf_g[t], symf_beta[t], ws, wq);
        cat[128 + t] = v;
    }
    __syncthreads();
    {
        float f = fus_b[t];
        for (int k = 0; k < 256; ++k) f = fmaf(fus_W[t * 256 + k], cat[k], f);
        f = fmaxf(f, 0.f);
        float v = block_ln128(f, fus_g[t], fus_beta[t], ws, wq);
        p[t] = v;
    }
    __syncthreads();
    for (int idx = t; idx < 192; idx += 128) {
        int k = idx >> 6, o = idx & 63;
        const float* w = hW1 + (size_t)(k * 64 + o) * 128;
        float acc = hb1[k * 64 + o];
        for (int j = 0; j < 128; ++j) acc = fmaf(w[j], p[j], acc);
        hh[idx] = fmaxf(acc, 0.f);
    }
    __syncthreads();
    if (t < 3) {
        float z = hb2[t];
        for (int o = 0; o < 64; ++o) z = fmaf(hW2[t * 64 + o], hh[t * 64 + o], z);
        outp[t * BB + b] = 1.f / (1.f + expf(-z));
    }
}

// ---------------- host ----------------
extern "C" void kernel_launch(void* const* d_in, const int* in_sizes, int n_in,
                              void* d_out, int out_size) {
    const float* nf = nullptr;
    const float* symf = nullptr;
    const int* ei = nullptr;
    const int* batch = nullptr;
    const float* P[26];
    int pi = 0;
    for (int i = 0; i < n_in; ++i) {
        int sz = in_sizes[i];
        if (sz == NN * HH)       nf    = (const float*)d_in[i];
        else if (sz == BB * 64)  symf  = (const float*)d_in[i];
        else if (sz == 2 * EE)   ei    = (const int*)d_in[i];
        else if (sz == NN)       batch = (const int*)d_in[i];
        else if (pi < 26)        P[pi++] = (const float*)d_in[i];
    }
    const float *W_in = P[0], *b_in = P[1], *sage_Wl = P[2], *sage_bl = P[3],
                *sage_Wr = P[4], *ln_g = P[5], *ln_b = P[6], *query = P[7],
                *in_proj_W = P[8], *in_proj_b = P[9], *out_W = P[10], *out_b = P[11],
                *sym_W = P[12], *sym_b = P[13], *symf_W = P[14], *symf_b = P[15],
                *symf_g = P[16], *symf_beta = P[17], *fus_W = P[18], *fus_b = P[19],
                *fus_g = P[20], *fus_beta = P[21], *hW1 = P[22], *hb1 = P[23],
                *hW2 = P[24], *hb2 = P[25];

    uint32_t *pxh, *pxl, *pxh2, *pxl2, *pah, *pal;
    float* pv;
    cudaGetSymbolAddress((void**)&pxh,  g_xh);
    cudaGetSymbolAddress((void**)&pxl,  g_xl);
    cudaGetSymbolAddress((void**)&pxh2, g_xh2);
    cudaGetSymbolAddress((void**)&pxl2, g_xl2);
    cudaGetSymbolAddress((void**)&pah,  g_aggh);
    cudaGetSymbolAddress((void**)&pal,  g_aggl);
    cudaGetSymbolAddress((void**)&pv,   g_v);

    cudaFuncSetAttribute((const void*)k_mma<0>, cudaFuncAttributeMaxDynamicSharedMemorySize, SMEM_BYTES);
    cudaFuncSetAttribute((const void*)k_mma<1>, cudaFuncAttributeMaxDynamicSharedMemorySize, SMEM_BYTES);
    cudaFuncSetAttribute((const void*)k_mma<2>, cudaFuncAttributeMaxDynamicSharedMemorySize, SMEM_BYTES);

    // weight slots: 0=W_in, 1=Wl0, 2=Wr0, 3=Wl1, 4=Wr1, 5=Wl2, 6=Wr2, 7=Wv
    k_wconv<<<128, 256>>>(W_in,
                          sage_Wl + 0 * 16384, sage_Wr + 0 * 16384,
                          sage_Wl + 1 * 16384, sage_Wr + 1 * 16384,
                          sage_Wl + 2 * 16384, sage_Wr + 2 * 16384,
                          in_proj_W + 256 * 128);
    k_init<<<(NN + 255) / 256, 256>>>();
    k_deg<<<(EE + 255) / 256, 256>>>(ei);
    // index 3: input-proj GEMM (profiled sample slot)
    k_mma<0><<<TILES64, 512, SMEM_BYTES>>>(nf, nullptr, nullptr, nullptr, nullptr,
                                           0, b_in, nullptr, nullptr, pxh, pxl, nullptr, NN);
    k_scan<<<1, 1024>>>();
    k_fill<<<(EE + 255) / 256, 256>>>(ei);
    k_prep<<<1, 128>>>(in_proj_W, in_proj_b, query);
    k_gbounds<<<(NN + 255) / 256, 256>>>(batch);

    uint32_t *curh = pxh, *curl = pxl, *nxth = pxh2, *nxtl = pxl2;
    for (int l = 0; l < 3; ++l) {
        k_aggr<<<(NN * 32 + 255) / 256, 256>>>(curh, curl);
        k_mma<1><<<TILES64, 512, SMEM_BYTES>>>(nullptr, pah, pal, curh, curl,
                                               1 + 2 * l, sage_bl + l * 128,
                                               ln_g + l * 128, ln_b + l * 128,
                                               nxth, nxtl, nullptr, NN);
        uint32_t* th = curh; curh = nxth; nxth = th;
        uint32_t* tl = curl; curl = nxtl; nxtl = tl;
    }

    // v = x @ Wv^T + bv (fp32) + fused attention scores
    k_mma<2><<<TILES64, 512, SMEM_BYTES>>>(nullptr, curh, curl, nullptr, nullptr,
                                           7, in_proj_b + 256, nullptr, nullptr,
                                           nullptr, nullptr, pv, NN);

    k_pool<<<BB, 256>>>();
    k_tail<<<BB, 128>>>(out_W, out_b, symf, sym_W, sym_b,
                        symf_W, symf_b, symf_g, symf_beta,
                        fus_W, fus_b, fus_g, fus_beta,
                        hW1, hb1, hW2, hb2, (float*)d_out);
    (void)out_size;
}

// round 7
// speedup vs baseline: 1.5092x; 1.1806x over previous
#include <cuda_runtime.h>
#include <cuda_bf16.h>
#include <math.h>
#include <stdint.h>

#define NN 50000
#define EE 800000
#define BB 64
#define HH 128
#define TILES64 782   // ceil(50000/64)
#define SPLITS 8

// ---------------- scratch (device globals) ----------------
__device__ uint32_t g_xh [NN * 64];
__device__ uint32_t g_xl [NN * 64];
__device__ uint32_t g_xh2[NN * 64];
__device__ uint32_t g_xl2[NN * 64];
__device__ uint32_t g_aggh[NN * 64];
__device__ uint32_t g_aggl[NN * 64];
__device__ float g_v   [NN * HH];
__device__ float g_scores[NN * 4];
__device__ float g_U[HH * 4];
__device__ float g_cvec[4];
__device__ float g_pm[BB * SPLITS * 4];
__device__ float g_pd[BB * SPLITS * 4];
__device__ float g_pp[BB * SPLITS * 128];
__device__ int   g_deg[NN];
__device__ int   g_off[NN + 1];
__device__ int   g_cur[NN];
__device__ int   g_col[EE];
__device__ int   g_gstart[BB + 1];
__device__ uint4 g_wbuf[8 * 4096];

// ---------------- helpers ----------------
__device__ __forceinline__ void hilo(float v, uint32_t& h, uint32_t& l) {
    __nv_bfloat16 hb = __float2bfloat16(v);
    __nv_bfloat16 lb = __float2bfloat16(v - __bfloat162float(hb));
    h = (uint32_t)__bfloat16_as_ushort(hb);
    l = (uint32_t)__bfloat16_as_ushort(lb);
}
__device__ __forceinline__ float2 bf2f(uint32_t u) {
    __nv_bfloat162 h;
    *reinterpret_cast<uint32_t*>(&h) = u;
    return __bfloat1622float2(h);
}
__device__ __forceinline__ uint32_t smem_u32(const void* p) {
    uint32_t a;
    asm("{ .reg .u64 t; cvta.to.shared.u64 t, %1; cvt.u32.u64 %0, t; }" : "=r"(a) : "l"(p));
    return a;
}
__device__ __forceinline__ float warp_sum(float v) {
#pragma unroll
    for (int o = 16; o > 0; o >>= 1) v += __shfl_xor_sync(0xffffffffu, v, o);
    return v;
}

#define HMMA(C, A0, A1, A2, A3, B0, B1) \
    asm volatile("mma.sync.aligned.m16n8k16.row.col.f32.bf16.bf16.f32 " \
                 "{%0,%1,%2,%3}, {%4,%5,%6,%7}, {%8,%9}, {%0,%1,%2,%3};" \
                 : "+f"((C)[0]), "+f"((C)[1]), "+f"((C)[2]), "+f"((C)[3]) \
                 : "r"(A0), "r"(A1), "r"(A2), "r"(A3), "r"(B0), "r"(B1))

#define LDSM4(D0, D1, D2, D3, A) \
    asm volatile("ldmatrix.sync.aligned.m8n8.x4.shared.b16 {%0,%1,%2,%3}, [%4];" \
                 : "=r"(D0), "=r"(D1), "=r"(D2), "=r"(D3) : "r"(A))

#define CP_ASYNC16(dst, src, sz) \
    asm volatile("cp.async.cg.shared.global [%0], [%1], 16, %2;" \
                 :: "r"(dst), "l"(src), "r"(sz) : "memory")
#define CP_COMMIT() asm volatile("cp.async.commit_group;" ::: "memory")
#define CP_WAIT0()  asm volatile("cp.async.wait_group 0;" ::: "memory")

// ---------------- SMEM layout (64-row tile) ----------------
#define OFF_AH  0
#define OFF_AL  16384
#define OFF_WH  32768
#define OFF_WL  65536
#define OFF_MISC 98304
#define OFF_BIAS (OFF_MISC)
#define OFF_G    (OFF_MISC + 512)
#define OFF_BETA (OFF_MISC + 1024)
#define OFF_MEAN (OFF_MISC + 1536)
#define OFF_RSTD (OFF_MISC + 1856)
#define OFF_U    (OFF_MISC + 2176)
#define OFF_CV   (OFF_MISC + 4224)
#define SMEM_BYTES (OFF_MISC + 4256)

__device__ __forceinline__ int CIDX(int row, int col) {
    return row * 128 + (((col >> 2) ^ (row & 7)) << 2) + (col & 3);
}
__device__ __forceinline__ int PIDX(int row, int cp) {
    return row * 64 + (((cp >> 2) ^ (row & 7)) << 2) + (cp & 3);
}

// ---------------- weight pre-conversion ----------------
__global__ void k_wconv(const float* w0, const float* w1, const float* w2, const float* w3,
                        const float* w4, const float* w5, const float* w6, const float* w7) {
    int m = blockIdx.x >> 4;
    const float* W;
    switch (m) {
        case 0: W = w0; break; case 1: W = w1; break; case 2: W = w2; break;
        case 3: W = w3; break; case 4: W = w4; break; case 5: W = w5; break;
        case 6: W = w6; break; default: W = w7; break;
    }
    int i = (blockIdx.x & 15) * 256 + threadIdx.x;
    int row = i >> 5, q = i & 31;
    float4 v = *reinterpret_cast<const float4*>(W + (size_t)row * 128 + q * 4);
    uint32_t h0, l0, h1, l1, h2, l2, h3, l3;
    hilo(v.x, h0, l0); hilo(v.y, h1, l1); hilo(v.z, h2, l2); hilo(v.w, h3, l3);
    uint2 uh, ul;
    uh.x = h0 | (h1 << 16); uh.y = h2 | (h3 << 16);
    ul.x = l0 | (l1 << 16); ul.y = l2 | (l3 << 16);
    char* base = (char*)g_wbuf + (size_t)m * 65536;
    int sw = row * 256 + q * 8;
    *reinterpret_cast<uint2*>(base + sw)         = uh;
    *reinterpret_cast<uint2*>(base + 32768 + sw) = ul;
}

// ---------------- GEMM fills ----------------
__device__ __forceinline__ void fill_copy_async(const uint32_t* __restrict__ gh,
                                                const uint32_t* __restrict__ gl,
                                                uint32_t sb, int tile0, int nrows, int t) {
#pragma unroll
    for (int rep = 0; rep < 2; ++rep) {
        int i = t + rep * 512;
        int row = i >> 4, chunk = i & 15;
        int grow = tile0 + row;
        int phys = row * 256 + ((chunk ^ (row & 7)) << 4);
        int sz = (grow < nrows) ? 16 : 0;
        const char* srch = (const char*)(gh + (size_t)grow * 64) + chunk * 16;
        const char* srcl = (const char*)(gl + (size_t)grow * 64) + chunk * 16;
        CP_ASYNC16(sb + OFF_AH + phys, srch, sz);
        CP_ASYNC16(sb + OFF_AL + phys, srcl, sz);
    }
}
__device__ __forceinline__ void fill_W_async(int slot, uint32_t sb, int t) {
    const char* src = (const char*)g_wbuf + (size_t)slot * 65536;
#pragma unroll
    for (int rep = 0; rep < 4; ++rep) {
        int i = t + rep * 512;
        int row = i >> 4, chunk = i & 15;
        int phys = row * 256 + ((chunk ^ (row & 7)) << 4);
        CP_ASYNC16(sb + OFF_WH + phys, src + i * 16, 16);
        CP_ASYNC16(sb + OFF_WL + phys, src + 32768 + i * 16, 16);
    }
}
__device__ __forceinline__ void fill_convert(const float* __restrict__ A, char* smem,
                                             int tile0, int nrows, int t) {
#pragma unroll
    for (int rep = 0; rep < 4; ++rep) {
        int i = t + rep * 512;
        int row = i >> 5, q = i & 31;
        int grow = tile0 + row;
        float4 v = make_float4(0.f, 0.f, 0.f, 0.f);
        if (grow < nrows) v = *reinterpret_cast<const float4*>(A + (size_t)grow * HH + q * 4);
        uint32_t h0, l0, h1, l1, h2, l2, h3, l3;
        hilo(v.x, h0, l0); hilo(v.y, h1, l1); hilo(v.z, h2, l2); hilo(v.w, h3, l3);
        uint2 uh, ul;
        uh.x = h0 | (h1 << 16); uh.y = h2 | (h3 << 16);
        ul.x = l0 | (l1 << 16); ul.y = l2 | (l3 << 16);
        int phys = row * 256 + (((q >> 1) ^ (row & 7)) << 4) + (q & 1) * 8;
        *reinterpret_cast<uint2*>(smem + OFF_AH + phys) = uh;
        *reinterpret_cast<uint2*>(smem + OFF_AL + phys) = ul;
    }
}

// ---------------- mainloop: 16x32 warp tile, 3-term split ----------------
__device__ __forceinline__ void mainloop(uint32_t sb, float c[4][4], int wm, int wn, int lane) {
    uint32_t rowA = wm * 16 + (lane & 15);
    uint32_t swA = rowA & 7;
    uint32_t aAddr = sb + OFF_AH + rowA * 256;
    uint32_t halfA = lane >> 4;
    uint32_t wrow = sb + OFF_WH + (uint32_t)(wn * 32 + lane) * 256;
    uint32_t swB = lane & 7;
#pragma unroll
    for (int ks = 0; ks < 8; ++ks) {
        uint32_t bh0[4], bh1[4], bl0[4], bl1[4];
        uint32_t cb0 = (uint32_t)(((2 * ks) ^ swB) << 4);
        uint32_t cb1 = (uint32_t)(((2 * ks + 1) ^ swB) << 4);
        LDSM4(bh0[0], bh0[1], bh0[2], bh0[3], wrow + cb0);
        LDSM4(bh1[0], bh1[1], bh1[2], bh1[3], wrow + cb1);
        LDSM4(bl0[0], bl0[1], bl0[2], bl0[3], wrow + 32768 + cb0);
        LDSM4(bl1[0], bl1[1], bl1[2], bl1[3], wrow + 32768 + cb1);
        uint32_t ca = (uint32_t)(((2 * ks + halfA) ^ swA) << 4);
        uint32_t ah0, ah1, ah2, ah3, al0, al1, al2, al3;
        LDSM4(ah0, ah1, ah2, ah3, aAddr + ca);
        LDSM4(al0, al1, al2, al3, aAddr + 16384 + ca);
#pragma unroll
        for (int nb = 0; nb < 4; ++nb) {
            HMMA(c[nb], ah0, ah1, ah2, ah3, bh0[nb], bh1[nb]);
            HMMA(c[nb], ah0, ah1, ah2, ah3, bl0[nb], bl1[nb]);
            HMMA(c[nb], al0, al1, al2, al3, bh0[nb], bh1[nb]);
        }
    }
}

// MODE: 0 = input proj, 1 = SAGE, 2 = V proj + scores
template <int MODE>
__global__ void __launch_bounds__(512, 2) k_mma(
    const float* __restrict__ Afp,
    const uint32_t* __restrict__ p1h, const uint32_t* __restrict__ p1l,
    const uint32_t* __restrict__ p2h, const uint32_t* __restrict__ p2l,
    int wslot, const float* __restrict__ bias,
    const float* __restrict__ lng, const float* __restrict__ lnb,
    uint32_t* __restrict__ outh, uint32_t* __restrict__ outl,
    float* __restrict__ outf, int nrows)
{
    extern __shared__ char smem[];
    uint32_t sb = smem_u32(smem);
    int t = threadIdx.x, wid = t >> 5, lane = t & 31;
    int tile0 = blockIdx.x * 64;
    int wm = wid & 3, wn = wid >> 2;

    fill_W_async(wslot, sb, t);
    if (MODE != 0) fill_copy_async(p1h, p1l, sb, tile0, nrows, t);
    CP_COMMIT();

    if (t < 128) {
        ((float*)(smem + OFF_BIAS))[t] = bias[t];
        if (MODE == 1) {
            ((float*)(smem + OFF_G))[t]    = lng[t];
            ((float*)(smem + OFF_BETA))[t] = lnb[t];
        }
    }
    if (MODE == 2) {
        if (t >= 128 && t < 256) ((float4*)(smem + OFF_U))[t - 128] = ((const float4*)g_U)[t - 128];
        if (t == 256) *((float4*)(smem + OFF_CV)) = *((const float4*)g_cvec);
    }
    if (MODE == 0) fill_convert(Afp, smem, tile0, nrows, t);

    float c[4][4];
#pragma unroll
    for (int nb = 0; nb < 4; ++nb)
#pragma unroll
        for (int j = 0; j < 4; ++j) c[nb][j] = 0.f;

    CP_WAIT0();
    __syncthreads();

    mainloop(sb, c, wm, wn, lane);

    if (MODE == 1) {
        __syncthreads();
        fill_copy_async(p2h, p2l, sb, tile0, nrows, t);
        fill_W_async(wslot + 1, sb, t);
        CP_COMMIT();
        CP_WAIT0();
        __syncthreads();
        mainloop(sb, c, wm, wn, lane);
    }
    __syncthreads();

    if (MODE == 2) {
        if (t < 64) {
            int grow = tile0 + t;
            if (grow < nrows) {
                const uint32_t* ph = (const uint32_t*)(smem + OFF_AH);
                const uint32_t* pl = (const uint32_t*)(smem + OFF_AL);
                const float4* U4 = (const float4*)(smem + OFF_U);
                const float* cv = (const float*)(smem + OFF_CV);
                float a0 = cv[0], a1 = cv[1], a2 = cv[2], a3 = cv[3];
#pragma unroll
                for (int kk = 0; kk < 64; ++kk) {
                    int idx = PIDX(t, kk);
                    float2 h = bf2f(ph[idx]);
                    float2 l = bf2f(pl[idx]);
                    float x0 = h.x + l.x, x1 = h.y + l.y;
                    float4 u0 = U4[2 * kk];
                    float4 u1 = U4[2 * kk + 1];
                    a0 += x0 * u0.x + x1 * u1.x;
                    a1 += x0 * u0.y + x1 * u1.y;
                    a2 += x0 * u0.z + x1 * u1.z;
                    a3 += x0 * u0.w + x1 * u1.w;
                }
                float4 r; r.x = a0; r.y = a1; r.z = a2; r.w = a3;
                reinterpret_cast<float4*>(g_scores)[grow] = r;
            }
        }
        __syncthreads();
    }

    float* Csm = (float*)(smem + OFF_WH);
    int g = lane >> 2, tt = lane & 3;
    {
        int r0 = wm * 16 + g;
        int r1 = r0 + 8;
#pragma unroll
        for (int nb = 0; nb < 4; ++nb) {
            int col = wn * 32 + nb * 8 + tt * 2;
            Csm[CIDX(r0, col)]     = c[nb][0];
            Csm[CIDX(r0, col + 1)] = c[nb][1];
            Csm[CIDX(r1, col)]     = c[nb][2];
            Csm[CIDX(r1, col + 1)] = c[nb][3];
        }
    }
    __syncthreads();

    const float* bs = (const float*)(smem + OFF_BIAS);
    if (MODE == 1) {
        if (t < 64) {
            float sum = 0.f, sq = 0.f;
#pragma unroll
            for (int j = 0; j < 128; ++j) {
                float x = Csm[CIDX(t, j)] + bs[j];
                sum += x; sq += x * x;
            }
            float mean = sum * (1.f / 128.f);
            float var  = sq * (1.f / 128.f) - mean * mean;
            ((float*)(smem + OFF_MEAN))[t] = mean;
            ((float*)(smem + OFF_RSTD))[t] = rsqrtf(var + 1e-5f);
        }
        __syncthreads();
    }

    if (MODE == 2) {
#pragma unroll
        for (int rep = 0; rep < 4; ++rep) {
            int i = t + rep * 512;
            int row = i >> 5, q = i & 31;
            int grow = tile0 + row;
            if (grow >= nrows) continue;
            int base = row * 128 + ((q ^ (row & 7)) << 2);
            float4 o;
            o.x = Csm[base + 0] + bs[q * 4 + 0];
            o.y = Csm[base + 1] + bs[q * 4 + 1];
            o.z = Csm[base + 2] + bs[q * 4 + 2];
            o.w = Csm[base + 3] + bs[q * 4 + 3];
            *reinterpret_cast<float4*>(outf + (size_t)grow * HH + q * 4) = o;
        }
    } else {
        const float* gg = (const float*)(smem + OFF_G);
        const float* bb = (const float*)(smem + OFF_BETA);
        const float* mn = (const float*)(smem + OFF_MEAN);
        const float* rs = (const float*)(smem + OFF_RSTD);
        const uint32_t* rxh = (const uint32_t*)(smem + OFF_AH);
        const uint32_t* rxl = (const uint32_t*)(smem + OFF_AL);
#pragma unroll
        for (int rep = 0; rep < 8; ++rep) {
            int i = t + rep * 512;
            int row = i >> 6, cp = i & 63;
            int grow = tile0 + row;
            if (grow >= nrows) continue;
            int c0 = cp * 2;
            float x0 = Csm[CIDX(row, c0)]     + bs[c0];
            float x1 = Csm[CIDX(row, c0 + 1)] + bs[c0 + 1];
            float o0, o1;
            if (MODE == 1) {
                float mean = mn[row], rstd = rs[row];
                int idx = PIDX(row, cp);
                float2 rh = bf2f(rxh[idx]);
                float2 rl = bf2f(rxl[idx]);
                o0 = fmaxf((x0 - mean) * rstd * gg[c0]     + bb[c0],     0.f) + (rh.x + rl.x);
                o1 = fmaxf((x1 - mean) * rstd * gg[c0 + 1] + bb[c0 + 1], 0.f) + (rh.y + rl.y);
            } else {
                o0 = fmaxf(x0, 0.f);
                o1 = fmaxf(x1, 0.f);
            }
            uint32_t h0, l0, h1, l1;
            hilo(o0, h0, l0); hilo(o1, h1, l1);
            outh[(size_t)grow * 64 + cp] = h0 | (h1 << 16);
            outl[(size_t)grow * 64 + cp] = l0 | (l1 << 16);
        }
    }
}

// ---------------- CSR build ----------------
__global__ void k_init() {
    int i = blockIdx.x * blockDim.x + threadIdx.x;
    if (i < NN) { g_deg[i] = 0; g_cur[i] = 0; }
}
__global__ void k_deg(const int* __restrict__ ei) {
    int e = blockIdx.x * blockDim.x + threadIdx.x;
    if (e < EE) atomicAdd(&g_deg[ei[EE + e]], 1);
}
__global__ void k_scan() {
    __shared__ int sm[1024];
    const int n = NN;
    const int chunk = (n + 1023) / 1024;
    int t = threadIdx.x;
    int base = t * chunk;
    int s = 0;
    for (int i = 0; i < chunk; ++i) {
        int idx = base + i;
        if (idx < n) s += g_deg[idx];
    }
    sm[t] = s;
    __syncthreads();
    for (int d = 1; d < 1024; d <<= 1) {
        int add = (t >= d) ? sm[t - d] : 0;
        __syncthreads();
        sm[t] += add;
        __syncthreads();
    }
    int run = sm[t] - s;
    for (int i = 0; i < chunk; ++i) {
        int idx = base + i;
        if (idx < n) { g_off[idx] = run; run += g_deg[idx]; }
    }
    if (t == 1023) g_off[n] = sm[1023];
}
__global__ void k_fill(const int* __restrict__ ei) {
    int e = blockIdx.x * blockDim.x + threadIdx.x;
    if (e < EE) {
        int s = ei[e];
        int d = ei[EE + e];
        int slot = atomicAdd(&g_cur[d], 1);
        g_col[g_off[d] + slot] = s;
    }
}

// ---------------- neighbor mean aggregation ----------------
__global__ void __launch_bounds__(256) k_aggr(const uint32_t* __restrict__ xh,
                                              const uint32_t* __restrict__ xl) {
    int warp = (blockIdx.x * blockDim.x + threadIdx.x) >> 5;
    int lane = threadIdx.x & 31;
    if (warp >= NN) return;
    int s0 = g_off[warp], s1 = g_off[warp + 1];
    float a0 = 0.f, a1 = 0.f, a2 = 0.f, a3 = 0.f;
    for (int i = s0; i < s1; ++i) {
        int nb = __ldg(&g_col[i]);
        uint2 vh = __ldg(reinterpret_cast<const uint2*>(xh + (size_t)nb * 64) + lane);
        uint2 vl = __ldg(reinterpret_cast<const uint2*>(xl + (size_t)nb * 64) + lane);
        float2 h0 = bf2f(vh.x), h1 = bf2f(vh.y);
        float2 l0 = bf2f(vl.x), l1 = bf2f(vl.y);
        a0 += h0.x + l0.x; a1 += h0.y + l0.y;
        a2 += h1.x + l1.x; a3 += h1.y + l1.y;
    }
    float inv = 1.f / fmaxf((float)(s1 - s0), 1.f);
    a0 *= inv; a1 *= inv; a2 *= inv; a3 *= inv;
    uint32_t h0, l0, h1, l1, h2, l2, h3, l3;
    hilo(a0, h0, l0); hilo(a1, h1, l1); hilo(a2, h2, l2); hilo(a3, h3, l3);
    uint2 uh, ul;
    uh.x = h0 | (h1 << 16); uh.y = h2 | (h3 << 16);
    ul.x = l0 | (l1 << 16); ul.y = l2 | (l3 << 16);
    reinterpret_cast<uint2*>(g_aggh + (size_t)warp * 64)[lane] = uh;
    reinterpret_cast<uint2*>(g_aggl + (size_t)warp * 64)[lane] = ul;
}

// ---------------- attention prep ----------------
__global__ void k_prep(const float* __restrict__ in_proj_W,
                       const float* __restrict__ in_proj_b,
                       const float* __restrict__ query) {
    __shared__ float qv[128];
    int t = threadIdx.x;
    float s = in_proj_b[t];
    for (int k = 0; k < 128; ++k) s = fmaf(in_proj_W[t * 128 + k], query[k], s);
    qv[t] = s;
    __syncthreads();
    const float inv = 1.0f / sqrtf(32.0f);
    float u[4] = {0.f, 0.f, 0.f, 0.f};
    for (int r = 0; r < 128; ++r) {
        float w = in_proj_W[(128 + r) * 128 + t];
        u[r >> 5] = fmaf(qv[r], w, u[r >> 5]);
    }
#pragma unroll
    for (int h = 0; h < 4; ++h) g_U[t * 4 + h] = u[h] * inv;
    if (t < 4) {
        float cc = 0.f;
        for (int d = 0; d < 32; ++d) cc = fmaf(qv[t * 32 + d], in_proj_b[128 + t * 32 + d], cc);
        g_cvec[t] = cc * inv;
    }
}

// ---------------- graph boundaries ----------------
__global__ void k_gbounds(const int* __restrict__ batch) {
    int i = blockIdx.x * blockDim.x + threadIdx.x;
    if (i >= NN) return;
    int bi = batch[i];
    if (i == 0) {
        for (int g = 0; g <= bi; ++g) g_gstart[g] = 0;
    } else {
        int bp = batch[i - 1];
        for (int g = bp + 1; g <= bi; ++g) g_gstart[g] = i;
    }
    if (i == NN - 1) {
        for (int g = bi + 1; g <= BB; ++g) g_gstart[g] = NN;
    }
}

// ---------------- split softmax pool: partials ----------------
__global__ void __launch_bounds__(128) k_pool_part() {
    int b = blockIdx.x >> 3, p = blockIdx.x & 7;
    int s0 = g_gstart[b], s1 = g_gstart[b + 1];
    int len = s1 - s0;
    int q0 = s0 + (len * p) / SPLITS;
    int q1 = s0 + (len * (p + 1)) / SPLITS;
    int t = threadIdx.x;
    __shared__ float4 red[128];
    __shared__ float smax[4];

    float4 mx = make_float4(-1e30f, -1e30f, -1e30f, -1e30f);
    for (int n = q0 + t; n < q1; n += 128) {
        float4 f = reinterpret_cast<const float4*>(g_scores)[n];
        mx.x = fmaxf(mx.x, f.x); mx.y = fmaxf(mx.y, f.y);
        mx.z = fmaxf(mx.z, f.z); mx.w = fmaxf(mx.w, f.w);
    }
    red[t] = mx;
    __syncthreads();
    for (int s = 64; s > 0; s >>= 1) {
        if (t < s) {
            float4 a = red[t], c = red[t + s];
            a.x = fmaxf(a.x, c.x); a.y = fmaxf(a.y, c.y);
            a.z = fmaxf(a.z, c.z); a.w = fmaxf(a.w, c.w);
            red[t] = a;
        }
        __syncthreads();
    }
    if (t == 0) { smax[0] = red[0].x; smax[1] = red[0].y; smax[2] = red[0].z; smax[3] = red[0].w; }
    __syncthreads();

    int h = t >> 5;
    float m = smax[h];
    float pl = 0.f, den = 0.f;
#pragma unroll 2
    for (int n = q0; n < q1; ++n) {
        float e = expf(g_scores[n * 4 + h] - m);
        pl = fmaf(e, g_v[(size_t)n * HH + t], pl);
        den += e;
    }
    int slot = b * SPLITS + p;
    g_pp[slot * 128 + t] = pl;
    if ((t & 31) == 0) g_pd[slot * 4 + h] = den;
    if (t < 4) g_pm[slot * 4 + t] = smax[t];
}

// ---------------- tail (merges pool partials, then MLP heads) ----------------
__global__ void __launch_bounds__(128) k_tail(
    const float* __restrict__ out_W, const float* __restrict__ out_b,
    const float* __restrict__ symfeat,
    const float* __restrict__ sym_W, const float* __restrict__ sym_b,
    const float* __restrict__ symf_W, const float* __restrict__ symf_b,
    const float* __restrict__ symf_g, const float* __restrict__ symf_beta,
    const float* __restrict__ fus_W, const float* __restrict__ fus_b,
    const float* __restrict__ fus_g, const float* __restrict__ fus_beta,
    const float* __restrict__ hW1, const float* __restrict__ hb1,
    const float* __restrict__ hW2, const float* __restrict__ hb2,
    float* __restrict__ outp)
{
    int b = blockIdx.x;
    int t = threadIdx.x;
    __shared__ float M[4], Dn[4];
    __shared__ float p[128];
    __shared__ float cat[256];
    __shared__ float buf[128];
    __shared__ float hh[192];
    __shared__ float ws[4], wq[4];

    if (t < 4) {
        float mm = -1e30f;
        for (int pp = 0; pp < SPLITS; ++pp)
            mm = fmaxf(mm, g_pm[(b * SPLITS + pp) * 4 + t]);
        M[t] = mm;
        float d = 0.f;
        for (int pp = 0; pp < SPLITS; ++pp) {
            float m = g_pm[(b * SPLITS + pp) * 4 + t];
            d += g_pd[(b * SPLITS + pp) * 4 + t] * expf(m - mm);
        }
        Dn[t] = d;
    }
    __syncthreads();
    {
        int h = t >> 5;
        float acc = 0.f;
        for (int pp = 0; pp < SPLITS; ++pp) {
            float m = g_pm[(b * SPLITS + pp) * 4 + h];
            acc += g_pp[(b * SPLITS + pp) * 128 + t] * expf(m - M[h]);
        }
        p[t] = (Dn[h] > 0.f) ? acc / Dn[h] : 0.f;
    }
    __syncthreads();
    {
        float acc = out_b[t];
        for (int k = 0; k < 128; ++k) acc = fmaf(out_W[t * 128 + k], p[k], acc);
        cat[t] = acc;
    }
    {
        int f = t >> 5, o = t & 31;
        const float* sf = symfeat + b * 64 + f * 16;
        const float* w  = sym_W + (f * 32 + o) * 16;
        float s = sym_b[f * 32 + o];
#pragma unroll
        for (int i = 0; i < 16; ++i) s = fmaf(w[i], sf[i], s);
        buf[t] = fmaxf(s, 0.f);
    }
    __syncthreads();
    {
        float s2 = symf_b[t];
        for (int k = 0; k < 128; ++k) s2 = fmaf(symf_W[t * 128 + k], buf[k], s2);
        s2 = fmaxf(s2, 0.f);
        float ssum = warp_sum(s2);
        float sq = warp_sum(s2 * s2);
        int wd = t >> 5, ln = t & 31;
        if (ln == 0) { ws[wd] = ssum; wq[wd] = sq; }
        __syncthreads();
        float ts = ws[0] + ws[1] + ws[2] + ws[3];
        float tq = wq[0] + wq[1] + wq[2] + wq[3];
        __syncthreads();
        float mean = ts * (1.f / 128.f);
        float var  = tq * (1.f / 128.f) - mean * mean;
        cat[128 + t] = (s2 - mean) * rsqrtf(var + 1e-5f) * symf_g[t] + symf_beta[t];
    }
    __syncthreads();
    {
        float f = fus_b[t];
        for (int k = 0; k < 256; ++k) f = fmaf(fus_W[t * 256 + k], cat[k], f);
        f = fmaxf(f, 0.f);
        float ssum = warp_sum(f);
        float sq = warp_sum(f * f);
        int wd = t >> 5, ln = t & 31;
        if (ln == 0) { ws[wd] = ssum; wq[wd] = sq; }
        __syncthreads();
        float ts = ws[0] + ws[1] + ws[2] + ws[3];
        float tq = wq[0] + wq[1] + wq[2] + wq[3];
        __syncthreads();
        float mean = ts * (1.f / 128.f);
        float var  = tq * (1.f / 128.f) - mean * mean;
        p[t] = (f - mean) * rsqrtf(var + 1e-5f) * fus_g[t] + fus_beta[t];
    }
    __syncthreads();
    for (int idx = t; idx < 192; idx += 128) {
        int k = idx >> 6, o = idx & 63;
        const float* w = hW1 + (size_t)(k * 64 + o) * 128;
        float acc = hb1[k * 64 + o];
        for (int j = 0; j < 128; ++j) acc = fmaf(w[j], p[j], acc);
        hh[idx] = fmaxf(acc, 0.f);
    }
    __syncthreads();
    if (t < 3) {
        float z = hb2[t];
        for (int o = 0; o < 64; ++o) z = fmaf(hW2[t * 64 + o], hh[t * 64 + o], z);
        outp[t * BB + b] = 1.f / (1.f + expf(-z));
    }
}

// ---------------- host ----------------
extern "C" void kernel_launch(void* const* d_in, const int* in_sizes, int n_in,
                              void* d_out, int out_size) {
    const float* nf = nullptr;
    const float* symf = nullptr;
    const int* ei = nullptr;
    const int* batch = nullptr;
    const float* P[26];
    int pi = 0;
    for (int i = 0; i < n_in; ++i) {
        int sz = in_sizes[i];
        if (sz == NN * HH)       nf    = (const float*)d_in[i];
        else if (sz == BB * 64)  symf  = (const float*)d_in[i];
        else if (sz == 2 * EE)   ei    = (const int*)d_in[i];
        else if (sz == NN)       batch = (const int*)d_in[i];
        else if (pi < 26)        P[pi++] = (const float*)d_in[i];
    }
    const float *W_in = P[0], *b_in = P[1], *sage_Wl = P[2], *sage_bl = P[3],
                *sage_Wr = P[4], *ln_g = P[5], *ln_b = P[6], *query = P[7],
                *in_proj_W = P[8], *in_proj_b = P[9], *out_W = P[10], *out_b = P[11],
                *sym_W = P[12], *sym_b = P[13], *symf_W = P[14], *symf_b = P[15],
                *symf_g = P[16], *symf_beta = P[17], *fus_W = P[18], *fus_b = P[19],
                *fus_g = P[20], *fus_beta = P[21], *hW1 = P[22], *hb1 = P[23],
                *hW2 = P[24], *hb2 = P[25];

    uint32_t *pxh, *pxl, *pxh2, *pxl2, *pah, *pal;
    float* pv;
    cudaGetSymbolAddress((void**)&pxh,  g_xh);
    cudaGetSymbolAddress((void**)&pxl,  g_xl);
    cudaGetSymbolAddress((void**)&pxh2, g_xh2);
    cudaGetSymbolAddress((void**)&pxl2, g_xl2);
    cudaGetSymbolAddress((void**)&pah,  g_aggh);
    cudaGetSymbolAddress((void**)&pal,  g_aggl);
    cudaGetSymbolAddress((void**)&pv,   g_v);

    cudaFuncSetAttribute((const void*)k_mma<0>, cudaFuncAttributeMaxDynamicSharedMemorySize, SMEM_BYTES);
    cudaFuncSetAttribute((const void*)k_mma<1>, cudaFuncAttributeMaxDynamicSharedMemorySize, SMEM_BYTES);
    cudaFuncSetAttribute((const void*)k_mma<2>, cudaFuncAttributeMaxDynamicSharedMemorySize, SMEM_BYTES);

    // weight slots: 0=W_in, 1=Wl0, 2=Wr0, 3=Wl1, 4=Wr1, 5=Wl2, 6=Wr2, 7=Wv
    k_wconv<<<128, 256>>>(W_in,
                          sage_Wl + 0 * 16384, sage_Wr + 0 * 16384,
                          sage_Wl + 1 * 16384, sage_Wr + 1 * 16384,
                          sage_Wl + 2 * 16384, sage_Wr + 2 * 16384,
                          in_proj_W + 256 * 128);
    k_init<<<(NN + 255) / 256, 256>>>();
    k_deg<<<(EE + 255) / 256, 256>>>(ei);
    // index 3: input-proj GEMM (profiled sample slot)
    k_mma<0><<<TILES64, 512, SMEM_BYTES>>>(nf, nullptr, nullptr, nullptr, nullptr,
                                           0, b_in, nullptr, nullptr, pxh, pxl, nullptr, NN);
    k_scan<<<1, 1024>>>();
    k_fill<<<(EE + 255) / 256, 256>>>(ei);
    k_prep<<<1, 128>>>(in_proj_W, in_proj_b, query);
    k_gbounds<<<(NN + 255) / 256, 256>>>(batch);

    uint32_t *curh = pxh, *curl = pxl, *nxth = pxh2, *nxtl = pxl2;
    for (int l = 0; l < 3; ++l) {
        k_aggr<<<(NN * 32 + 255) / 256, 256>>>(curh, curl);
        k_mma<1><<<TILES64, 512, SMEM_BYTES>>>(nullptr, pah, pal, curh, curl,
                                               1 + 2 * l, sage_bl + l * 128,
                                               ln_g + l * 128, ln_b + l * 128,
                                               nxth, nxtl, nullptr, NN);
        uint32_t* th = curh; curh = nxth; nxth = th;
        uint32_t* tl = curl; curl = nxtl; nxtl = tl;
    }

    // v = x @ Wv^T + bv (fp32) + fused attention scores
    k_mma<2><<<TILES64, 512, SMEM_BYTES>>>(nullptr, curh, curl, nullptr, nullptr,
                                           7, in_proj_b + 256, nullptr, nullptr,
                                           nullptr, nullptr, pv, NN);

    k_pool_part<<<BB * SPLITS, 128>>>();
    k_tail<<<BB, 128>>>(out_W, out_b, symf, sym_W, sym_b,
                        symf_W, symf_b, symf_g, symf_beta,
                        fus_W, fus_b, fus_g, fus_beta,
                        hW1, hb1, hW2, hb2, (float*)d_out);
    (void)out_size;
}

// round 8
// speedup vs baseline: 1.5653x; 1.0372x over previous
#include <cuda_runtime.h>
#include <cuda_bf16.h>
#include <math.h>
#include <stdint.h>

#define NN 50000
#define EE 800000
#define BB 64
#define HH 128
#define TILES64 782   // ceil(50000/64)
#define SPLITS 8

// ---------------- scratch (device globals) ----------------
// x as interleaved bf16 hi/lo: per node 128 uint32 = [64 hi words | 64 lo words]
__device__ uint32_t g_xA [NN * 128];
__device__ uint32_t g_xB [NN * 128];
__device__ uint32_t g_agg[NN * 128];
__device__ float g_v   [NN * HH];
__device__ float g_scores[NN * 4];
__device__ float g_U[HH * 4];
__device__ float g_cvec[4];
__device__ float g_pm[BB * SPLITS * 4];
__device__ float g_pd[BB * SPLITS * 4];
__device__ float g_pp[BB * SPLITS * 128];
__device__ int   g_deg[NN];
__device__ int   g_off[NN + 1];
__device__ int   g_cur[NN];
__device__ int   g_col[EE];
__device__ int   g_gstart[BB + 1];
__device__ uint4 g_wbuf[8 * 4096];

// ---------------- helpers ----------------
__device__ __forceinline__ void hilo(float v, uint32_t& h, uint32_t& l) {
    __nv_bfloat16 hb = __float2bfloat16(v);
    __nv_bfloat16 lb = __float2bfloat16(v - __bfloat162float(hb));
    h = (uint32_t)__bfloat16_as_ushort(hb);
    l = (uint32_t)__bfloat16_as_ushort(lb);
}
__device__ __forceinline__ float2 bf2f(uint32_t u) {
    __nv_bfloat162 h;
    *reinterpret_cast<uint32_t*>(&h) = u;
    return __bfloat1622float2(h);
}
__device__ __forceinline__ uint32_t smem_u32(const void* p) {
    uint32_t a;
    asm("{ .reg .u64 t; cvta.to.shared.u64 t, %1; cvt.u32.u64 %0, t; }" : "=r"(a) : "l"(p));
    return a;
}
__device__ __forceinline__ float warp_sum(float v) {
#pragma unroll
    for (int o = 16; o > 0; o >>= 1) v += __shfl_xor_sync(0xffffffffu, v, o);
    return v;
}

#define HMMA(C, A0, A1, A2, A3, B0, B1) \
    asm volatile("mma.sync.aligned.m16n8k16.row.col.f32.bf16.bf16.f32 " \
                 "{%0,%1,%2,%3}, {%4,%5,%6,%7}, {%8,%9}, {%0,%1,%2,%3};" \
                 : "+f"((C)[0]), "+f"((C)[1]), "+f"((C)[2]), "+f"((C)[3]) \
                 : "r"(A0), "r"(A1), "r"(A2), "r"(A3), "r"(B0), "r"(B1))

#define LDSM4(D0, D1, D2, D3, A) \
    asm volatile("ldmatrix.sync.aligned.m8n8.x4.shared.b16 {%0,%1,%2,%3}, [%4];" \
                 : "=r"(D0), "=r"(D1), "=r"(D2), "=r"(D3) : "r"(A))

#define CP_ASYNC16(dst, src, sz) \
    asm volatile("cp.async.cg.shared.global [%0], [%1], 16, %2;" \
                 :: "r"(dst), "l"(src), "r"(sz) : "memory")
#define CP_COMMIT() asm volatile("cp.async.commit_group;" ::: "memory")
#define CP_WAIT0()  asm volatile("cp.async.wait_group 0;" ::: "memory")

// ---------------- SMEM layout (64-row tile) ----------------
#define OFF_AH  0
#define OFF_AL  16384
#define OFF_WH  32768
#define OFF_WL  65536
#define OFF_MISC 98304
#define OFF_BIAS (OFF_MISC)
#define OFF_G    (OFF_MISC + 512)
#define OFF_BETA (OFF_MISC + 1024)
#define OFF_MEAN (OFF_MISC + 1536)
#define OFF_RSTD (OFF_MISC + 1856)
#define OFF_U    (OFF_MISC + 2176)
#define OFF_CV   (OFF_MISC + 4224)
#define SMEM_BYTES (OFF_MISC + 4256)

__device__ __forceinline__ int CIDX(int row, int col) {
    return row * 128 + (((col >> 2) ^ (row & 7)) << 2) + (col & 3);
}
__device__ __forceinline__ int PIDX(int row, int cp) {
    return row * 64 + (((cp >> 2) ^ (row & 7)) << 2) + (cp & 3);
}

// ---------------- setup1: CSR init + weight pre-conversion ----------------
__global__ void k_setup1(const float* w0, const float* w1, const float* w2, const float* w3,
                         const float* w4, const float* w5, const float* w6, const float* w7) {
    int b = blockIdx.x;
    if (b < 196) {
        int i = b * 256 + threadIdx.x;
        if (i < NN) { g_deg[i] = 0; g_cur[i] = 0; }
        return;
    }
    int bb = b - 196;
    int m = bb >> 4;
    const float* W;
    switch (m) {
        case 0: W = w0; break; case 1: W = w1; break; case 2: W = w2; break;
        case 3: W = w3; break; case 4: W = w4; break; case 5: W = w5; break;
        case 6: W = w6; break; default: W = w7; break;
    }
    int i = (bb & 15) * 256 + threadIdx.x;
    int row = i >> 5, q = i & 31;
    float4 v = *reinterpret_cast<const float4*>(W + (size_t)row * 128 + q * 4);
    uint32_t h0, l0, h1, l1, h2, l2, h3, l3;
    hilo(v.x, h0, l0); hilo(v.y, h1, l1); hilo(v.z, h2, l2); hilo(v.w, h3, l3);
    uint2 uh, ul;
    uh.x = h0 | (h1 << 16); uh.y = h2 | (h3 << 16);
    ul.x = l0 | (l1 << 16); ul.y = l2 | (l3 << 16);
    char* base = (char*)g_wbuf + (size_t)m * 65536;
    int sw = row * 256 + q * 8;
    *reinterpret_cast<uint2*>(base + sw)         = uh;
    *reinterpret_cast<uint2*>(base + 32768 + sw) = ul;
}

// ---------------- deg count ----------------
__global__ void k_deg(const int* __restrict__ ei) {
    int e = blockIdx.x * blockDim.x + threadIdx.x;
    if (e < EE) atomicAdd(&g_deg[ei[EE + e]], 1);
}

// ---------------- setup2: scan + attention prep + graph bounds ----------------
__global__ void __launch_bounds__(1024) k_setup2(const float* __restrict__ in_proj_W,
                                                 const float* __restrict__ in_proj_b,
                                                 const float* __restrict__ query,
                                                 const int* __restrict__ batch) {
    int t = threadIdx.x;
    if (blockIdx.x == 0) {
        // exclusive scan of g_deg -> g_off
        __shared__ int sm[1024];
        const int chunk = (NN + 1023) / 1024;
        int base = t * chunk;
        int s = 0;
        for (int i = 0; i < chunk; ++i) {
            int idx = base + i;
            if (idx < NN) s += g_deg[idx];
        }
        sm[t] = s;
        __syncthreads();
        for (int d = 1; d < 1024; d <<= 1) {
            int add = (t >= d) ? sm[t - d] : 0;
            __syncthreads();
            sm[t] += add;
            __syncthreads();
        }
        int run = sm[t] - s;
        for (int i = 0; i < chunk; ++i) {
            int idx = base + i;
            if (idx < NN) { g_off[idx] = run; run += g_deg[idx]; }
        }
        if (t == 1023) g_off[NN] = sm[1023];
    } else if (blockIdx.x == 1) {
        __shared__ float qv[128];
        if (t < 128) {
            float s = in_proj_b[t];
            for (int k = 0; k < 128; ++k) s = fmaf(in_proj_W[t * 128 + k], query[k], s);
            qv[t] = s;
        }
        __syncthreads();
        if (t < 128) {
            const float inv = 1.0f / sqrtf(32.0f);
            float u[4] = {0.f, 0.f, 0.f, 0.f};
            for (int r = 0; r < 128; ++r) {
                float w = in_proj_W[(128 + r) * 128 + t];
                u[r >> 5] = fmaf(qv[r], w, u[r >> 5]);
            }
#pragma unroll
            for (int h = 0; h < 4; ++h) g_U[t * 4 + h] = u[h] * inv;
            if (t < 4) {
                float cc = 0.f;
                for (int d = 0; d < 32; ++d)
                    cc = fmaf(qv[t * 32 + d], in_proj_b[128 + t * 32 + d], cc);
                g_cvec[t] = cc * inv;
            }
        }
    } else {
        int i = (blockIdx.x - 2) * 1024 + t;
        if (i >= NN) return;
        int bi = batch[i];
        if (i == 0) {
            for (int g = 0; g <= bi; ++g) g_gstart[g] = 0;
        } else {
            int bp = batch[i - 1];
            for (int g = bp + 1; g <= bi; ++g) g_gstart[g] = i;
        }
        if (i == NN - 1) {
            for (int g = bi + 1; g <= BB; ++g) g_gstart[g] = NN;
        }
    }
}

// ---------------- CSR fill ----------------
__global__ void k_fill(const int* __restrict__ ei) {
    int e = blockIdx.x * blockDim.x + threadIdx.x;
    if (e < EE) {
        int s = ei[e];
        int d = ei[EE + e];
        int slot = atomicAdd(&g_cur[d], 1);
        g_col[g_off[d] + slot] = s;
    }
}

// ---------------- GEMM fills ----------------
// interleaved plane source: node block = 128 uint32 (hi 0..63, lo 64..127)
__device__ __forceinline__ void fill_copy_async(const uint32_t* __restrict__ g,
                                                uint32_t sb, int tile0, int nrows, int t) {
#pragma unroll
    for (int rep = 0; rep < 4; ++rep) {
        int i = t + rep * 512;          // 0..2047 = 64 rows x 32 chunks(16B)
        int row = i >> 5, c = i & 31;   // c<16 hi, else lo
        int grow = tile0 + row;
        int sz = (grow < nrows) ? 16 : 0;
        const char* src = (const char*)(g + (size_t)grow * 128) + c * 16;
        int cc = c & 15;
        int phys = row * 256 + ((cc ^ (row & 7)) << 4);
        uint32_t dst = sb + ((c < 16) ? OFF_AH : OFF_AL) + phys;
        CP_ASYNC16(dst, src, sz);
    }
}
__device__ __forceinline__ void fill_W_async(int slot, uint32_t sb, int t) {
    const char* src = (const char*)g_wbuf + (size_t)slot * 65536;
#pragma unroll
    for (int rep = 0; rep < 4; ++rep) {
        int i = t + rep * 512;
        int row = i >> 4, chunk = i & 15;
        int phys = row * 256 + ((chunk ^ (row & 7)) << 4);
        CP_ASYNC16(sb + OFF_WH + phys, src + i * 16, 16);
        CP_ASYNC16(sb + OFF_WL + phys, src + 32768 + i * 16, 16);
    }
}
__device__ __forceinline__ void fill_convert(const float* __restrict__ A, char* smem,
                                             int tile0, int nrows, int t) {
#pragma unroll
    for (int rep = 0; rep < 4; ++rep) {
        int i = t + rep * 512;
        int row = i >> 5, q = i & 31;
        int grow = tile0 + row;
        float4 v = make_float4(0.f, 0.f, 0.f, 0.f);
        if (grow < nrows) v = *reinterpret_cast<const float4*>(A + (size_t)grow * HH + q * 4);
        uint32_t h0, l0, h1, l1, h2, l2, h3, l3;
        hilo(v.x, h0, l0); hilo(v.y, h1, l1); hilo(v.z, h2, l2); hilo(v.w, h3, l3);
        uint2 uh, ul;
        uh.x = h0 | (h1 << 16); uh.y = h2 | (h3 << 16);
        ul.x = l0 | (l1 << 16); ul.y = l2 | (l3 << 16);
        int phys = row * 256 + (((q >> 1) ^ (row & 7)) << 4) + (q & 1) * 8;
        *reinterpret_cast<uint2*>(smem + OFF_AH + phys) = uh;
        *reinterpret_cast<uint2*>(smem + OFF_AL + phys) = ul;
    }
}

// ---------------- mainloop: 16x32 warp tile, 3-term split ----------------
__device__ __forceinline__ void mainloop(uint32_t sb, float c[4][4], int wm, int wn, int lane) {
    uint32_t rowA = wm * 16 + (lane & 15);
    uint32_t swA = rowA & 7;
    uint32_t aAddr = sb + OFF_AH + rowA * 256;
    uint32_t halfA = lane >> 4;
    uint32_t wrow = sb + OFF_WH + (uint32_t)(wn * 32 + lane) * 256;
    uint32_t swB = lane & 7;
#pragma unroll
    for (int ks = 0; ks < 8; ++ks) {
        uint32_t bh0[4], bh1[4], bl0[4], bl1[4];
        uint32_t cb0 = (uint32_t)(((2 * ks) ^ swB) << 4);
        uint32_t cb1 = (uint32_t)(((2 * ks + 1) ^ swB) << 4);
        LDSM4(bh0[0], bh0[1], bh0[2], bh0[3], wrow + cb0);
        LDSM4(bh1[0], bh1[1], bh1[2], bh1[3], wrow + cb1);
        LDSM4(bl0[0], bl0[1], bl0[2], bl0[3], wrow + 32768 + cb0);
        LDSM4(bl1[0], bl1[1], bl1[2], bl1[3], wrow + 32768 + cb1);
        uint32_t ca = (uint32_t)(((2 * ks + halfA) ^ swA) << 4);
        uint32_t ah0, ah1, ah2, ah3, al0, al1, al2, al3;
        LDSM4(ah0, ah1, ah2, ah3, aAddr + ca);
        LDSM4(al0, al1, al2, al3, aAddr + 16384 + ca);
#pragma unroll
        for (int nb = 0; nb < 4; ++nb) {
            HMMA(c[nb], ah0, ah1, ah2, ah3, bh0[nb], bh1[nb]);
            HMMA(c[nb], ah0, ah1, ah2, ah3, bl0[nb], bl1[nb]);
            HMMA(c[nb], al0, al1, al2, al3, bh0[nb], bh1[nb]);
        }
    }
}

// MODE: 0 = input proj, 1 = SAGE, 2 = V proj + scores
template <int MODE>
__global__ void __launch_bounds__(512, 2) k_mma(
    const float* __restrict__ Afp,
    const uint32_t* __restrict__ p1, const uint32_t* __restrict__ p2,
    int wslot, const float* __restrict__ bias,
    const float* __restrict__ lng, const float* __restrict__ lnb,
    uint32_t* __restrict__ out, float* __restrict__ outf, int nrows)
{
    extern __shared__ char smem[];
    uint32_t sb = smem_u32(smem);
    int t = threadIdx.x, wid = t >> 5, lane = t & 31;
    int tile0 = blockIdx.x * 64;
    int wm = wid & 3, wn = wid >> 2;

    fill_W_async(wslot, sb, t);
    if (MODE != 0) fill_copy_async(p1, sb, tile0, nrows, t);
    CP_COMMIT();

    if (t < 128) {
        ((float*)(smem + OFF_BIAS))[t] = bias[t];
        if (MODE == 1) {
            ((float*)(smem + OFF_G))[t]    = lng[t];
            ((float*)(smem + OFF_BETA))[t] = lnb[t];
        }
    }
    if (MODE == 2) {
        if (t >= 128 && t < 256) ((float4*)(smem + OFF_U))[t - 128] = ((const float4*)g_U)[t - 128];
        if (t == 256) *((float4*)(smem + OFF_CV)) = *((const float4*)g_cvec);
    }
    if (MODE == 0) fill_convert(Afp, smem, tile0, nrows, t);

    float c[4][4];
#pragma unroll
    for (int nb = 0; nb < 4; ++nb)
#pragma unroll
        for (int j = 0; j < 4; ++j) c[nb][j] = 0.f;

    CP_WAIT0();
    __syncthreads();

    mainloop(sb, c, wm, wn, lane);

    if (MODE == 1) {
        __syncthreads();
        fill_copy_async(p2, sb, tile0, nrows, t);
        fill_W_async(wslot + 1, sb, t);
        CP_COMMIT();
        CP_WAIT0();
        __syncthreads();
        mainloop(sb, c, wm, wn, lane);
    }
    __syncthreads();

    if (MODE == 2) {
        if (t < 64) {
            int grow = tile0 + t;
            if (grow < nrows) {
                const uint32_t* ph = (const uint32_t*)(smem + OFF_AH);
                const uint32_t* pl = (const uint32_t*)(smem + OFF_AL);
                const float4* U4 = (const float4*)(smem + OFF_U);
                const float* cv = (const float*)(smem + OFF_CV);
                float a0 = cv[0], a1 = cv[1], a2 = cv[2], a3 = cv[3];
#pragma unroll
                for (int kk = 0; kk < 64; ++kk) {
                    int idx = PIDX(t, kk);
                    float2 h = bf2f(ph[idx]);
                    float2 l = bf2f(pl[idx]);
                    float x0 = h.x + l.x, x1 = h.y + l.y;
                    float4 u0 = U4[2 * kk];
                    float4 u1 = U4[2 * kk + 1];
                    a0 += x0 * u0.x + x1 * u1.x;
                    a1 += x0 * u0.y + x1 * u1.y;
                    a2 += x0 * u0.z + x1 * u1.z;
                    a3 += x0 * u0.w + x1 * u1.w;
                }
                float4 r; r.x = a0; r.y = a1; r.z = a2; r.w = a3;
                reinterpret_cast<float4*>(g_scores)[grow] = r;
            }
        }
        __syncthreads();
    }

    float* Csm = (float*)(smem + OFF_WH);
    int g = lane >> 2, tt = lane & 3;
    {
        int r0 = wm * 16 + g;
        int r1 = r0 + 8;
#pragma unroll
        for (int nb = 0; nb < 4; ++nb) {
            int col = wn * 32 + nb * 8 + tt * 2;
            Csm[CIDX(r0, col)]     = c[nb][0];
            Csm[CIDX(r0, col + 1)] = c[nb][1];
            Csm[CIDX(r1, col)]     = c[nb][2];
            Csm[CIDX(r1, col + 1)] = c[nb][3];
        }
    }
    __syncthreads();

    const float* bs = (const float*)(smem + OFF_BIAS);
    if (MODE == 1) {
        if (t < 64) {
            float sum = 0.f, sq = 0.f;
#pragma unroll
            for (int j = 0; j < 128; ++j) {
                float x = Csm[CIDX(t, j)] + bs[j];
                sum += x; sq += x * x;
            }
            float mean = sum * (1.f / 128.f);
            float var  = sq * (1.f / 128.f) - mean * mean;
            ((float*)(smem + OFF_MEAN))[t] = mean;
            ((float*)(smem + OFF_RSTD))[t] = rsqrtf(var + 1e-5f);
        }
        __syncthreads();
    }

    if (MODE == 2) {
#pragma unroll
        for (int rep = 0; rep < 4; ++rep) {
            int i = t + rep * 512;
            int row = i >> 5, q = i & 31;
            int grow = tile0 + row;
            if (grow >= nrows) continue;
            int base = row * 128 + ((q ^ (row & 7)) << 2);
            float4 o;
            o.x = Csm[base + 0] + bs[q * 4 + 0];
            o.y = Csm[base + 1] + bs[q * 4 + 1];
            o.z = Csm[base + 2] + bs[q * 4 + 2];
            o.w = Csm[base + 3] + bs[q * 4 + 3];
            *reinterpret_cast<float4*>(outf + (size_t)grow * HH + q * 4) = o;
        }
    } else {
        const float* gg = (const float*)(smem + OFF_G);
        const float* bb = (const float*)(smem + OFF_BETA);
        const float* mn = (const float*)(smem + OFF_MEAN);
        const float* rs = (const float*)(smem + OFF_RSTD);
        const uint32_t* rxh = (const uint32_t*)(smem + OFF_AH);
        const uint32_t* rxl = (const uint32_t*)(smem + OFF_AL);
#pragma unroll
        for (int rep = 0; rep < 8; ++rep) {
            int i = t + rep * 512;
            int row = i >> 6, cp = i & 63;
            int grow = tile0 + row;
            if (grow >= nrows) continue;
            int c0 = cp * 2;
            float x0 = Csm[CIDX(row, c0)]     + bs[c0];
            float x1 = Csm[CIDX(row, c0 + 1)] + bs[c0 + 1];
            float o0, o1;
            if (MODE == 1) {
                float mean = mn[row], rstd = rs[row];
                int idx = PIDX(row, cp);
                float2 rh = bf2f(rxh[idx]);
                float2 rl = bf2f(rxl[idx]);
                o0 = fmaxf((x0 - mean) * rstd * gg[c0]     + bb[c0],     0.f) + (rh.x + rl.x);
                o1 = fmaxf((x1 - mean) * rstd * gg[c0 + 1] + bb[c0 + 1], 0.f) + (rh.y + rl.y);
            } else {
                o0 = fmaxf(x0, 0.f);
                o1 = fmaxf(x1, 0.f);
            }
            uint32_t h0, l0, h1, l1;
            hilo(o0, h0, l0); hilo(o1, h1, l1);
            out[(size_t)grow * 128 + cp]      = h0 | (h1 << 16);
            out[(size_t)grow * 128 + 64 + cp] = l0 | (l1 << 16);
        }
    }
}

// ---------------- neighbor mean aggregation (1 LDG.128 per lane per neighbor) ----------------
__global__ void __launch_bounds__(256) k_aggr(const uint32_t* __restrict__ x) {
    int warp = (blockIdx.x * blockDim.x + threadIdx.x) >> 5;
    int lane = threadIdx.x & 31;
    if (warp >= NN) return;
    int s0 = g_off[warp], s1 = g_off[warp + 1];
    float a[8] = {0.f, 0.f, 0.f, 0.f, 0.f, 0.f, 0.f, 0.f};
    const uint4* xp = reinterpret_cast<const uint4*>(x);
    for (int i = s0; i < s1; ++i) {
        int nb = __ldg(&g_col[i]);
        uint4 v = __ldg(xp + (size_t)nb * 32 + lane);
        float2 f0 = bf2f(v.x), f1 = bf2f(v.y), f2 = bf2f(v.z), f3 = bf2f(v.w);
        a[0] += f0.x; a[1] += f0.y; a[2] += f1.x; a[3] += f1.y;
        a[4] += f2.x; a[5] += f2.y; a[6] += f3.x; a[7] += f3.y;
    }
    float inv = 1.f / fmaxf((float)(s1 - s0), 1.f);
#pragma unroll
    for (int j = 0; j < 8; ++j) {
        a[j] += __shfl_xor_sync(0xffffffffu, a[j], 16);  // hi-part + lo-part of same cols
        a[j] *= inv;
    }
    uint32_t w[4];
#pragma unroll
    for (int p = 0; p < 4; ++p) {
        uint32_t h0, l0, h1, l1;
        hilo(a[2 * p], h0, l0);
        hilo(a[2 * p + 1], h1, l1);
        w[p] = (lane < 16) ? (h0 | (h1 << 16)) : (l0 | (l1 << 16));
    }
    uint4 o; o.x = w[0]; o.y = w[1]; o.z = w[2]; o.w = w[3];
    reinterpret_cast<uint4*>(g_agg)[(size_t)warp * 32 + lane] = o;
}

// ---------------- split softmax pool: partials ----------------
__global__ void __launch_bounds__(128) k_pool_part() {
    int b = blockIdx.x >> 3, p = blockIdx.x & 7;
    int s0 = g_gstart[b], s1 = g_gstart[b + 1];
    int len = s1 - s0;
    int q0 = s0 + (len * p) / SPLITS;
    int q1 = s0 + (len * (p + 1)) / SPLITS;
    int t = threadIdx.x;
    __shared__ float4 red[128];
    __shared__ float smax[4];

    float4 mx = make_float4(-1e30f, -1e30f, -1e30f, -1e30f);
    for (int n = q0 + t; n < q1; n += 128) {
        float4 f = reinterpret_cast<const float4*>(g_scores)[n];
        mx.x = fmaxf(mx.x, f.x); mx.y = fmaxf(mx.y, f.y);
        mx.z = fmaxf(mx.z, f.z); mx.w = fmaxf(mx.w, f.w);
    }
    red[t] = mx;
    __syncthreads();
    for (int s = 64; s > 0; s >>= 1) {
        if (t < s) {
            float4 a = red[t], c = red[t + s];
            a.x = fmaxf(a.x, c.x); a.y = fmaxf(a.y, c.y);
            a.z = fmaxf(a.z, c.z); a.w = fmaxf(a.w, c.w);
            red[t] = a;
        }
        __syncthreads();
    }
    if (t == 0) { smax[0] = red[0].x; smax[1] = red[0].y; smax[2] = red[0].z; smax[3] = red[0].w; }
    __syncthreads();

    int h = t >> 5;
    float m = smax[h];
    float pl = 0.f, den = 0.f;
#pragma unroll 2
    for (int n = q0; n < q1; ++n) {
        float e = expf(g_scores[n * 4 + h] - m);
        pl = fmaf(e, g_v[(size_t)n * HH + t], pl);
        den += e;
    }
    int slot = b * SPLITS + p;
    g_pp[slot * 128 + t] = pl;
    if ((t & 31) == 0) g_pd[slot * 4 + h] = den;
    if (t < 4) g_pm[slot * 4 + t] = smax[t];
}

// ---------------- tail (merges pool partials, then MLP heads) ----------------
__global__ void __launch_bounds__(128) k_tail(
    const float* __restrict__ out_W, const float* __restrict__ out_b,
    const float* __restrict__ symfeat,
    const float* __restrict__ sym_W, const float* __restrict__ sym_b,
    const float* __restrict__ symf_W, const float* __restrict__ symf_b,
    const float* __restrict__ symf_g, const float* __restrict__ symf_beta,
    const float* __restrict__ fus_W, const float* __restrict__ fus_b,
    const float* __restrict__ fus_g, const float* __restrict__ fus_beta,
    const float* __restrict__ hW1, const float* __restrict__ hb1,
    const float* __restrict__ hW2, const float* __restrict__ hb2,
    float* __restrict__ outp)
{
    int b = blockIdx.x;
    int t = threadIdx.x;
    __shared__ float M[4], Dn[4];
    __shared__ float p[128];
    __shared__ float cat[256];
    __shared__ float buf[128];
    __shared__ float hh[192];
    __shared__ float ws[4], wq[4];

    if (t < 4) {
        float mm = -1e30f;
        for (int pp = 0; pp < SPLITS; ++pp)
            mm = fmaxf(mm, g_pm[(b * SPLITS + pp) * 4 + t]);
        M[t] = mm;
        float d = 0.f;
        for (int pp = 0; pp < SPLITS; ++pp) {
            float m = g_pm[(b * SPLITS + pp) * 4 + t];
            d += g_pd[(b * SPLITS + pp) * 4 + t] * expf(m - mm);
        }
        Dn[t] = d;
    }
    __syncthreads();
    {
        int h = t >> 5;
        float acc = 0.f;
        for (int pp = 0; pp < SPLITS; ++pp) {
            float m = g_pm[(b * SPLITS + pp) * 4 + h];
            acc += g_pp[(b * SPLITS + pp) * 128 + t] * expf(m - M[h]);
        }
        p[t] = (Dn[h] > 0.f) ? acc / Dn[h] : 0.f;
    }
    __syncthreads();
    {
        float acc = out_b[t];
        for (int k = 0; k < 128; ++k) acc = fmaf(out_W[t * 128 + k], p[k], acc);
        cat[t] = acc;
    }
    {
        int f = t >> 5, o = t & 31;
        const float* sf = symfeat + b * 64 + f * 16;
        const float* w  = sym_W + (f * 32 + o) * 16;
        float s = sym_b[f * 32 + o];
#pragma unroll
        for (int i = 0; i < 16; ++i) s = fmaf(w[i], sf[i], s);
        buf[t] = fmaxf(s, 0.f);
    }
    __syncthreads();
    {
        float s2 = symf_b[t];
        for (int k = 0; k < 128; ++k) s2 = fmaf(symf_W[t * 128 + k], buf[k], s2);
        s2 = fmaxf(s2, 0.f);
        float ssum = warp_sum(s2);
        float sq = warp_sum(s2 * s2);
        int wd = t >> 5, ln = t & 31;
        if (ln == 0) { ws[wd] = ssum; wq[wd] = sq; }
        __syncthreads();
        float ts = ws[0] + ws[1] + ws[2] + ws[3];
        float tq = wq[0] + wq[1] + wq[2] + wq[3];
        __syncthreads();
        float mean = ts * (1.f / 128.f);
        float var  = tq * (1.f / 128.f) - mean * mean;
        cat[128 + t] = (s2 - mean) * rsqrtf(var + 1e-5f) * symf_g[t] + symf_beta[t];
    }
    __syncthreads();
    {
        float f = fus_b[t];
        for (int k = 0; k < 256; ++k) f = fmaf(fus_W[t * 256 + k], cat[k], f);
        f = fmaxf(f, 0.f);
        float ssum = warp_sum(f);
        float sq = warp_sum(f * f);
        int wd = t >> 5, ln = t & 31;
        if (ln == 0) { ws[wd] = ssum; wq[wd] = sq; }
        __syncthreads();
        float ts = ws[0] + ws[1] + ws[2] + ws[3];
        float tq = wq[0] + wq[1] + wq[2] + wq[3];
        __syncthreads();
        float mean = ts * (1.f / 128.f);
        float var  = tq * (1.f / 128.f) - mean * mean;
        p[t] = (f - mean) * rsqrtf(var + 1e-5f) * fus_g[t] + fus_beta[t];
    }
    __syncthreads();
    for (int idx = t; idx < 192; idx += 128) {
        int k = idx >> 6, o = idx & 63;
        const float* w = hW1 + (size_t)(k * 64 + o) * 128;
        float acc = hb1[k * 64 + o];
        for (int j = 0; j < 128; ++j) acc = fmaf(w[j], p[j], acc);
        hh[idx] = fmaxf(acc, 0.f);
    }
    __syncthreads();
    if (t < 3) {
        float z = hb2[t];
        for (int o = 0; o < 64; ++o) z = fmaf(hW2[t * 64 + o], hh[t * 64 + o], z);
        outp[t * BB + b] = 1.f / (1.f + expf(-z));
    }
}

// ---------------- host ----------------
extern "C" void kernel_launch(void* const* d_in, const int* in_sizes, int n_in,
                              void* d_out, int out_size) {
    const float* nf = nullptr;
    const float* symf = nullptr;
    const int* ei = nullptr;
    const int* batch = nullptr;
    const float* P[26];
    int pi = 0;
    for (int i = 0; i < n_in; ++i) {
        int sz = in_sizes[i];
        if (sz == NN * HH)       nf    = (const float*)d_in[i];
        else if (sz == BB * 64)  symf  = (const float*)d_in[i];
        else if (sz == 2 * EE)   ei    = (const int*)d_in[i];
        else if (sz == NN)       batch = (const int*)d_in[i];
        else if (pi < 26)        P[pi++] = (const float*)d_in[i];
    }
    const float *W_in = P[0], *b_in = P[1], *sage_Wl = P[2], *sage_bl = P[3],
                *sage_Wr = P[4], *ln_g = P[5], *ln_b = P[6], *query = P[7],
                *in_proj_W = P[8], *in_proj_b = P[9], *out_W = P[10], *out_b = P[11],
                *sym_W = P[12], *sym_b = P[13], *symf_W = P[14], *symf_b = P[15],
                *symf_g = P[16], *symf_beta = P[17], *fus_W = P[18], *fus_b = P[19],
                *fus_g = P[20], *fus_beta = P[21], *hW1 = P[22], *hb1 = P[23],
                *hW2 = P[24], *hb2 = P[25];

    uint32_t *pxA, *pxB, *pag;
    float* pv;
    cudaGetSymbolAddress((void**)&pxA, g_xA);
    cudaGetSymbolAddress((void**)&pxB, g_xB);
    cudaGetSymbolAddress((void**)&pag, g_agg);
    cudaGetSymbolAddress((void**)&pv,  g_v);

    cudaFuncSetAttribute((const void*)k_mma<0>, cudaFuncAttributeMaxDynamicSharedMemorySize, SMEM_BYTES);
    cudaFuncSetAttribute((const void*)k_mma<1>, cudaFuncAttributeMaxDynamicSharedMemorySize, SMEM_BYTES);
    cudaFuncSetAttribute((const void*)k_mma<2>, cudaFuncAttributeMaxDynamicSharedMemorySize, SMEM_BYTES);

    // weight slots: 0=W_in, 1=Wl0, 2=Wr0, 3=Wl1, 4=Wr1, 5=Wl2, 6=Wr2, 7=Wv
    k_setup1<<<324, 256>>>(W_in,
                           sage_Wl + 0 * 16384, sage_Wr + 0 * 16384,
                           sage_Wl + 1 * 16384, sage_Wr + 1 * 16384,
                           sage_Wl + 2 * 16384, sage_Wr + 2 * 16384,
                           in_proj_W + 256 * 128);
    k_deg<<<(EE + 255) / 256, 256>>>(ei);
    k_setup2<<<2 + (NN + 1023) / 1024, 1024>>>(in_proj_W, in_proj_b, query, batch);
    // index 3: input-proj GEMM (profiled sample slot)
    k_mma<0><<<TILES64, 512, SMEM_BYTES>>>(nf, nullptr, nullptr, 0, b_in,
                                           nullptr, nullptr, pxA, nullptr, NN);
    k_fill<<<(EE + 255) / 256, 256>>>(ei);

    uint32_t *cur = pxA, *nxt = pxB;
    for (int l = 0; l < 3; ++l) {
        k_aggr<<<(NN * 32 + 255) / 256, 256>>>(cur);
        k_mma<1><<<TILES64, 512, SMEM_BYTES>>>(nullptr, pag, cur, 1 + 2 * l,
                                               sage_bl + l * 128,
                                               ln_g + l * 128, ln_b + l * 128,
                                               nxt, nullptr, NN);
        uint32_t* tmp = cur; cur = nxt; nxt = tmp;
    }

    // v = x @ Wv^T + bv (fp32) + fused attention scores
    k_mma<2><<<TILES64, 512, SMEM_BYTES>>>(nullptr, cur, nullptr, 7, in_proj_b + 256,
                                           nullptr, nullptr, nullptr, pv, NN);

    k_pool_part<<<BB * SPLITS, 128>>>();
    k_tail<<<BB, 128>>>(out_W, out_b, symf, sym_W, sym_b,
                        symf_W, symf_b, symf_g, symf_beta,
                        fus_W, fus_b, fus_g, fus_beta,
                        hW1, hb1, hW2, hb2, (float*)d_out);
    (void)out_size;
}

// round 9
// speedup vs baseline: 1.8011x; 1.1506x over previous
#include <cuda_runtime.h>
#include <cuda_bf16.h>
#include <math.h>
#include <stdint.h>

#define NN 50000
#define EE 800000
#define BB 64
#define HH 128
#define TILES64 782   // ceil(50000/64)
#define SPLITS 8

// ---------------- scratch (device globals) ----------------
// x as interleaved bf16 hi/lo: per node 128 uint32 = [64 hi words | 64 lo words]
__device__ uint32_t g_xA [NN * 128];
__device__ uint32_t g_xB [NN * 128];
__device__ uint32_t g_agg[NN * 64];   // single bf16 plane (hi only)
__device__ float g_v   [NN * HH];
__device__ float g_scores[NN * 4];
__device__ float g_U[HH * 4];
__device__ float g_cvec[4];
__device__ float g_pm[BB * SPLITS * 4];
__device__ float g_pd[BB * SPLITS * 4];
__device__ float g_pp[BB * SPLITS * 128];
__device__ int   g_deg[NN];
__device__ int   g_off[NN + 1];
__device__ int   g_cur[NN];
__device__ int   g_col[EE];
__device__ int   g_gstart[BB + 1];
__device__ uint4 g_wbuf[8 * 4096];

// ---------------- helpers ----------------
__device__ __forceinline__ void hilo(float v, uint32_t& h, uint32_t& l) {
    __nv_bfloat16 hb = __float2bfloat16(v);
    __nv_bfloat16 lb = __float2bfloat16(v - __bfloat162float(hb));
    h = (uint32_t)__bfloat16_as_ushort(hb);
    l = (uint32_t)__bfloat16_as_ushort(lb);
}
__device__ __forceinline__ uint32_t bfh(float v) {
    return (uint32_t)__bfloat16_as_ushort(__float2bfloat16(v));
}
__device__ __forceinline__ float2 bf2f(uint32_t u) {
    __nv_bfloat162 h;
    *reinterpret_cast<uint32_t*>(&h) = u;
    return __bfloat1622float2(h);
}
__device__ __forceinline__ uint32_t smem_u32(const void* p) {
    uint32_t a;
    asm("{ .reg .u64 t; cvta.to.shared.u64 t, %1; cvt.u32.u64 %0, t; }" : "=r"(a) : "l"(p));
    return a;
}
__device__ __forceinline__ float warp_sum(float v) {
#pragma unroll
    for (int o = 16; o > 0; o >>= 1) v += __shfl_xor_sync(0xffffffffu, v, o);
    return v;
}

#define HMMA(C, A0, A1, A2, A3, B0, B1) \
    asm volatile("mma.sync.aligned.m16n8k16.row.col.f32.bf16.bf16.f32 " \
                 "{%0,%1,%2,%3}, {%4,%5,%6,%7}, {%8,%9}, {%0,%1,%2,%3};" \
                 : "+f"((C)[0]), "+f"((C)[1]), "+f"((C)[2]), "+f"((C)[3]) \
                 : "r"(A0), "r"(A1), "r"(A2), "r"(A3), "r"(B0), "r"(B1))

#define LDSM4(D0, D1, D2, D3, A) \
    asm volatile("ldmatrix.sync.aligned.m8n8.x4.shared.b16 {%0,%1,%2,%3}, [%4];" \
                 : "=r"(D0), "=r"(D1), "=r"(D2), "=r"(D3) : "r"(A))

#define CP_ASYNC16(dst, src, sz) \
    asm volatile("cp.async.cg.shared.global [%0], [%1], 16, %2;" \
                 :: "r"(dst), "l"(src), "r"(sz) : "memory")
#define CP_COMMIT() asm volatile("cp.async.commit_group;" ::: "memory")
#define CP_WAIT0()  asm volatile("cp.async.wait_group 0;" ::: "memory")

// ---------------- SMEM layout (64-row tile) ----------------
#define OFF_AH  0
#define OFF_AL  16384
#define OFF_WH  32768
#define OFF_WL  65536
#define OFF_MISC 98304
#define OFF_BIAS (OFF_MISC)
#define OFF_G    (OFF_MISC + 512)
#define OFF_BETA (OFF_MISC + 1024)
#define OFF_MEAN (OFF_MISC + 1536)
#define OFF_RSTD (OFF_MISC + 1856)
#define OFF_U    (OFF_MISC + 2176)
#define OFF_CV   (OFF_MISC + 4224)
#define SMEM_BYTES (OFF_MISC + 4256)

__device__ __forceinline__ int CIDX(int row, int col) {
    return row * 128 + (((col >> 2) ^ (row & 7)) << 2) + (col & 3);
}
__device__ __forceinline__ int PIDX(int row, int cp) {
    return row * 64 + (((cp >> 2) ^ (row & 7)) << 2) + (cp & 3);
}

// ---------------- setup1: CSR init + weight pre-conversion ----------------
__global__ void k_setup1(const float* w0, const float* w1, const float* w2, const float* w3,
                         const float* w4, const float* w5, const float* w6, const float* w7) {
    int b = blockIdx.x;
    if (b < 196) {
        int i = b * 256 + threadIdx.x;
        if (i < NN) { g_deg[i] = 0; g_cur[i] = 0; }
        return;
    }
    int bb = b - 196;
    int m = bb >> 4;
    const float* W;
    switch (m) {
        case 0: W = w0; break; case 1: W = w1; break; case 2: W = w2; break;
        case 3: W = w3; break; case 4: W = w4; break; case 5: W = w5; break;
        case 6: W = w6; break; default: W = w7; break;
    }
    int i = (bb & 15) * 256 + threadIdx.x;
    int row = i >> 5, q = i & 31;
    float4 v = *reinterpret_cast<const float4*>(W + (size_t)row * 128 + q * 4);
    uint32_t h0, l0, h1, l1, h2, l2, h3, l3;
    hilo(v.x, h0, l0); hilo(v.y, h1, l1); hilo(v.z, h2, l2); hilo(v.w, h3, l3);
    uint2 uh, ul;
    uh.x = h0 | (h1 << 16); uh.y = h2 | (h3 << 16);
    ul.x = l0 | (l1 << 16); ul.y = l2 | (l3 << 16);
    char* base = (char*)g_wbuf + (size_t)m * 65536;
    int sw = row * 256 + q * 8;
    *reinterpret_cast<uint2*>(base + sw)         = uh;
    *reinterpret_cast<uint2*>(base + 32768 + sw) = ul;
}

// ---------------- deg count ----------------
__global__ void k_deg(const int* __restrict__ ei) {
    int e = blockIdx.x * blockDim.x + threadIdx.x;
    if (e < EE) atomicAdd(&g_deg[ei[EE + e]], 1);
}

// ---------------- setup2: scan + attention prep + graph bounds ----------------
__global__ void __launch_bounds__(1024) k_setup2(const float* __restrict__ in_proj_W,
                                                 const float* __restrict__ in_proj_b,
                                                 const float* __restrict__ query,
                                                 const int* __restrict__ batch) {
    int t = threadIdx.x;
    if (blockIdx.x == 0) {
        __shared__ int sm[1024];
        const int chunk = (NN + 1023) / 1024;
        int base = t * chunk;
        int s = 0;
        for (int i = 0; i < chunk; ++i) {
            int idx = base + i;
            if (idx < NN) s += g_deg[idx];
        }
        sm[t] = s;
        __syncthreads();
        for (int d = 1; d < 1024; d <<= 1) {
            int add = (t >= d) ? sm[t - d] : 0;
            __syncthreads();
            sm[t] += add;
            __syncthreads();
        }
        int run = sm[t] - s;
        for (int i = 0; i < chunk; ++i) {
            int idx = base + i;
            if (idx < NN) { g_off[idx] = run; run += g_deg[idx]; }
        }
        if (t == 1023) g_off[NN] = sm[1023];
    } else if (blockIdx.x == 1) {
        __shared__ float qv[128];
        if (t < 128) {
            float s = in_proj_b[t];
            for (int k = 0; k < 128; ++k) s = fmaf(in_proj_W[t * 128 + k], query[k], s);
            qv[t] = s;
        }
        __syncthreads();
        if (t < 128) {
            const float inv = 1.0f / sqrtf(32.0f);
            float u[4] = {0.f, 0.f, 0.f, 0.f};
            for (int r = 0; r < 128; ++r) {
                float w = in_proj_W[(128 + r) * 128 + t];
                u[r >> 5] = fmaf(qv[r], w, u[r >> 5]);
            }
#pragma unroll
            for (int h = 0; h < 4; ++h) g_U[t * 4 + h] = u[h] * inv;
            if (t < 4) {
                float cc = 0.f;
                for (int d = 0; d < 32; ++d)
                    cc = fmaf(qv[t * 32 + d], in_proj_b[128 + t * 32 + d], cc);
                g_cvec[t] = cc * inv;
            }
        }
    } else {
        int i = (blockIdx.x - 2) * 1024 + t;
        if (i >= NN) return;
        int bi = batch[i];
        if (i == 0) {
            for (int g = 0; g <= bi; ++g) g_gstart[g] = 0;
        } else {
            int bp = batch[i - 1];
            for (int g = bp + 1; g <= bi; ++g) g_gstart[g] = i;
        }
        if (i == NN - 1) {
            for (int g = bi + 1; g <= BB; ++g) g_gstart[g] = NN;
        }
    }
}

// ---------------- CSR fill ----------------
__global__ void k_fill(const int* __restrict__ ei) {
    int e = blockIdx.x * blockDim.x + threadIdx.x;
    if (e < EE) {
        int s = ei[e];
        int d = ei[EE + e];
        int slot = atomicAdd(&g_cur[d], 1);
        g_col[g_off[d] + slot] = s;
    }
}

// ---------------- GEMM fills ----------------
// full hi/lo tile from interleaved planes (node block = 128 words: hi 0..63, lo 64..127)
__device__ __forceinline__ void fill_copy_async(const uint32_t* __restrict__ g,
                                                uint32_t sb, int tile0, int nrows, int t) {
#pragma unroll
    for (int rep = 0; rep < 4; ++rep) {
        int i = t + rep * 512;          // 0..2047 = 64 rows x 32 chunks(16B)
        int row = i >> 5, c = i & 31;
        int grow = tile0 + row;
        int sz = (grow < nrows) ? 16 : 0;
        const char* src = (const char*)(g + (size_t)grow * 128) + c * 16;
        int cc = c & 15;
        int phys = row * 256 + ((cc ^ (row & 7)) << 4);
        uint32_t dst = sb + ((c < 16) ? OFF_AH : OFF_AL) + phys;
        CP_ASYNC16(dst, src, sz);
    }
}
// single-plane A tile (16KB) from g_agg (node block = 64 words)
__device__ __forceinline__ void fill_copy_half(const uint32_t* __restrict__ g,
                                               uint32_t sb, int tile0, int nrows, int t) {
#pragma unroll
    for (int rep = 0; rep < 2; ++rep) {
        int i = t + rep * 512;          // 0..1023 = 64 rows x 16 chunks
        int row = i >> 4, chunk = i & 15;
        int grow = tile0 + row;
        int sz = (grow < nrows) ? 16 : 0;
        const char* src = (const char*)(g + (size_t)grow * 64) + chunk * 16;
        int phys = row * 256 + ((chunk ^ (row & 7)) << 4);
        CP_ASYNC16(sb + OFF_AH + phys, src, sz);
    }
}
__device__ __forceinline__ void fill_W_async(int slot, uint32_t sb, int t) {
    const char* src = (const char*)g_wbuf + (size_t)slot * 65536;
#pragma unroll
    for (int rep = 0; rep < 4; ++rep) {
        int i = t + rep * 512;
        int row = i >> 4, chunk = i & 15;
        int phys = row * 256 + ((chunk ^ (row & 7)) << 4);
        CP_ASYNC16(sb + OFF_WH + phys, src + i * 16, 16);
        CP_ASYNC16(sb + OFF_WL + phys, src + 32768 + i * 16, 16);
    }
}
__device__ __forceinline__ void fill_convert(const float* __restrict__ A, char* smem,
                                             int tile0, int nrows, int t) {
#pragma unroll
    for (int rep = 0; rep < 4; ++rep) {
        int i = t + rep * 512;
        int row = i >> 5, q = i & 31;
        int grow = tile0 + row;
        float4 v = make_float4(0.f, 0.f, 0.f, 0.f);
        if (grow < nrows) v = *reinterpret_cast<const float4*>(A + (size_t)grow * HH + q * 4);
        uint32_t h0, l0, h1, l1, h2, l2, h3, l3;
        hilo(v.x, h0, l0); hilo(v.y, h1, l1); hilo(v.z, h2, l2); hilo(v.w, h3, l3);
        uint2 uh, ul;
        uh.x = h0 | (h1 << 16); uh.y = h2 | (h3 << 16);
        ul.x = l0 | (l1 << 16); ul.y = l2 | (l3 << 16);
        int phys = row * 256 + (((q >> 1) ^ (row & 7)) << 4) + (q & 1) * 8;
        *reinterpret_cast<uint2*>(smem + OFF_AH + phys) = uh;
        *reinterpret_cast<uint2*>(smem + OFF_AL + phys) = ul;
    }
}

// ---------------- mainloops ----------------
// FULL: 3-term (A hi/lo), else 2-term (A single plane)
template <bool FULL>
__device__ __forceinline__ void mainloop(uint32_t sb, float c[4][4], int wm, int wn, int lane) {
    uint32_t rowA = wm * 16 + (lane & 15);
    uint32_t swA = rowA & 7;
    uint32_t aAddr = sb + OFF_AH + rowA * 256;
    uint32_t halfA = lane >> 4;
    uint32_t wrow = sb + OFF_WH + (uint32_t)(wn * 32 + lane) * 256;
    uint32_t swB = lane & 7;
#pragma unroll
    for (int ks = 0; ks < 8; ++ks) {
        uint32_t bh0[4], bh1[4], bl0[4], bl1[4];
        uint32_t cb0 = (uint32_t)(((2 * ks) ^ swB) << 4);
        uint32_t cb1 = (uint32_t)(((2 * ks + 1) ^ swB) << 4);
        LDSM4(bh0[0], bh0[1], bh0[2], bh0[3], wrow + cb0);
        LDSM4(bh1[0], bh1[1], bh1[2], bh1[3], wrow + cb1);
        LDSM4(bl0[0], bl0[1], bl0[2], bl0[3], wrow + 32768 + cb0);
        LDSM4(bl1[0], bl1[1], bl1[2], bl1[3], wrow + 32768 + cb1);
        uint32_t ca = (uint32_t)(((2 * ks + halfA) ^ swA) << 4);
        uint32_t ah0, ah1, ah2, ah3;
        LDSM4(ah0, ah1, ah2, ah3, aAddr + ca);
        if (FULL) {
            uint32_t al0, al1, al2, al3;
            LDSM4(al0, al1, al2, al3, aAddr + 16384 + ca);
#pragma unroll
            for (int nb = 0; nb < 4; ++nb) {
                HMMA(c[nb], ah0, ah1, ah2, ah3, bh0[nb], bh1[nb]);
                HMMA(c[nb], ah0, ah1, ah2, ah3, bl0[nb], bl1[nb]);
                HMMA(c[nb], al0, al1, al2, al3, bh0[nb], bh1[nb]);
            }
        } else {
#pragma unroll
            for (int nb = 0; nb < 4; ++nb) {
                HMMA(c[nb], ah0, ah1, ah2, ah3, bh0[nb], bh1[nb]);
                HMMA(c[nb], ah0, ah1, ah2, ah3, bl0[nb], bl1[nb]);
            }
        }
    }
}

// MODE: 0 = input proj, 1 = SAGE (pass1: agg single-plane 2-term; pass2: x full 3-term),
//       2 = V proj + scores
template <int MODE>
__global__ void __launch_bounds__(512, 2) k_mma(
    const float* __restrict__ Afp,
    const uint32_t* __restrict__ p1, const uint32_t* __restrict__ p2,
    int wslot, const float* __restrict__ bias,
    const float* __restrict__ lng, const float* __restrict__ lnb,
    uint32_t* __restrict__ out, float* __restrict__ outf, int nrows)
{
    extern __shared__ char smem[];
    uint32_t sb = smem_u32(smem);
    int t = threadIdx.x, wid = t >> 5, lane = t & 31;
    int tile0 = blockIdx.x * 64;
    int wm = wid & 3, wn = wid >> 2;

    fill_W_async(wslot, sb, t);
    if (MODE == 1) fill_copy_half(p1, sb, tile0, nrows, t);
    else if (MODE == 2) fill_copy_async(p1, sb, tile0, nrows, t);
    CP_COMMIT();

    if (t < 128) {
        ((float*)(smem + OFF_BIAS))[t] = bias[t];
        if (MODE == 1) {
            ((float*)(smem + OFF_G))[t]    = lng[t];
            ((float*)(smem + OFF_BETA))[t] = lnb[t];
        }
    }
    if (MODE == 2) {
        if (t >= 128 && t < 256) ((float4*)(smem + OFF_U))[t - 128] = ((const float4*)g_U)[t - 128];
        if (t == 256) *((float4*)(smem + OFF_CV)) = *((const float4*)g_cvec);
    }
    if (MODE == 0) fill_convert(Afp, smem, tile0, nrows, t);

    float c[4][4];
#pragma unroll
    for (int nb = 0; nb < 4; ++nb)
#pragma unroll
        for (int j = 0; j < 4; ++j) c[nb][j] = 0.f;

    CP_WAIT0();
    __syncthreads();

    if (MODE == 1) mainloop<false>(sb, c, wm, wn, lane);
    else           mainloop<true>(sb, c, wm, wn, lane);

    if (MODE == 1) {
        __syncthreads();
        fill_copy_async(p2, sb, tile0, nrows, t);
        fill_W_async(wslot + 1, sb, t);
        CP_COMMIT();
        CP_WAIT0();
        __syncthreads();
        mainloop<true>(sb, c, wm, wn, lane);
    }
    __syncthreads();

    if (MODE == 2) {
        if (t < 64) {
            int grow = tile0 + t;
            if (grow < nrows) {
                const uint32_t* ph = (const uint32_t*)(smem + OFF_AH);
                const uint32_t* pl = (const uint32_t*)(smem + OFF_AL);
                const float4* U4 = (const float4*)(smem + OFF_U);
                const float* cv = (const float*)(smem + OFF_CV);
                float a0 = cv[0], a1 = cv[1], a2 = cv[2], a3 = cv[3];
#pragma unroll
                for (int kk = 0; kk < 64; ++kk) {
                    int idx = PIDX(t, kk);
                    float2 h = bf2f(ph[idx]);
                    float2 l = bf2f(pl[idx]);
                    float x0 = h.x + l.x, x1 = h.y + l.y;
                    float4 u0 = U4[2 * kk];
                    float4 u1 = U4[2 * kk + 1];
                    a0 += x0 * u0.x + x1 * u1.x;
                    a1 += x0 * u0.y + x1 * u1.y;
                    a2 += x0 * u0.z + x1 * u1.z;
                    a3 += x0 * u0.w + x1 * u1.w;
                }
                float4 r; r.x = a0; r.y = a1; r.z = a2; r.w = a3;
                reinterpret_cast<float4*>(g_scores)[grow] = r;
            }
        }
        __syncthreads();
    }

    float* Csm = (float*)(smem + OFF_WH);
    int g = lane >> 2, tt = lane & 3;
    {
        int r0 = wm * 16 + g;
        int r1 = r0 + 8;
#pragma unroll
        for (int nb = 0; nb < 4; ++nb) {
            int col = wn * 32 + nb * 8 + tt * 2;
            Csm[CIDX(r0, col)]     = c[nb][0];
            Csm[CIDX(r0, col + 1)] = c[nb][1];
            Csm[CIDX(r1, col)]     = c[nb][2];
            Csm[CIDX(r1, col + 1)] = c[nb][3];
        }
    }
    __syncthreads();

    const float* bs = (const float*)(smem + OFF_BIAS);
    if (MODE == 1) {
        if (t < 64) {
            float sum = 0.f, sq = 0.f;
#pragma unroll
            for (int j = 0; j < 128; ++j) {
                float x = Csm[CIDX(t, j)] + bs[j];
                sum += x; sq += x * x;
            }
            float mean = sum * (1.f / 128.f);
            float var  = sq * (1.f / 128.f) - mean * mean;
            ((float*)(smem + OFF_MEAN))[t] = mean;
            ((float*)(smem + OFF_RSTD))[t] = rsqrtf(var + 1e-5f);
        }
        __syncthreads();
    }

    if (MODE == 2) {
#pragma unroll
        for (int rep = 0; rep < 4; ++rep) {
            int i = t + rep * 512;
            int row = i >> 5, q = i & 31;
            int grow = tile0 + row;
            if (grow >= nrows) continue;
            int base = row * 128 + ((q ^ (row & 7)) << 2);
            float4 o;
            o.x = Csm[base + 0] + bs[q * 4 + 0];
            o.y = Csm[base + 1] + bs[q * 4 + 1];
            o.z = Csm[base + 2] + bs[q * 4 + 2];
            o.w = Csm[base + 3] + bs[q * 4 + 3];
            *reinterpret_cast<float4*>(outf + (size_t)grow * HH + q * 4) = o;
        }
    } else {
        const float* gg = (const float*)(smem + OFF_G);
        const float* bb = (const float*)(smem + OFF_BETA);
        const float* mn = (const float*)(smem + OFF_MEAN);
        const float* rs = (const float*)(smem + OFF_RSTD);
        const uint32_t* rxh = (const uint32_t*)(smem + OFF_AH);
        const uint32_t* rxl = (const uint32_t*)(smem + OFF_AL);
#pragma unroll
        for (int rep = 0; rep < 8; ++rep) {
            int i = t + rep * 512;
            int row = i >> 6, cp = i & 63;
            int grow = tile0 + row;
            if (grow >= nrows) continue;
            int c0 = cp * 2;
            float x0 = Csm[CIDX(row, c0)]     + bs[c0];
            float x1 = Csm[CIDX(row, c0 + 1)] + bs[c0 + 1];
            float o0, o1;
            if (MODE == 1) {
                float mean = mn[row], rstd = rs[row];
                int idx = PIDX(row, cp);
                float2 rh = bf2f(rxh[idx]);
                float2 rl = bf2f(rxl[idx]);
                o0 = fmaxf((x0 - mean) * rstd * gg[c0]     + bb[c0],     0.f) + (rh.x + rl.x);
                o1 = fmaxf((x1 - mean) * rstd * gg[c0 + 1] + bb[c0 + 1], 0.f) + (rh.y + rl.y);
            } else {
                o0 = fmaxf(x0, 0.f);
                o1 = fmaxf(x1, 0.f);
            }
            uint32_t h0, l0, h1, l1;
            hilo(o0, h0, l0); hilo(o1, h1, l1);
            out[(size_t)grow * 128 + cp]      = h0 | (h1 << 16);
            out[(size_t)grow * 128 + 64 + cp] = l0 | (l1 << 16);
        }
    }
}

// ---------------- neighbor mean aggregation (hi plane only; 1 LDG.64 per lane per nb) ----------------
__global__ void __launch_bounds__(256) k_aggr(const uint32_t* __restrict__ x) {
    int warp = (blockIdx.x * blockDim.x + threadIdx.x) >> 5;
    int lane = threadIdx.x & 31;
    if (warp >= NN) return;
    int s0 = g_off[warp], s1 = g_off[warp + 1];
    float a0 = 0.f, a1 = 0.f, a2 = 0.f, a3 = 0.f;
    const uint2* xp = reinterpret_cast<const uint2*>(x);  // node block = 64 uint2; first 32 = hi plane
#pragma unroll 4
    for (int i = s0; i < s1; ++i) {
        int nb = __ldg(&g_col[i]);
        uint2 v = __ldg(xp + (size_t)nb * 64 + lane);     // hi-plane words 2*lane, 2*lane+1
        float2 f0 = bf2f(v.x), f1 = bf2f(v.y);
        a0 += f0.x; a1 += f0.y; a2 += f1.x; a3 += f1.y;
    }
    float inv = 1.f / fmaxf((float)(s1 - s0), 1.f);
    a0 *= inv; a1 *= inv; a2 *= inv; a3 *= inv;
    uint2 o;
    o.x = bfh(a0) | (bfh(a1) << 16);
    o.y = bfh(a2) | (bfh(a3) << 16);
    reinterpret_cast<uint2*>(g_agg)[(size_t)warp * 32 + lane] = o;
}

// ---------------- split softmax pool: partials ----------------
__global__ void __launch_bounds__(128) k_pool_part() {
    int b = blockIdx.x >> 3, p = blockIdx.x & 7;
    int s0 = g_gstart[b], s1 = g_gstart[b + 1];
    int len = s1 - s0;
    int q0 = s0 + (len * p) / SPLITS;
    int q1 = s0 + (len * (p + 1)) / SPLITS;
    int t = threadIdx.x;
    __shared__ float4 red[128];
    __shared__ float smax[4];

    float4 mx = make_float4(-1e30f, -1e30f, -1e30f, -1e30f);
    for (int n = q0 + t; n < q1; n += 128) {
        float4 f = reinterpret_cast<const float4*>(g_scores)[n];
        mx.x = fmaxf(mx.x, f.x); mx.y = fmaxf(mx.y, f.y);
        mx.z = fmaxf(mx.z, f.z); mx.w = fmaxf(mx.w, f.w);
    }
    red[t] = mx;
    __syncthreads();
    for (int s = 64; s > 0; s >>= 1) {
        if (t < s) {
            float4 a = red[t], c = red[t + s];
            a.x = fmaxf(a.x, c.x); a.y = fmaxf(a.y, c.y);
            a.z = fmaxf(a.z, c.z); a.w = fmaxf(a.w, c.w);
            red[t] = a;
        }
        __syncthreads();
    }
    if (t == 0) { smax[0] = red[0].x; smax[1] = red[0].y; smax[2] = red[0].z; smax[3] = red[0].w; }
    __syncthreads();

    int h = t >> 5;
    float m = smax[h];
    float pl = 0.f, den = 0.f;
#pragma unroll 2
    for (int n = q0; n < q1; ++n) {
        float e = expf(g_scores[n * 4 + h] - m);
        pl = fmaf(e, g_v[(size_t)n * HH + t], pl);
        den += e;
    }
    int slot = b * SPLITS + p;
    g_pp[slot * 128 + t] = pl;
    if ((t & 31) == 0) g_pd[slot * 4 + h] = den;
    if (t < 4) g_pm[slot * 4 + t] = smax[t];
}

// ---------------- tail (merges pool partials, then MLP heads) ----------------
__global__ void __launch_bounds__(128) k_tail(
    const float* __restrict__ out_W, const float* __restrict__ out_b,
    const float* __restrict__ symfeat,
    const float* __restrict__ sym_W, const float* __restrict__ sym_b,
    const float* __restrict__ symf_W, const float* __restrict__ symf_b,
    const float* __restrict__ symf_g, const float* __restrict__ symf_beta,
    const float* __restrict__ fus_W, const float* __restrict__ fus_b,
    const float* __restrict__ fus_g, const float* __restrict__ fus_beta,
    const float* __restrict__ hW1, const float* __restrict__ hb1,
    const float* __restrict__ hW2, const float* __restrict__ hb2,
    float* __restrict__ outp)
{
    int b = blockIdx.x;
    int t = threadIdx.x;
    __shared__ float M[4], Dn[4];
    __shared__ float p[128];
    __shared__ float cat[256];
    __shared__ float buf[128];
    __shared__ float hh[192];
    __shared__ float ws[4], wq[4];

    if (t < 4) {
        float mm = -1e30f;
        for (int pp = 0; pp < SPLITS; ++pp)
            mm = fmaxf(mm, g_pm[(b * SPLITS + pp) * 4 + t]);
        M[t] = mm;
        float d = 0.f;
        for (int pp = 0; pp < SPLITS; ++pp) {
            float m = g_pm[(b * SPLITS + pp) * 4 + t];
            d += g_pd[(b * SPLITS + pp) * 4 + t] * expf(m - mm);
        }
        Dn[t] = d;
    }
    __syncthreads();
    {
        int h = t >> 5;
        float acc = 0.f;
        for (int pp = 0; pp < SPLITS; ++pp) {
            float m = g_pm[(b * SPLITS + pp) * 4 + h];
            acc += g_pp[(b * SPLITS + pp) * 128 + t] * expf(m - M[h]);
        }
        p[t] = (Dn[h] > 0.f) ? acc / Dn[h] : 0.f;
    }
    __syncthreads();
    {
        float acc = out_b[t];
        for (int k = 0; k < 128; ++k) acc = fmaf(out_W[t * 128 + k], p[k], acc);
        cat[t] = acc;
    }
    {
        int f = t >> 5, o = t & 31;
        const float* sf = symfeat + b * 64 + f * 16;
        const float* w  = sym_W + (f * 32 + o) * 16;
        float s = sym_b[f * 32 + o];
#pragma unroll
        for (int i = 0; i < 16; ++i) s = fmaf(w[i], sf[i], s);
        buf[t] = fmaxf(s, 0.f);
    }
    __syncthreads();
    {
        float s2 = symf_b[t];
        for (int k = 0; k < 128; ++k) s2 = fmaf(symf_W[t * 128 + k], buf[k], s2);
        s2 = fmaxf(s2, 0.f);
        float ssum = warp_sum(s2);
        float sq = warp_sum(s2 * s2);
        int wd = t >> 5, ln = t & 31;
        if (ln == 0) { ws[wd] = ssum; wq[wd] = sq; }
        __syncthreads();
        float ts = ws[0] + ws[1] + ws[2] + ws[3];
        float tq = wq[0] + wq[1] + wq[2] + wq[3];
        __syncthreads();
        float mean = ts * (1.f / 128.f);
        float var  = tq * (1.f / 128.f) - mean * mean;
        cat[128 + t] = (s2 - mean) * rsqrtf(var + 1e-5f) * symf_g[t] + symf_beta[t];
    }
    __syncthreads();
    {
        float f = fus_b[t];
        for (int k = 0; k < 256; ++k) f = fmaf(fus_W[t * 256 + k], cat[k], f);
        f = fmaxf(f, 0.f);
        float ssum = warp_sum(f);
        float sq = warp_sum(f * f);
        int wd = t >> 5, ln = t & 31;
        if (ln == 0) { ws[wd] = ssum; wq[wd] = sq; }
        __syncthreads();
        float ts = ws[0] + ws[1] + ws[2] + ws[3];
        float tq = wq[0] + wq[1] + wq[2] + wq[3];
        __syncthreads();
        float mean = ts * (1.f / 128.f);
        float var  = tq * (1.f / 128.f) - mean * mean;
        p[t] = (f - mean) * rsqrtf(var + 1e-5f) * fus_g[t] + fus_beta[t];
    }
    __syncthreads();
    for (int idx = t; idx < 192; idx += 128) {
        int k = idx >> 6, o = idx & 63;
        const float* w = hW1 + (size_t)(k * 64 + o) * 128;
        float acc = hb1[k * 64 + o];
        for (int j = 0; j < 128; ++j) acc = fmaf(w[j], p[j], acc);
        hh[idx] = fmaxf(acc, 0.f);
    }
    __syncthreads();
    if (t < 3) {
        float z = hb2[t];
        for (int o = 0; o < 64; ++o) z = fmaf(hW2[t * 64 + o], hh[t * 64 + o], z);
        outp[t * BB + b] = 1.f / (1.f + expf(-z));
    }
}

// ---------------- host ----------------
extern "C" void kernel_launch(void* const* d_in, const int* in_sizes, int n_in,
                              void* d_out, int out_size) {
    const float* nf = nullptr;
    const float* symf = nullptr;
    const int* ei = nullptr;
    const int* batch = nullptr;
    const float* P[26];
    int pi = 0;
    for (int i = 0; i < n_in; ++i) {
        int sz = in_sizes[i];
        if (sz == NN * HH)       nf    = (const float*)d_in[i];
        else if (sz == BB * 64)  symf  = (const float*)d_in[i];
        else if (sz == 2 * EE)   ei    = (const int*)d_in[i];
        else if (sz == NN)       batch = (const int*)d_in[i];
        else if (pi < 26)        P[pi++] = (const float*)d_in[i];
    }
    const float *W_in = P[0], *b_in = P[1], *sage_Wl = P[2], *sage_bl = P[3],
                *sage_Wr = P[4], *ln_g = P[5], *ln_b = P[6], *query = P[7],
                *in_proj_W = P[8], *in_proj_b = P[9], *out_W = P[10], *out_b = P[11],
                *sym_W = P[12], *sym_b = P[13], *symf_W = P[14], *symf_b = P[15],
                *symf_g = P[16], *symf_beta = P[17], *fus_W = P[18], *fus_b = P[19],
                *fus_g = P[20], *fus_beta = P[21], *hW1 = P[22], *hb1 = P[23],
                *hW2 = P[24], *hb2 = P[25];

    uint32_t *pxA, *pxB, *pag;
    float* pv;
    cudaGetSymbolAddress((void**)&pxA, g_xA);
    cudaGetSymbolAddress((void**)&pxB, g_xB);
    cudaGetSymbolAddress((void**)&pag, g_agg);
    cudaGetSymbolAddress((void**)&pv,  g_v);

    cudaFuncSetAttribute((const void*)k_mma<0>, cudaFuncAttributeMaxDynamicSharedMemorySize, SMEM_BYTES);
    cudaFuncSetAttribute((const void*)k_mma<1>, cudaFuncAttributeMaxDynamicSharedMemorySize, SMEM_BYTES);
    cudaFuncSetAttribute((const void*)k_mma<2>, cudaFuncAttributeMaxDynamicSharedMemorySize, SMEM_BYTES);

    // weight slots: 0=W_in, 1=Wl0, 2=Wr0, 3=Wl1, 4=Wr1, 5=Wl2, 6=Wr2, 7=Wv
    k_setup1<<<324, 256>>>(W_in,
                           sage_Wl + 0 * 16384, sage_Wr + 0 * 16384,
                           sage_Wl + 1 * 16384, sage_Wr + 1 * 16384,
                           sage_Wl + 2 * 16384, sage_Wr + 2 * 16384,
                           in_proj_W + 256 * 128);
    k_deg<<<(EE + 255) / 256, 256>>>(ei);
    k_setup2<<<2 + (NN + 1023) / 1024, 1024>>>(in_proj_W, in_proj_b, query, batch);
    // index 3: input-proj GEMM (profiled sample slot)
    k_mma<0><<<TILES64, 512, SMEM_BYTES>>>(nf, nullptr, nullptr, 0, b_in,
                                           nullptr, nullptr, pxA, nullptr, NN);
    k_fill<<<(EE + 255) / 256, 256>>>(ei);

    uint32_t *cur = pxA, *nxt = pxB;
    for (int l = 0; l < 3; ++l) {
        k_aggr<<<(NN * 32 + 255) / 256, 256>>>(cur);
        k_mma<1><<<TILES64, 512, SMEM_BYTES>>>(nullptr, pag, cur, 1 + 2 * l,
                                               sage_bl + l * 128,
                                               ln_g + l * 128, ln_b + l * 128,
                                               nxt, nullptr, NN);
        uint32_t* tmp = cur; cur = nxt; nxt = tmp;
    }

    // v = x @ Wv^T + bv (fp32) + fused attention scores
    k_mma<2><<<TILES64, 512, SMEM_BYTES>>>(nullptr, cur, nullptr, 7, in_proj_b + 256,
                                           nullptr, nullptr, nullptr, pv, NN);

    k_pool_part<<<BB * SPLITS, 128>>>();
    k_tail<<<BB, 128>>>(out_W, out_b, symf, sym_W, sym_b,
                        symf_W, symf_b, symf_g, symf_beta,
                        fus_W, fus_b, fus_g, fus_beta,
                        hW1, hb1, hW2, hb2, (float*)d_out);
    (void)out_size;
}

// round 10
// speedup vs baseline: 1.9637x; 1.0903x over previous
#include <cuda_runtime.h>
#include <cuda_bf16.h>
#include <math.h>
#include <stdint.h>

#define NN 50000
#define EE 800000
#define BB 64
#define HH 128
#define TILES64 782   // ceil(50000/64)
#define SPLITS 8

// ---------------- scratch (device globals) ----------------
// x as interleaved bf16 hi/lo: per node 128 uint32 = [64 hi words | 64 lo words]
__device__ uint32_t g_xA [NN * 128];
__device__ uint32_t g_xB [NN * 128];
__device__ uint32_t g_agg[NN * 64];   // single bf16 plane (hi only)
__device__ float g_v   [NN * HH];
__device__ float g_scores[NN * 4];
__device__ float g_U[HH * 4];
__device__ float g_cvec[4];
__device__ float g_pm[BB * SPLITS * 4];
__device__ float g_pd[BB * SPLITS * 4];
__device__ float g_pp[BB * SPLITS * 128];
__device__ int   g_deg[NN];
__device__ int   g_off[NN + 1];
__device__ int   g_cur[NN];
__device__ int   g_col[EE];
__device__ int   g_gstart[BB + 1];
__device__ uint4 g_wbuf[8 * 4096];

// ---------------- helpers ----------------
__device__ __forceinline__ void hilo(float v, uint32_t& h, uint32_t& l) {
    __nv_bfloat16 hb = __float2bfloat16(v);
    __nv_bfloat16 lb = __float2bfloat16(v - __bfloat162float(hb));
    h = (uint32_t)__bfloat16_as_ushort(hb);
    l = (uint32_t)__bfloat16_as_ushort(lb);
}
__device__ __forceinline__ uint32_t bfh(float v) {
    return (uint32_t)__bfloat16_as_ushort(__float2bfloat16(v));
}
__device__ __forceinline__ float2 bf2f(uint32_t u) {
    __nv_bfloat162 h;
    *reinterpret_cast<uint32_t*>(&h) = u;
    return __bfloat1622float2(h);
}
__device__ __forceinline__ uint32_t smem_u32(const void* p) {
    uint32_t a;
    asm("{ .reg .u64 t; cvta.to.shared.u64 t, %1; cvt.u32.u64 %0, t; }" : "=r"(a) : "l"(p));
    return a;
}
__device__ __forceinline__ float warp_sum(float v) {
#pragma unroll
    for (int o = 16; o > 0; o >>= 1) v += __shfl_xor_sync(0xffffffffu, v, o);
    return v;
}

#define HMMA(C, A0, A1, A2, A3, B0, B1) \
    asm volatile("mma.sync.aligned.m16n8k16.row.col.f32.bf16.bf16.f32 " \
                 "{%0,%1,%2,%3}, {%4,%5,%6,%7}, {%8,%9}, {%0,%1,%2,%3};" \
                 : "+f"((C)[0]), "+f"((C)[1]), "+f"((C)[2]), "+f"((C)[3]) \
                 : "r"(A0), "r"(A1), "r"(A2), "r"(A3), "r"(B0), "r"(B1))

#define LDSM4(D0, D1, D2, D3, A) \
    asm volatile("ldmatrix.sync.aligned.m8n8.x4.shared.b16 {%0,%1,%2,%3}, [%4];" \
                 : "=r"(D0), "=r"(D1), "=r"(D2), "=r"(D3) : "r"(A))

#define CP_ASYNC16(dst, src, sz) \
    asm volatile("cp.async.cg.shared.global [%0], [%1], 16, %2;" \
                 :: "r"(dst), "l"(src), "r"(sz) : "memory")
#define CP_COMMIT() asm volatile("cp.async.commit_group;" ::: "memory")
#define CP_WAIT0()  asm volatile("cp.async.wait_group 0;" ::: "memory")

// ---------------- SMEM layout (64-row tile) ----------------
#define OFF_AH  0
#define OFF_AL  16384
#define OFF_WH  32768
#define OFF_WL  65536
#define OFF_MISC 98304
#define OFF_BIAS (OFF_MISC)
#define OFF_G    (OFF_MISC + 512)
#define OFF_BETA (OFF_MISC + 1024)
#define OFF_MEAN (OFF_MISC + 1536)
#define OFF_RSTD (OFF_MISC + 1856)
#define OFF_U    (OFF_MISC + 2176)
#define OFF_CV   (OFF_MISC + 4224)
#define SMEM_BYTES (OFF_MISC + 4256)

__device__ __forceinline__ int CIDX(int row, int col) {
    return row * 128 + (((col >> 2) ^ (row & 7)) << 2) + (col & 3);
}
__device__ __forceinline__ int PIDX(int row, int cp) {
    return row * 64 + (((cp >> 2) ^ (row & 7)) << 2) + (cp & 3);
}

// ---------------- setup1: CSR init + weight pre-conversion ----------------
__global__ void k_setup1(const float* w0, const float* w1, const float* w2, const float* w3,
                         const float* w4, const float* w5, const float* w6, const float* w7) {
    int b = blockIdx.x;
    if (b < 196) {
        int i = b * 256 + threadIdx.x;
        if (i < NN) { g_deg[i] = 0; g_cur[i] = 0; }
        return;
    }
    int bb = b - 196;
    int m = bb >> 4;
    const float* W;
    switch (m) {
        case 0: W = w0; break; case 1: W = w1; break; case 2: W = w2; break;
        case 3: W = w3; break; case 4: W = w4; break; case 5: W = w5; break;
        case 6: W = w6; break; default: W = w7; break;
    }
    int i = (bb & 15) * 256 + threadIdx.x;
    int row = i >> 5, q = i & 31;
    float4 v = *reinterpret_cast<const float4*>(W + (size_t)row * 128 + q * 4);
    uint32_t h0, l0, h1, l1, h2, l2, h3, l3;
    hilo(v.x, h0, l0); hilo(v.y, h1, l1); hilo(v.z, h2, l2); hilo(v.w, h3, l3);
    uint2 uh, ul;
    uh.x = h0 | (h1 << 16); uh.y = h2 | (h3 << 16);
    ul.x = l0 | (l1 << 16); ul.y = l2 | (l3 << 16);
    char* base = (char*)g_wbuf + (size_t)m * 65536;
    int sw = row * 256 + q * 8;
    *reinterpret_cast<uint2*>(base + sw)         = uh;
    *reinterpret_cast<uint2*>(base + 32768 + sw) = ul;
}

// ---------------- deg count ----------------
__global__ void k_deg(const int* __restrict__ ei) {
    int e = blockIdx.x * blockDim.x + threadIdx.x;
    if (e < EE) atomicAdd(&g_deg[ei[EE + e]], 1);
}

// ---------------- setup2: scan + attention prep + graph bounds ----------------
__global__ void __launch_bounds__(1024) k_setup2(const float* __restrict__ in_proj_W,
                                                 const float* __restrict__ in_proj_b,
                                                 const float* __restrict__ query,
                                                 const int* __restrict__ batch) {
    int t = threadIdx.x;
    if (blockIdx.x == 0) {
        __shared__ int sm[1024];
        const int chunk = (NN + 1023) / 1024;
        int base = t * chunk;
        int s = 0;
        for (int i = 0; i < chunk; ++i) {
            int idx = base + i;
            if (idx < NN) s += g_deg[idx];
        }
        sm[t] = s;
        __syncthreads();
        for (int d = 1; d < 1024; d <<= 1) {
            int add = (t >= d) ? sm[t - d] : 0;
            __syncthreads();
            sm[t] += add;
            __syncthreads();
        }
        int run = sm[t] - s;
        for (int i = 0; i < chunk; ++i) {
            int idx = base + i;
            if (idx < NN) { g_off[idx] = run; run += g_deg[idx]; }
        }
        if (t == 1023) g_off[NN] = sm[1023];
    } else if (blockIdx.x == 1) {
        __shared__ float qv[128];
        if (t < 128) {
            float s = in_proj_b[t];
            for (int k = 0; k < 128; ++k) s = fmaf(in_proj_W[t * 128 + k], query[k], s);
            qv[t] = s;
        }
        __syncthreads();
        if (t < 128) {
            const float inv = 1.0f / sqrtf(32.0f);
            float u[4] = {0.f, 0.f, 0.f, 0.f};
            for (int r = 0; r < 128; ++r) {
                float w = in_proj_W[(128 + r) * 128 + t];
                u[r >> 5] = fmaf(qv[r], w, u[r >> 5]);
            }
#pragma unroll
            for (int h = 0; h < 4; ++h) g_U[t * 4 + h] = u[h] * inv;
            if (t < 4) {
                float cc = 0.f;
                for (int d = 0; d < 32; ++d)
                    cc = fmaf(qv[t * 32 + d], in_proj_b[128 + t * 32 + d], cc);
                g_cvec[t] = cc * inv;
            }
        }
    } else {
        int i = (blockIdx.x - 2) * 1024 + t;
        if (i >= NN) return;
        int bi = batch[i];
        if (i == 0) {
            for (int g = 0; g <= bi; ++g) g_gstart[g] = 0;
        } else {
            int bp = batch[i - 1];
            for (int g = bp + 1; g <= bi; ++g) g_gstart[g] = i;
        }
        if (i == NN - 1) {
            for (int g = bi + 1; g <= BB; ++g) g_gstart[g] = NN;
        }
    }
}

// ---------------- CSR fill ----------------
__global__ void k_fill(const int* __restrict__ ei) {
    int e = blockIdx.x * blockDim.x + threadIdx.x;
    if (e < EE) {
        int s = ei[e];
        int d = ei[EE + e];
        int slot = atomicAdd(&g_cur[d], 1);
        g_col[g_off[d] + slot] = s;
    }
}

// ---------------- GEMM fills ----------------
// full hi/lo tile from interleaved planes (node block = 128 words: hi 0..63, lo 64..127)
__device__ __forceinline__ void fill_copy_async(const uint32_t* __restrict__ g,
                                                uint32_t sb, int tile0, int nrows, int t) {
#pragma unroll
    for (int rep = 0; rep < 4; ++rep) {
        int i = t + rep * 512;          // 0..2047 = 64 rows x 32 chunks(16B)
        int row = i >> 5, c = i & 31;
        int grow = tile0 + row;
        int sz = (grow < nrows) ? 16 : 0;
        const char* src = (const char*)(g + (size_t)grow * 128) + c * 16;
        int cc = c & 15;
        int phys = row * 256 + ((cc ^ (row & 7)) << 4);
        uint32_t dst = sb + ((c < 16) ? OFF_AH : OFF_AL) + phys;
        CP_ASYNC16(dst, src, sz);
    }
}
// single-plane A tile (16KB) from g_agg (node block = 64 words)
__device__ __forceinline__ void fill_copy_half(const uint32_t* __restrict__ g,
                                               uint32_t sb, int tile0, int nrows, int t) {
#pragma unroll
    for (int rep = 0; rep < 2; ++rep) {
        int i = t + rep * 512;          // 0..1023 = 64 rows x 16 chunks
        int row = i >> 4, chunk = i & 15;
        int grow = tile0 + row;
        int sz = (grow < nrows) ? 16 : 0;
        const char* src = (const char*)(g + (size_t)grow * 64) + chunk * 16;
        int phys = row * 256 + ((chunk ^ (row & 7)) << 4);
        CP_ASYNC16(sb + OFF_AH + phys, src, sz);
    }
}
// W hi+lo (64KB) for MODE0
__device__ __forceinline__ void fill_W_async(int slot, uint32_t sb, int t) {
    const char* src = (const char*)g_wbuf + (size_t)slot * 65536;
#pragma unroll
    for (int rep = 0; rep < 4; ++rep) {
        int i = t + rep * 512;
        int row = i >> 4, chunk = i & 15;
        int phys = row * 256 + ((chunk ^ (row & 7)) << 4);
        CP_ASYNC16(sb + OFF_WH + phys, src + i * 16, 16);
        CP_ASYNC16(sb + OFF_WL + phys, src + 32768 + i * 16, 16);
    }
}
// W hi-plane only (32KB) into dstoff
__device__ __forceinline__ void fill_Whi_async(int slot, uint32_t sb, uint32_t dstoff, int t) {
    const char* src = (const char*)g_wbuf + (size_t)slot * 65536;  // hi plane = first 32KB
#pragma unroll
    for (int rep = 0; rep < 4; ++rep) {
        int i = t + rep * 512;          // 0..2047
        int row = i >> 4, chunk = i & 15;
        int phys = row * 256 + ((chunk ^ (row & 7)) << 4);
        CP_ASYNC16(sb + dstoff + phys, src + i * 16, 16);
    }
}
__device__ __forceinline__ void fill_convert(const float* __restrict__ A, char* smem,
                                             int tile0, int nrows, int t) {
#pragma unroll
    for (int rep = 0; rep < 4; ++rep) {
        int i = t + rep * 512;
        int row = i >> 5, q = i & 31;
        int grow = tile0 + row;
        float4 v = make_float4(0.f, 0.f, 0.f, 0.f);
        if (grow < nrows) v = *reinterpret_cast<const float4*>(A + (size_t)grow * HH + q * 4);
        uint32_t h0, l0, h1, l1, h2, l2, h3, l3;
        hilo(v.x, h0, l0); hilo(v.y, h1, l1); hilo(v.z, h2, l2); hilo(v.w, h3, l3);
        uint2 uh, ul;
        uh.x = h0 | (h1 << 16); uh.y = h2 | (h3 << 16);
        ul.x = l0 | (l1 << 16); ul.y = l2 | (l3 << 16);
        int phys = row * 256 + (((q >> 1) ^ (row & 7)) << 4) + (q & 1) * 8;
        *reinterpret_cast<uint2*>(smem + OFF_AH + phys) = uh;
        *reinterpret_cast<uint2*>(smem + OFF_AL + phys) = ul;
    }
}

// ---------------- mainloop ----------------
// TERMS: 1 = Ah*Bh | 2 = Ah*Bh + Al*Bh | 3 = Ah*Bh + Ah*Bl + Al*Bh (B lo at boff+32768)
template <int TERMS>
__device__ __forceinline__ void mainloop(uint32_t sb, uint32_t aoff, uint32_t boff,
                                         float c[4][4], int wm, int wn, int lane) {
    uint32_t rowA = wm * 16 + (lane & 15);
    uint32_t swA = rowA & 7;
    uint32_t aAddr = sb + aoff + rowA * 256;
    uint32_t halfA = lane >> 4;
    uint32_t wrow = sb + boff + (uint32_t)(wn * 32 + lane) * 256;
    uint32_t swB = lane & 7;
#pragma unroll
    for (int ks = 0; ks < 8; ++ks) {
        uint32_t bh0[4], bh1[4];
        uint32_t cb0 = (uint32_t)(((2 * ks) ^ swB) << 4);
        uint32_t cb1 = (uint32_t)(((2 * ks + 1) ^ swB) << 4);
        LDSM4(bh0[0], bh0[1], bh0[2], bh0[3], wrow + cb0);
        LDSM4(bh1[0], bh1[1], bh1[2], bh1[3], wrow + cb1);
        uint32_t bl0[4], bl1[4];
        if (TERMS == 3) {
            LDSM4(bl0[0], bl0[1], bl0[2], bl0[3], wrow + 32768 + cb0);
            LDSM4(bl1[0], bl1[1], bl1[2], bl1[3], wrow + 32768 + cb1);
        }
        uint32_t ca = (uint32_t)(((2 * ks + halfA) ^ swA) << 4);
        uint32_t ah0, ah1, ah2, ah3;
        LDSM4(ah0, ah1, ah2, ah3, aAddr + ca);
        uint32_t al0, al1, al2, al3;
        if (TERMS >= 2) LDSM4(al0, al1, al2, al3, aAddr + 16384 + ca);
#pragma unroll
        for (int nb = 0; nb < 4; ++nb) {
            HMMA(c[nb], ah0, ah1, ah2, ah3, bh0[nb], bh1[nb]);
            if (TERMS == 3) HMMA(c[nb], ah0, ah1, ah2, ah3, bl0[nb], bl1[nb]);
            if (TERMS >= 2) HMMA(c[nb], al0, al1, al2, al3, bh0[nb], bh1[nb]);
        }
    }
}

// MODE: 0 = input proj (3-term, W hi/lo)
//       1 = SAGE (Wl_hi+Wr_hi upfront; pass1 agg 1-term; pass2 x 2-term; LN+relu+residual)
//       2 = V proj + scores (2-term, Wv hi only)
template <int MODE>
__global__ void __launch_bounds__(512, 2) k_mma(
    const float* __restrict__ Afp,
    const uint32_t* __restrict__ p1, const uint32_t* __restrict__ p2,
    int wslot, const float* __restrict__ bias,
    const float* __restrict__ lng, const float* __restrict__ lnb,
    uint32_t* __restrict__ out, float* __restrict__ outf, int nrows)
{
    extern __shared__ char smem[];
    uint32_t sb = smem_u32(smem);
    int t = threadIdx.x, wid = t >> 5, lane = t & 31;
    int tile0 = blockIdx.x * 64;
    int wm = wid & 3, wn = wid >> 2;

    if (MODE == 0) {
        fill_W_async(wslot, sb, t);                 // W_in hi+lo
    } else if (MODE == 1) {
        fill_Whi_async(wslot, sb, OFF_WH, t);       // Wl hi
        fill_Whi_async(wslot + 1, sb, OFF_WL, t);   // Wr hi
        fill_copy_half(p1, sb, tile0, nrows, t);    // agg hi
    } else {
        fill_Whi_async(wslot, sb, OFF_WH, t);       // Wv hi
        fill_copy_async(p1, sb, tile0, nrows, t);   // x hi+lo
    }
    CP_COMMIT();

    if (t < 128) {
        ((float*)(smem + OFF_BIAS))[t] = bias[t];
        if (MODE == 1) {
            ((float*)(smem + OFF_G))[t]    = lng[t];
            ((float*)(smem + OFF_BETA))[t] = lnb[t];
        }
    }
    if (MODE == 2) {
        if (t >= 128 && t < 256) ((float4*)(smem + OFF_U))[t - 128] = ((const float4*)g_U)[t - 128];
        if (t == 256) *((float4*)(smem + OFF_CV)) = *((const float4*)g_cvec);
    }
    if (MODE == 0) fill_convert(Afp, smem, tile0, nrows, t);

    float c[4][4];
#pragma unroll
    for (int nb = 0; nb < 4; ++nb)
#pragma unroll
        for (int j = 0; j < 4; ++j) c[nb][j] = 0.f;

    CP_WAIT0();
    __syncthreads();

    if (MODE == 0)      mainloop<3>(sb, OFF_AH, OFF_WH, c, wm, wn, lane);
    else if (MODE == 1) mainloop<1>(sb, OFF_AH, OFF_WH, c, wm, wn, lane);
    else                mainloop<2>(sb, OFF_AH, OFF_WH, c, wm, wn, lane);

    if (MODE == 1) {
        __syncthreads();
        fill_copy_async(p2, sb, tile0, nrows, t);   // x hi+lo -> A planes
        CP_COMMIT();
        CP_WAIT0();
        __syncthreads();
        mainloop<2>(sb, OFF_AH, OFF_WL, c, wm, wn, lane);  // x @ Wr_hi
    }
    __syncthreads();

    if (MODE == 2) {
        if (t < 64) {
            int grow = tile0 + t;
            if (grow < nrows) {
                const uint32_t* ph = (const uint32_t*)(smem + OFF_AH);
                const uint32_t* pl = (const uint32_t*)(smem + OFF_AL);
                const float4* U4 = (const float4*)(smem + OFF_U);
                const float* cv = (const float*)(smem + OFF_CV);
                float a0 = cv[0], a1 = cv[1], a2 = cv[2], a3 = cv[3];
#pragma unroll
                for (int kk = 0; kk < 64; ++kk) {
                    int idx = PIDX(t, kk);
                    float2 h = bf2f(ph[idx]);
                    float2 l = bf2f(pl[idx]);
                    float x0 = h.x + l.x, x1 = h.y + l.y;
                    float4 u0 = U4[2 * kk];
                    float4 u1 = U4[2 * kk + 1];
                    a0 += x0 * u0.x + x1 * u1.x;
                    a1 += x0 * u0.y + x1 * u1.y;
                    a2 += x0 * u0.z + x1 * u1.z;
                    a3 += x0 * u0.w + x1 * u1.w;
                }
                float4 r; r.x = a0; r.y = a1; r.z = a2; r.w = a3;
                reinterpret_cast<float4*>(g_scores)[grow] = r;
            }
        }
        __syncthreads();
    }

    // spill C over W-hi region (dead after mainloops)
    float* Csm = (float*)(smem + OFF_WH);
    int g = lane >> 2, tt = lane & 3;
    {
        int r0 = wm * 16 + g;
        int r1 = r0 + 8;
#pragma unroll
        for (int nb = 0; nb < 4; ++nb) {
            int col = wn * 32 + nb * 8 + tt * 2;
            Csm[CIDX(r0, col)]     = c[nb][0];
            Csm[CIDX(r0, col + 1)] = c[nb][1];
            Csm[CIDX(r1, col)]     = c[nb][2];
            Csm[CIDX(r1, col + 1)] = c[nb][3];
        }
    }
    __syncthreads();

    const float* bs = (const float*)(smem + OFF_BIAS);
    if (MODE == 1) {
        if (t < 64) {
            float sum = 0.f, sq = 0.f;
#pragma unroll
            for (int j = 0; j < 128; ++j) {
                float x = Csm[CIDX(t, j)] + bs[j];
                sum += x; sq += x * x;
            }
            float mean = sum * (1.f / 128.f);
            float var  = sq * (1.f / 128.f) - mean * mean;
            ((float*)(smem + OFF_MEAN))[t] = mean;
            ((float*)(smem + OFF_RSTD))[t] = rsqrtf(var + 1e-5f);
        }
        __syncthreads();
    }

    if (MODE == 2) {
#pragma unroll
        for (int rep = 0; rep < 4; ++rep) {
            int i = t + rep * 512;
            int row = i >> 5, q = i & 31;
            int grow = tile0 + row;
            if (grow >= nrows) continue;
            int base = row * 128 + ((q ^ (row & 7)) << 2);
            float4 o;
            o.x = Csm[base + 0] + bs[q * 4 + 0];
            o.y = Csm[base + 1] + bs[q * 4 + 1];
            o.z = Csm[base + 2] + bs[q * 4 + 2];
            o.w = Csm[base + 3] + bs[q * 4 + 3];
            *reinterpret_cast<float4*>(outf + (size_t)grow * HH + q * 4) = o;
        }
    } else {
        const float* gg = (const float*)(smem + OFF_G);
        const float* bb = (const float*)(smem + OFF_BETA);
        const float* mn = (const float*)(smem + OFF_MEAN);
        const float* rs = (const float*)(smem + OFF_RSTD);
        const uint32_t* rxh = (const uint32_t*)(smem + OFF_AH);
        const uint32_t* rxl = (const uint32_t*)(smem + OFF_AL);
#pragma unroll
        for (int rep = 0; rep < 8; ++rep) {
            int i = t + rep * 512;
            int row = i >> 6, cp = i & 63;
            int grow = tile0 + row;
            if (grow >= nrows) continue;
            int c0 = cp * 2;
            float x0 = Csm[CIDX(row, c0)]     + bs[c0];
            float x1 = Csm[CIDX(row, c0 + 1)] + bs[c0 + 1];
            float o0, o1;
            if (MODE == 1) {
                float mean = mn[row], rstd = rs[row];
                int idx = PIDX(row, cp);
                float2 rh = bf2f(rxh[idx]);
                float2 rl = bf2f(rxl[idx]);
                o0 = fmaxf((x0 - mean) * rstd * gg[c0]     + bb[c0],     0.f) + (rh.x + rl.x);
                o1 = fmaxf((x1 - mean) * rstd * gg[c0 + 1] + bb[c0 + 1], 0.f) + (rh.y + rl.y);
            } else {
                o0 = fmaxf(x0, 0.f);
                o1 = fmaxf(x1, 0.f);
            }
            uint32_t h0, l0, h1, l1;
            hilo(o0, h0, l0); hilo(o1, h1, l1);
            out[(size_t)grow * 128 + cp]      = h0 | (h1 << 16);
            out[(size_t)grow * 128 + 64 + cp] = l0 | (l1 << 16);
        }
    }
}

// ---------------- neighbor mean aggregation (hi plane only; 1 LDG.64 per lane per nb) ----------------
__global__ void __launch_bounds__(256) k_aggr(const uint32_t* __restrict__ x) {
    int warp = (blockIdx.x * blockDim.x + threadIdx.x) >> 5;
    int lane = threadIdx.x & 31;
    if (warp >= NN) return;
    int s0 = g_off[warp], s1 = g_off[warp + 1];
    float a0 = 0.f, a1 = 0.f, a2 = 0.f, a3 = 0.f;
    const uint2* xp = reinterpret_cast<const uint2*>(x);  // node block = 64 uint2; first 32 = hi plane
#pragma unroll 4
    for (int i = s0; i < s1; ++i) {
        int nb = __ldg(&g_col[i]);
        uint2 v = __ldg(xp + (size_t)nb * 64 + lane);
        float2 f0 = bf2f(v.x), f1 = bf2f(v.y);
        a0 += f0.x; a1 += f0.y; a2 += f1.x; a3 += f1.y;
    }
    float inv = 1.f / fmaxf((float)(s1 - s0), 1.f);
    a0 *= inv; a1 *= inv; a2 *= inv; a3 *= inv;
    uint2 o;
    o.x = bfh(a0) | (bfh(a1) << 16);
    o.y = bfh(a2) | (bfh(a3) << 16);
    reinterpret_cast<uint2*>(g_agg)[(size_t)warp * 32 + lane] = o;
}

// ---------------- split softmax pool: partials ----------------
__global__ void __launch_bounds__(128) k_pool_part() {
    int b = blockIdx.x >> 3, p = blockIdx.x & 7;
    int s0 = g_gstart[b], s1 = g_gstart[b + 1];
    int len = s1 - s0;
    int q0 = s0 + (len * p) / SPLITS;
    int q1 = s0 + (len * (p + 1)) / SPLITS;
    int t = threadIdx.x;
    __shared__ float4 red[128];
    __shared__ float smax[4];

    float4 mx = make_float4(-1e30f, -1e30f, -1e30f, -1e30f);
    for (int n = q0 + t; n < q1; n += 128) {
        float4 f = reinterpret_cast<const float4*>(g_scores)[n];
        mx.x = fmaxf(mx.x, f.x); mx.y = fmaxf(mx.y, f.y);
        mx.z = fmaxf(mx.z, f.z); mx.w = fmaxf(mx.w, f.w);
    }
    red[t] = mx;
    __syncthreads();
    for (int s = 64; s > 0; s >>= 1) {
        if (t < s) {
            float4 a = red[t], c = red[t + s];
            a.x = fmaxf(a.x, c.x); a.y = fmaxf(a.y, c.y);
            a.z = fmaxf(a.z, c.z); a.w = fmaxf(a.w, c.w);
            red[t] = a;
        }
        __syncthreads();
    }
    if (t == 0) { smax[0] = red[0].x; smax[1] = red[0].y; smax[2] = red[0].z; smax[3] = red[0].w; }
    __syncthreads();

    int h = t >> 5;
    float m = smax[h];
    float pl = 0.f, den = 0.f;
#pragma unroll 2
    for (int n = q0; n < q1; ++n) {
        float e = expf(g_scores[n * 4 + h] - m);
        pl = fmaf(e, g_v[(size_t)n * HH + t], pl);
        den += e;
    }
    int slot = b * SPLITS + p;
    g_pp[slot * 128 + t] = pl;
    if ((t & 31) == 0) g_pd[slot * 4 + h] = den;
    if (t < 4) g_pm[slot * 4 + t] = smax[t];
}

// ---------------- tail (merges pool partials, then MLP heads) ----------------
__global__ void __launch_bounds__(128) k_tail(
    const float* __restrict__ out_W, const float* __restrict__ out_b,
    const float* __restrict__ symfeat,
    const float* __restrict__ sym_W, const float* __restrict__ sym_b,
    const float* __restrict__ symf_W, const float* __restrict__ symf_b,
    const float* __restrict__ symf_g, const float* __restrict__ symf_beta,
    const float* __restrict__ fus_W, const float* __restrict__ fus_b,
    const float* __restrict__ fus_g, const float* __restrict__ fus_beta,
    const float* __restrict__ hW1, const float* __restrict__ hb1,
    const float* __restrict__ hW2, const float* __restrict__ hb2,
    float* __restrict__ outp)
{
    int b = blockIdx.x;
    int t = threadIdx.x;
    __shared__ float M[4], Dn[4];
    __shared__ float p[128];
    __shared__ float cat[256];
    __shared__ float buf[128];
    __shared__ float hh[192];
    __shared__ float ws[4], wq[4];

    if (t < 4) {
        float mm = -1e30f;
        for (int pp = 0; pp < SPLITS; ++pp)
            mm = fmaxf(mm, g_pm[(b * SPLITS + pp) * 4 + t]);
        M[t] = mm;
        float d = 0.f;
        for (int pp = 0; pp < SPLITS; ++pp) {
            float m = g_pm[(b * SPLITS + pp) * 4 + t];
            d += g_pd[(b * SPLITS + pp) * 4 + t] * expf(m - mm);
        }
        Dn[t] = d;
    }
    __syncthreads();
    {
        int h = t >> 5;
        float acc = 0.f;
        for (int pp = 0; pp < SPLITS; ++pp) {
            float m = g_pm[(b * SPLITS + pp) * 4 + h];
            acc += g_pp[(b * SPLITS + pp) * 128 + t] * expf(m - M[h]);
        }
        p[t] = (Dn[h] > 0.f) ? acc / Dn[h] : 0.f;
    }
    __syncthreads();
    {
        float acc = out_b[t];
        for (int k = 0; k < 128; ++k) acc = fmaf(out_W[t * 128 + k], p[k], acc);
        cat[t] = acc;
    }
    {
        int f = t >> 5, o = t & 31;
        const float* sf = symfeat + b * 64 + f * 16;
        const float* w  = sym_W + (f * 32 + o) * 16;
        float s = sym_b[f * 32 + o];
#pragma unroll
        for (int i = 0; i < 16; ++i) s = fmaf(w[i], sf[i], s);
        buf[t] = fmaxf(s, 0.f);
    }
    __syncthreads();
    {
        float s2 = symf_b[t];
        for (int k = 0; k < 128; ++k) s2 = fmaf(symf_W[t * 128 + k], buf[k], s2);
        s2 = fmaxf(s2, 0.f);
        float ssum = warp_sum(s2);
        float sq = warp_sum(s2 * s2);
        int wd = t >> 5, ln = t & 31;
        if (ln == 0) { ws[wd] = ssum; wq[wd] = sq; }
        __syncthreads();
        float ts = ws[0] + ws[1] + ws[2] + ws[3];
        float tq = wq[0] + wq[1] + wq[2] + wq[3];
        __syncthreads();
        float mean = ts * (1.f / 128.f);
        float var  = tq * (1.f / 128.f) - mean * mean;
        cat[128 + t] = (s2 - mean) * rsqrtf(var + 1e-5f) * symf_g[t] + symf_beta[t];
    }
    __syncthreads();
    {
        float f = fus_b[t];
        for (int k = 0; k < 256; ++k) f = fmaf(fus_W[t * 256 + k], cat[k], f);
        f = fmaxf(f, 0.f);
        float ssum = warp_sum(f);
        float sq = warp_sum(f * f);
        int wd = t >> 5, ln = t & 31;
        if (ln == 0) { ws[wd] = ssum; wq[wd] = sq; }
        __syncthreads();
        float ts = ws[0] + ws[1] + ws[2] + ws[3];
        float tq = wq[0] + wq[1] + wq[2] + wq[3];
        __syncthreads();
        float mean = ts * (1.f / 128.f);
        float var  = tq * (1.f / 128.f) - mean * mean;
        p[t] = (f - mean) * rsqrtf(var + 1e-5f) * fus_g[t] + fus_beta[t];
    }
    __syncthreads();
    for (int idx = t; idx < 192; idx += 128) {
        int k = idx >> 6, o = idx & 63;
        const float* w = hW1 + (size_t)(k * 64 + o) * 128;
        float acc = hb1[k * 64 + o];
        for (int j = 0; j < 128; ++j) acc = fmaf(w[j], p[j], acc);
        hh[idx] = fmaxf(acc, 0.f);
    }
    __syncthreads();
    if (t < 3) {
        float z = hb2[t];
        for (int o = 0; o < 64; ++o) z = fmaf(hW2[t * 64 + o], hh[t * 64 + o], z);
        outp[t * BB + b] = 1.f / (1.f + expf(-z));
    }
}

// ---------------- host ----------------
extern "C" void kernel_launch(void* const* d_in, const int* in_sizes, int n_in,
                              void* d_out, int out_size) {
    const float* nf = nullptr;
    const float* symf = nullptr;
    const int* ei = nullptr;
    const int* batch = nullptr;
    const float* P[26];
    int pi = 0;
    for (int i = 0; i < n_in; ++i) {
        int sz = in_sizes[i];
        if (sz == NN * HH)       nf    = (const float*)d_in[i];
        else if (sz == BB * 64)  symf  = (const float*)d_in[i];
        else if (sz == 2 * EE)   ei    = (const int*)d_in[i];
        else if (sz == NN)       batch = (const int*)d_in[i];
        else if (pi < 26)        P[pi++] = (const float*)d_in[i];
    }
    const float *W_in = P[0], *b_in = P[1], *sage_Wl = P[2], *sage_bl = P[3],
                *sage_Wr = P[4], *ln_g = P[5], *ln_b = P[6], *query = P[7],
                *in_proj_W = P[8], *in_proj_b = P[9], *out_W = P[10], *out_b = P[11],
                *sym_W = P[12], *sym_b = P[13], *symf_W = P[14], *symf_b = P[15],
                *symf_g = P[16], *symf_beta = P[17], *fus_W = P[18], *fus_b = P[19],
                *fus_g = P[20], *fus_beta = P[21], *hW1 = P[22], *hb1 = P[23],
                *hW2 = P[24], *hb2 = P[25];

    uint32_t *pxA, *pxB, *pag;
    float* pv;
    cudaGetSymbolAddress((void**)&pxA, g_xA);
    cudaGetSymbolAddress((void**)&pxB, g_xB);
    cudaGetSymbolAddress((void**)&pag, g_agg);
    cudaGetSymbolAddress((void**)&pv,  g_v);

    cudaFuncSetAttribute((const void*)k_mma<0>, cudaFuncAttributeMaxDynamicSharedMemorySize, SMEM_BYTES);
    cudaFuncSetAttribute((const void*)k_mma<1>, cudaFuncAttributeMaxDynamicSharedMemorySize, SMEM_BYTES);
    cudaFuncSetAttribute((const void*)k_mma<2>, cudaFuncAttributeMaxDynamicSharedMemorySize, SMEM_BYTES);

    // weight slots: 0=W_in, 1=Wl0, 2=Wr0, 3=Wl1, 4=Wr1, 5=Wl2, 6=Wr2, 7=Wv
    k_setup1<<<324, 256>>>(W_in,
                           sage_Wl + 0 * 16384, sage_Wr + 0 * 16384,
                           sage_Wl + 1 * 16384, sage_Wr + 1 * 16384,
                           sage_Wl + 2 * 16384, sage_Wr + 2 * 16384,
                           in_proj_W + 256 * 128);
    k_deg<<<(EE + 255) / 256, 256>>>(ei);
    k_setup2<<<2 + (NN + 1023) / 1024, 1024>>>(in_proj_W, in_proj_b, query, batch);
    // index 3: input-proj GEMM (profiled sample slot)
    k_mma<0><<<TILES64, 512, SMEM_BYTES>>>(nf, nullptr, nullptr, 0, b_in,
                                           nullptr, nullptr, pxA, nullptr, NN);
    k_fill<<<(EE + 255) / 256, 256>>>(ei);

    uint32_t *cur = pxA, *nxt = pxB;
    for (int l = 0; l < 3; ++l) {
        k_aggr<<<(NN * 32 + 255) / 256, 256>>>(cur);
        k_mma<1><<<TILES64, 512, SMEM_BYTES>>>(nullptr, pag, cur, 1 + 2 * l,
                                               sage_bl + l * 128,
                                               ln_g + l * 128, ln_b + l * 128,
                                               nxt, nullptr, NN);
        uint32_t* tmp = cur; cur = nxt; nxt = tmp;
    }

    // v = x @ Wv^T + bv (fp32) + fused attention scores
    k_mma<2><<<TILES64, 512, SMEM_BYTES>>>(nullptr, cur, nullptr, 7, in_proj_b + 256,
                                           nullptr, nullptr, nullptr, pv, NN);

    k_pool_part<<<BB * SPLITS, 128>>>();
    k_tail<<<BB, 128>>>(out_W, out_b, symf, sym_W, sym_b,
                        symf_W, symf_b, symf_g, symf_beta,
                        fus_W, fus_b, fus_g, fus_beta,
                        hW1, hb1, hW2, hb2, (float*)d_out);
    (void)out_size;
}

// round 11
// speedup vs baseline: 1.9799x; 1.0083x over previous
#include <cuda_runtime.h>
#include <cuda_bf16.h>
#include <math.h>
#include <stdint.h>

#define NN 50000
#define EE 800000
#define BB 64
#define HH 128
#define TILES64 782   // ceil(50000/64)
#define SPLITS 8

// ---------------- scratch (device globals) ----------------
// x as interleaved bf16 hi/lo: per node 128 uint32 = [64 hi words | 64 lo words]
__device__ uint32_t g_xA [NN * 128];
__device__ uint32_t g_xB [NN * 128];
__device__ uint32_t g_agg[NN * 64];   // single bf16 plane (hi only)
__device__ float g_v   [NN * HH];
__device__ float g_scores[NN * 4];
__device__ float g_U[HH * 4];
__device__ float g_cvec[4];
__device__ float g_pm[BB * SPLITS * 4];
__device__ float g_pd[BB * SPLITS * 4];
__device__ float g_pp[BB * SPLITS * 128];
__device__ int   g_deg[NN];
__device__ int   g_off[NN + 1];
__device__ int   g_cur[NN];
__device__ int   g_col[EE];
__device__ int   g_gstart[BB + 1];
__device__ uint4 g_wbuf[8 * 4096];

// ---------------- helpers ----------------
__device__ __forceinline__ void hilo(float v, uint32_t& h, uint32_t& l) {
    __nv_bfloat16 hb = __float2bfloat16(v);
    __nv_bfloat16 lb = __float2bfloat16(v - __bfloat162float(hb));
    h = (uint32_t)__bfloat16_as_ushort(hb);
    l = (uint32_t)__bfloat16_as_ushort(lb);
}
__device__ __forceinline__ uint32_t bfh(float v) {
    return (uint32_t)__bfloat16_as_ushort(__float2bfloat16(v));
}
__device__ __forceinline__ float2 bf2f(uint32_t u) {
    __nv_bfloat162 h;
    *reinterpret_cast<uint32_t*>(&h) = u;
    return __bfloat1622float2(h);
}
__device__ __forceinline__ uint32_t smem_u32(const void* p) {
    uint32_t a;
    asm("{ .reg .u64 t; cvta.to.shared.u64 t, %1; cvt.u32.u64 %0, t; }" : "=r"(a) : "l"(p));
    return a;
}
__device__ __forceinline__ float warp_sum(float v) {
#pragma unroll
    for (int o = 16; o > 0; o >>= 1) v += __shfl_xor_sync(0xffffffffu, v, o);
    return v;
}

#define HMMA(C, A0, A1, A2, A3, B0, B1) \
    asm volatile("mma.sync.aligned.m16n8k16.row.col.f32.bf16.bf16.f32 " \
                 "{%0,%1,%2,%3}, {%4,%5,%6,%7}, {%8,%9}, {%0,%1,%2,%3};" \
                 : "+f"((C)[0]), "+f"((C)[1]), "+f"((C)[2]), "+f"((C)[3]) \
                 : "r"(A0), "r"(A1), "r"(A2), "r"(A3), "r"(B0), "r"(B1))

#define LDSM4(D0, D1, D2, D3, A) \
    asm volatile("ldmatrix.sync.aligned.m8n8.x4.shared.b16 {%0,%1,%2,%3}, [%4];" \
                 : "=r"(D0), "=r"(D1), "=r"(D2), "=r"(D3) : "r"(A))

#define CP_ASYNC16(dst, src, sz) \
    asm volatile("cp.async.cg.shared.global [%0], [%1], 16, %2;" \
                 :: "r"(dst), "l"(src), "r"(sz) : "memory")
#define CP_COMMIT() asm volatile("cp.async.commit_group;" ::: "memory")
#define CP_WAIT0()  asm volatile("cp.async.wait_group 0;" ::: "memory")

// ---------------- SMEM layout (64-row tile) ----------------
#define OFF_AH  0
#define OFF_AL  16384
#define OFF_WH  32768
#define OFF_WL  65536
#define OFF_MISC 98304
#define OFF_BIAS (OFF_MISC)
#define OFF_G    (OFF_MISC + 512)
#define OFF_BETA (OFF_MISC + 1024)
#define OFF_MEAN (OFF_MISC + 1536)
#define OFF_RSTD (OFF_MISC + 1856)
#define OFF_U    (OFF_MISC + 2176)
#define OFF_CV   (OFF_MISC + 4224)
#define SMEM_BYTES (OFF_MISC + 4256)

__device__ __forceinline__ int CIDX(int row, int col) {
    return row * 128 + (((col >> 2) ^ (row & 7)) << 2) + (col & 3);
}
__device__ __forceinline__ int PIDX(int row, int cp) {
    return row * 64 + (((cp >> 2) ^ (row & 7)) << 2) + (cp & 3);
}

// ---------------- setup1: CSR init + weight pre-conversion ----------------
__global__ void k_setup1(const float* w0, const float* w1, const float* w2, const float* w3,
                         const float* w4, const float* w5, const float* w6, const float* w7) {
    int b = blockIdx.x;
    if (b < 196) {
        int i = b * 256 + threadIdx.x;
        if (i < NN) { g_deg[i] = 0; g_cur[i] = 0; }
        return;
    }
    int bb = b - 196;
    int m = bb >> 4;
    const float* W;
    switch (m) {
        case 0: W = w0; break; case 1: W = w1; break; case 2: W = w2; break;
        case 3: W = w3; break; case 4: W = w4; break; case 5: W = w5; break;
        case 6: W = w6; break; default: W = w7; break;
    }
    int i = (bb & 15) * 256 + threadIdx.x;
    int row = i >> 5, q = i & 31;
    float4 v = *reinterpret_cast<const float4*>(W + (size_t)row * 128 + q * 4);
    uint32_t h0, l0, h1, l1, h2, l2, h3, l3;
    hilo(v.x, h0, l0); hilo(v.y, h1, l1); hilo(v.z, h2, l2); hilo(v.w, h3, l3);
    uint2 uh, ul;
    uh.x = h0 | (h1 << 16); uh.y = h2 | (h3 << 16);
    ul.x = l0 | (l1 << 16); ul.y = l2 | (l3 << 16);
    char* base = (char*)g_wbuf + (size_t)m * 65536;
    int sw = row * 256 + q * 8;
    *reinterpret_cast<uint2*>(base + sw)         = uh;
    *reinterpret_cast<uint2*>(base + 32768 + sw) = ul;
}

// ---------------- deg count ----------------
__global__ void k_deg(const int* __restrict__ ei) {
    int e = blockIdx.x * blockDim.x + threadIdx.x;
    if (e < EE) atomicAdd(&g_deg[ei[EE + e]], 1);
}

// ---------------- setup2: scan + attention prep + graph bounds ----------------
__global__ void __launch_bounds__(1024) k_setup2(const float* __restrict__ in_proj_W,
                                                 const float* __restrict__ in_proj_b,
                                                 const float* __restrict__ query,
                                                 const int* __restrict__ batch) {
    int t = threadIdx.x;
    if (blockIdx.x == 0) {
        __shared__ int sm[1024];
        const int chunk = (NN + 1023) / 1024;
        int base = t * chunk;
        int s = 0;
        for (int i = 0; i < chunk; ++i) {
            int idx = base + i;
            if (idx < NN) s += g_deg[idx];
        }
        sm[t] = s;
        __syncthreads();
        for (int d = 1; d < 1024; d <<= 1) {
            int add = (t >= d) ? sm[t - d] : 0;
            __syncthreads();
            sm[t] += add;
            __syncthreads();
        }
        int run = sm[t] - s;
        for (int i = 0; i < chunk; ++i) {
            int idx = base + i;
            if (idx < NN) { g_off[idx] = run; run += g_deg[idx]; }
        }
        if (t == 1023) g_off[NN] = sm[1023];
    } else if (blockIdx.x == 1) {
        __shared__ float qv[128];
        if (t < 128) {
            float s = in_proj_b[t];
            for (int k = 0; k < 128; ++k) s = fmaf(in_proj_W[t * 128 + k], query[k], s);
            qv[t] = s;
        }
        __syncthreads();
        if (t < 128) {
            const float inv = 1.0f / sqrtf(32.0f);
            float u[4] = {0.f, 0.f, 0.f, 0.f};
            for (int r = 0; r < 128; ++r) {
                float w = in_proj_W[(128 + r) * 128 + t];
                u[r >> 5] = fmaf(qv[r], w, u[r >> 5]);
            }
#pragma unroll
            for (int h = 0; h < 4; ++h) g_U[t * 4 + h] = u[h] * inv;
            if (t < 4) {
                float cc = 0.f;
                for (int d = 0; d < 32; ++d)
                    cc = fmaf(qv[t * 32 + d], in_proj_b[128 + t * 32 + d], cc);
                g_cvec[t] = cc * inv;
            }
        }
    } else {
        int i = (blockIdx.x - 2) * 1024 + t;
        if (i >= NN) return;
        int bi = batch[i];
        if (i == 0) {
            for (int g = 0; g <= bi; ++g) g_gstart[g] = 0;
        } else {
            int bp = batch[i - 1];
            for (int g = bp + 1; g <= bi; ++g) g_gstart[g] = i;
        }
        if (i == NN - 1) {
            for (int g = bi + 1; g <= BB; ++g) g_gstart[g] = NN;
        }
    }
}

// ---------------- CSR fill ----------------
__global__ void k_fill(const int* __restrict__ ei) {
    int e = blockIdx.x * blockDim.x + threadIdx.x;
    if (e < EE) {
        int s = ei[e];
        int d = ei[EE + e];
        int slot = atomicAdd(&g_cur[d], 1);
        g_col[g_off[d] + slot] = s;
    }
}

// ---------------- GEMM fills ----------------
// full hi/lo tile from interleaved planes (node block = 128 words: hi 0..63, lo 64..127)
__device__ __forceinline__ void fill_copy_async(const uint32_t* __restrict__ g,
                                                uint32_t sb, int tile0, int nrows, int t) {
#pragma unroll
    for (int rep = 0; rep < 4; ++rep) {
        int i = t + rep * 512;          // 0..2047 = 64 rows x 32 chunks(16B)
        int row = i >> 5, c = i & 31;
        int grow = tile0 + row;
        int sz = (grow < nrows) ? 16 : 0;
        const char* src = (const char*)(g + (size_t)grow * 128) + c * 16;
        int cc = c & 15;
        int phys = row * 256 + ((cc ^ (row & 7)) << 4);
        uint32_t dst = sb + ((c < 16) ? OFF_AH : OFF_AL) + phys;
        CP_ASYNC16(dst, src, sz);
    }
}
// hi plane of interleaved x (16KB) into dstoff
__device__ __forceinline__ void fill_copy_hi(const uint32_t* __restrict__ g,
                                             uint32_t sb, uint32_t dstoff,
                                             int tile0, int nrows, int t) {
#pragma unroll
    for (int rep = 0; rep < 2; ++rep) {
        int i = t + rep * 512;          // 0..1023 = 64 rows x 16 chunks
        int row = i >> 4, chunk = i & 15;
        int grow = tile0 + row;
        int sz = (grow < nrows) ? 16 : 0;
        const char* src = (const char*)(g + (size_t)grow * 128) + chunk * 16;
        int phys = row * 256 + ((chunk ^ (row & 7)) << 4);
        CP_ASYNC16(sb + dstoff + phys, src, sz);
    }
}
// lo plane of interleaved x (16KB) into dstoff
__device__ __forceinline__ void fill_copy_lo(const uint32_t* __restrict__ g,
                                             uint32_t sb, uint32_t dstoff,
                                             int tile0, int nrows, int t) {
#pragma unroll
    for (int rep = 0; rep < 2; ++rep) {
        int i = t + rep * 512;
        int row = i >> 4, chunk = i & 15;
        int grow = tile0 + row;
        int sz = (grow < nrows) ? 16 : 0;
        const char* src = (const char*)(g + (size_t)grow * 128) + (16 + chunk) * 16;
        int phys = row * 256 + ((chunk ^ (row & 7)) << 4);
        CP_ASYNC16(sb + dstoff + phys, src, sz);
    }
}
// single-plane A tile (16KB) from g_agg (node block = 64 words)
__device__ __forceinline__ void fill_copy_half(const uint32_t* __restrict__ g,
                                               uint32_t sb, int tile0, int nrows, int t) {
#pragma unroll
    for (int rep = 0; rep < 2; ++rep) {
        int i = t + rep * 512;
        int row = i >> 4, chunk = i & 15;
        int grow = tile0 + row;
        int sz = (grow < nrows) ? 16 : 0;
        const char* src = (const char*)(g + (size_t)grow * 64) + chunk * 16;
        int phys = row * 256 + ((chunk ^ (row & 7)) << 4);
        CP_ASYNC16(sb + OFF_AH + phys, src, sz);
    }
}
// W hi+lo (64KB) for MODE0
__device__ __forceinline__ void fill_W_async(int slot, uint32_t sb, int t) {
    const char* src = (const char*)g_wbuf + (size_t)slot * 65536;
#pragma unroll
    for (int rep = 0; rep < 4; ++rep) {
        int i = t + rep * 512;
        int row = i >> 4, chunk = i & 15;
        int phys = row * 256 + ((chunk ^ (row & 7)) << 4);
        CP_ASYNC16(sb + OFF_WH + phys, src + i * 16, 16);
        CP_ASYNC16(sb + OFF_WL + phys, src + 32768 + i * 16, 16);
    }
}
// W hi-plane only (32KB) into dstoff
__device__ __forceinline__ void fill_Whi_async(int slot, uint32_t sb, uint32_t dstoff, int t) {
    const char* src = (const char*)g_wbuf + (size_t)slot * 65536;
#pragma unroll
    for (int rep = 0; rep < 4; ++rep) {
        int i = t + rep * 512;
        int row = i >> 4, chunk = i & 15;
        int phys = row * 256 + ((chunk ^ (row & 7)) << 4);
        CP_ASYNC16(sb + dstoff + phys, src + i * 16, 16);
    }
}
// fp32 -> hi/lo smem tile, MLP-4: all loads issued before converts
__device__ __forceinline__ void fill_convert(const float* __restrict__ A, char* smem,
                                             int tile0, int nrows, int t) {
    float4 v[4];
#pragma unroll
    for (int rep = 0; rep < 4; ++rep) {
        int i = t + rep * 512;
        int row = i >> 5, q = i & 31;
        int grow = tile0 + row;
        v[rep] = make_float4(0.f, 0.f, 0.f, 0.f);
        if (grow < nrows)
            v[rep] = __ldg(reinterpret_cast<const float4*>(A + (size_t)grow * HH + q * 4));
    }
#pragma unroll
    for (int rep = 0; rep < 4; ++rep) {
        int i = t + rep * 512;
        int row = i >> 5, q = i & 31;
        uint32_t h0, l0, h1, l1, h2, l2, h3, l3;
        hilo(v[rep].x, h0, l0); hilo(v[rep].y, h1, l1);
        hilo(v[rep].z, h2, l2); hilo(v[rep].w, h3, l3);
        uint2 uh, ul;
        uh.x = h0 | (h1 << 16); uh.y = h2 | (h3 << 16);
        ul.x = l0 | (l1 << 16); ul.y = l2 | (l3 << 16);
        int phys = row * 256 + (((q >> 1) ^ (row & 7)) << 4) + (q & 1) * 8;
        *reinterpret_cast<uint2*>(smem + OFF_AH + phys) = uh;
        *reinterpret_cast<uint2*>(smem + OFF_AL + phys) = ul;
    }
}

// ---------------- mainloop ----------------
// TERMS: 1 = Ah*Bh | 2 = Ah*Bh + Al*Bh | 3 = Ah*Bh + Ah*Bl + Al*Bh (B lo at boff+32768)
// A hi plane at aoff_hi; A lo plane at aoff_lo (TERMS>=2)
template <int TERMS>
__device__ __forceinline__ void mainloop(uint32_t sb, uint32_t aoff_hi, uint32_t aoff_lo,
                                         uint32_t boff, float c[4][4],
                                         int wm, int wn, int lane) {
    uint32_t rowA = wm * 16 + (lane & 15);
    uint32_t swA = rowA & 7;
    uint32_t aAddrH = sb + aoff_hi + rowA * 256;
    uint32_t aAddrL = sb + aoff_lo + rowA * 256;
    uint32_t halfA = lane >> 4;
    uint32_t wrow = sb + boff + (uint32_t)(wn * 32 + lane) * 256;
    uint32_t swB = lane & 7;
#pragma unroll
    for (int ks = 0; ks < 8; ++ks) {
        uint32_t bh0[4], bh1[4];
        uint32_t cb0 = (uint32_t)(((2 * ks) ^ swB) << 4);
        uint32_t cb1 = (uint32_t)(((2 * ks + 1) ^ swB) << 4);
        LDSM4(bh0[0], bh0[1], bh0[2], bh0[3], wrow + cb0);
        LDSM4(bh1[0], bh1[1], bh1[2], bh1[3], wrow + cb1);
        uint32_t bl0[4], bl1[4];
        if (TERMS == 3) {
            LDSM4(bl0[0], bl0[1], bl0[2], bl0[3], wrow + 32768 + cb0);
            LDSM4(bl1[0], bl1[1], bl1[2], bl1[3], wrow + 32768 + cb1);
        }
        uint32_t ca = (uint32_t)(((2 * ks + halfA) ^ swA) << 4);
        uint32_t ah0, ah1, ah2, ah3;
        LDSM4(ah0, ah1, ah2, ah3, aAddrH + ca);
        uint32_t al0, al1, al2, al3;
        if (TERMS >= 2) LDSM4(al0, al1, al2, al3, aAddrL + ca);
#pragma unroll
        for (int nb = 0; nb < 4; ++nb) {
            HMMA(c[nb], ah0, ah1, ah2, ah3, bh0[nb], bh1[nb]);
            if (TERMS == 3) HMMA(c[nb], ah0, ah1, ah2, ah3, bl0[nb], bl1[nb]);
            if (TERMS >= 2) HMMA(c[nb], al0, al1, al2, al3, bh0[nb], bh1[nb]);
        }
    }
}

// MODE: 0 = input proj (3-term, W hi/lo)
//       1 = SAGE: upfront {Wl_hi, Wr_hi, agg_hi->AH, x_hi->AL}; pass1 agg 1-term;
//                 mid-fill x_lo->AH; pass2 x 2-term (hi=AL, lo=AH); LN+relu+residual
//       2 = V proj + scores (2-term, Wv hi only)
template <int MODE>
__global__ void __launch_bounds__(512, 2) k_mma(
    const float* __restrict__ Afp,
    const uint32_t* __restrict__ p1, const uint32_t* __restrict__ p2,
    int wslot, const float* __restrict__ bias,
    const float* __restrict__ lng, const float* __restrict__ lnb,
    uint32_t* __restrict__ out, float* __restrict__ outf, int nrows)
{
    extern __shared__ char smem[];
    uint32_t sb = smem_u32(smem);
    int t = threadIdx.x, wid = t >> 5, lane = t & 31;
    int tile0 = blockIdx.x * 64;
    int wm = wid & 3, wn = wid >> 2;

    if (MODE == 0) {
        fill_W_async(wslot, sb, t);                   // W_in hi+lo
    } else if (MODE == 1) {
        fill_Whi_async(wslot, sb, OFF_WH, t);         // Wl hi
        fill_Whi_async(wslot + 1, sb, OFF_WL, t);     // Wr hi
        fill_copy_half(p1, sb, tile0, nrows, t);      // agg hi -> AH
        fill_copy_hi(p2, sb, OFF_AL, tile0, nrows, t);// x hi  -> AL (prefetch)
    } else {
        fill_Whi_async(wslot, sb, OFF_WH, t);         // Wv hi
        fill_copy_async(p1, sb, tile0, nrows, t);     // x hi+lo
    }
    CP_COMMIT();

    if (t < 128) {
        ((float*)(smem + OFF_BIAS))[t] = bias[t];
        if (MODE == 1) {
            ((float*)(smem + OFF_G))[t]    = lng[t];
            ((float*)(smem + OFF_BETA))[t] = lnb[t];
        }
    }
    if (MODE == 2) {
        if (t >= 128 && t < 256) ((float4*)(smem + OFF_U))[t - 128] = ((const float4*)g_U)[t - 128];
        if (t == 256) *((float4*)(smem + OFF_CV)) = *((const float4*)g_cvec);
    }
    if (MODE == 0) fill_convert(Afp, smem, tile0, nrows, t);

    float c[4][4];
#pragma unroll
    for (int nb = 0; nb < 4; ++nb)
#pragma unroll
        for (int j = 0; j < 4; ++j) c[nb][j] = 0.f;

    CP_WAIT0();
    __syncthreads();

    if (MODE == 0)      mainloop<3>(sb, OFF_AH, OFF_AL, OFF_WH, c, wm, wn, lane);
    else if (MODE == 1) mainloop<1>(sb, OFF_AH, OFF_AH, OFF_WH, c, wm, wn, lane);
    else                mainloop<2>(sb, OFF_AH, OFF_AL, OFF_WH, c, wm, wn, lane);

    if (MODE == 1) {
        __syncthreads();
        fill_copy_lo(p2, sb, OFF_AH, tile0, nrows, t);   // x lo -> AH (over dead agg)
        CP_COMMIT();
        CP_WAIT0();
        __syncthreads();
        mainloop<2>(sb, OFF_AL, OFF_AH, OFF_WL, c, wm, wn, lane);  // x @ Wr_hi
    }
    __syncthreads();

    if (MODE == 2) {
        if (t < 64) {
            int grow = tile0 + t;
            if (grow < nrows) {
                const uint32_t* ph = (const uint32_t*)(smem + OFF_AH);
                const uint32_t* pl = (const uint32_t*)(smem + OFF_AL);
                const float4* U4 = (const float4*)(smem + OFF_U);
                const float* cv = (const float*)(smem + OFF_CV);
                float a0 = cv[0], a1 = cv[1], a2 = cv[2], a3 = cv[3];
#pragma unroll
                for (int kk = 0; kk < 64; ++kk) {
                    int idx = PIDX(t, kk);
                    float2 h = bf2f(ph[idx]);
                    float2 l = bf2f(pl[idx]);
                    float x0 = h.x + l.x, x1 = h.y + l.y;
                    float4 u0 = U4[2 * kk];
                    float4 u1 = U4[2 * kk + 1];
                    a0 += x0 * u0.x + x1 * u1.x;
                    a1 += x0 * u0.y + x1 * u1.y;
                    a2 += x0 * u0.z + x1 * u1.z;
                    a3 += x0 * u0.w + x1 * u1.w;
                }
                float4 r; r.x = a0; r.y = a1; r.z = a2; r.w = a3;
                reinterpret_cast<float4*>(g_scores)[grow] = r;
            }
        }
        __syncthreads();
    }

    // spill C over W-hi region (dead after mainloops)
    float* Csm = (float*)(smem + OFF_WH);
    int g = lane >> 2, tt = lane & 3;
    {
        int r0 = wm * 16 + g;
        int r1 = r0 + 8;
#pragma unroll
        for (int nb = 0; nb < 4; ++nb) {
            int col = wn * 32 + nb * 8 + tt * 2;
            Csm[CIDX(r0, col)]     = c[nb][0];
            Csm[CIDX(r0, col + 1)] = c[nb][1];
            Csm[CIDX(r1, col)]     = c[nb][2];
            Csm[CIDX(r1, col + 1)] = c[nb][3];
        }
    }
    __syncthreads();

    const float* bs = (const float*)(smem + OFF_BIAS);
    if (MODE == 1) {
        if (t < 64) {
            float sum = 0.f, sq = 0.f;
#pragma unroll
            for (int j = 0; j < 128; ++j) {
                float x = Csm[CIDX(t, j)] + bs[j];
                sum += x; sq += x * x;
            }
            float mean = sum * (1.f / 128.f);
            float var  = sq * (1.f / 128.f) - mean * mean;
            ((float*)(smem + OFF_MEAN))[t] = mean;
            ((float*)(smem + OFF_RSTD))[t] = rsqrtf(var + 1e-5f);
        }
        __syncthreads();
    }

    if (MODE == 2) {
#pragma unroll
        for (int rep = 0; rep < 4; ++rep) {
            int i = t + rep * 512;
            int row = i >> 5, q = i & 31;
            int grow = tile0 + row;
            if (grow >= nrows) continue;
            int base = row * 128 + ((q ^ (row & 7)) << 2);
            float4 o;
            o.x = Csm[base + 0] + bs[q * 4 + 0];
            o.y = Csm[base + 1] + bs[q * 4 + 1];
            o.z = Csm[base + 2] + bs[q * 4 + 2];
            o.w = Csm[base + 3] + bs[q * 4 + 3];
            *reinterpret_cast<float4*>(outf + (size_t)grow * HH + q * 4) = o;
        }
    } else {
        const float* gg = (const float*)(smem + OFF_G);
        const float* bb = (const float*)(smem + OFF_BETA);
        const float* mn = (const float*)(smem + OFF_MEAN);
        const float* rs = (const float*)(smem + OFF_RSTD);
        // MODE1: x hi at OFF_AL, x lo at OFF_AH (post-swap); MODE0 unused
        const uint32_t* rxh = (const uint32_t*)(smem + OFF_AL);
        const uint32_t* rxl = (const uint32_t*)(smem + OFF_AH);
#pragma unroll
        for (int rep = 0; rep < 8; ++rep) {
            int i = t + rep * 512;
            int row = i >> 6, cp = i & 63;
            int grow = tile0 + row;
            if (grow >= nrows) continue;
            int c0 = cp * 2;
            float x0 = Csm[CIDX(row, c0)]     + bs[c0];
            float x1 = Csm[CIDX(row, c0 + 1)] + bs[c0 + 1];
            float o0, o1;
            if (MODE == 1) {
                float mean = mn[row], rstd = rs[row];
                int idx = PIDX(row, cp);
                float2 rh = bf2f(rxh[idx]);
                float2 rl = bf2f(rxl[idx]);
                o0 = fmaxf((x0 - mean) * rstd * gg[c0]     + bb[c0],     0.f) + (rh.x + rl.x);
                o1 = fmaxf((x1 - mean) * rstd * gg[c0 + 1] + bb[c0 + 1], 0.f) + (rh.y + rl.y);
            } else {
                o0 = fmaxf(x0, 0.f);
                o1 = fmaxf(x1, 0.f);
            }
            uint32_t h0, l0, h1, l1;
            hilo(o0, h0, l0); hilo(o1, h1, l1);
            out[(size_t)grow * 128 + cp]      = h0 | (h1 << 16);
            out[(size_t)grow * 128 + 64 + cp] = l0 | (l1 << 16);
        }
    }
}

// ---------------- neighbor mean aggregation (hi plane only) ----------------
__global__ void __launch_bounds__(256) k_aggr(const uint32_t* __restrict__ x) {
    int warp = (blockIdx.x * blockDim.x + threadIdx.x) >> 5;
    int lane = threadIdx.x & 31;
    if (warp >= NN) return;
    int s0 = g_off[warp], s1 = g_off[warp + 1];
    float a0 = 0.f, a1 = 0.f, a2 = 0.f, a3 = 0.f;
    const uint2* xp = reinterpret_cast<const uint2*>(x);
#pragma unroll 4
    for (int i = s0; i < s1; ++i) {
        int nb = __ldg(&g_col[i]);
        uint2 v = __ldg(xp + (size_t)nb * 64 + lane);
        float2 f0 = bf2f(v.x), f1 = bf2f(v.y);
        a0 += f0.x; a1 += f0.y; a2 += f1.x; a3 += f1.y;
    }
    float inv = 1.f / fmaxf((float)(s1 - s0), 1.f);
    a0 *= inv; a1 *= inv; a2 *= inv; a3 *= inv;
    uint2 o;
    o.x = bfh(a0) | (bfh(a1) << 16);
    o.y = bfh(a2) | (bfh(a3) << 16);
    reinterpret_cast<uint2*>(g_agg)[(size_t)warp * 32 + lane] = o;
}

// ---------------- split softmax pool: partials ----------------
__global__ void __launch_bounds__(128) k_pool_part() {
    int b = blockIdx.x >> 3, p = blockIdx.x & 7;
    int s0 = g_gstart[b], s1 = g_gstart[b + 1];
    int len = s1 - s0;
    int q0 = s0 + (len * p) / SPLITS;
    int q1 = s0 + (len * (p + 1)) / SPLITS;
    int t = threadIdx.x;
    __shared__ float4 red[128];
    __shared__ float smax[4];

    float4 mx = make_float4(-1e30f, -1e30f, -1e30f, -1e30f);
    for (int n = q0 + t; n < q1; n += 128) {
        float4 f = reinterpret_cast<const float4*>(g_scores)[n];
        mx.x = fmaxf(mx.x, f.x); mx.y = fmaxf(mx.y, f.y);
        mx.z = fmaxf(mx.z, f.z); mx.w = fmaxf(mx.w, f.w);
    }
    red[t] = mx;
    __syncthreads();
    for (int s = 64; s > 0; s >>= 1) {
        if (t < s) {
            float4 a = red[t], c = red[t + s];
            a.x = fmaxf(a.x, c.x); a.y = fmaxf(a.y, c.y);
            a.z = fmaxf(a.z, c.z); a.w = fmaxf(a.w, c.w);
            red[t] = a;
        }
        __syncthreads();
    }
    if (t == 0) { smax[0] = red[0].x; smax[1] = red[0].y; smax[2] = red[0].z; smax[3] = red[0].w; }
    __syncthreads();

    int h = t >> 5;
    float m = smax[h];
    float pl = 0.f, den = 0.f;
#pragma unroll 2
    for (int n = q0; n < q1; ++n) {
        float e = expf(g_scores[n * 4 + h] - m);
        pl = fmaf(e, g_v[(size_t)n * HH + t], pl);
        den += e;
    }
    int slot = b * SPLITS + p;
    g_pp[slot * 128 + t] = pl;
    if ((t & 31) == 0) g_pd[slot * 4 + h] = den;
    if (t < 4) g_pm[slot * 4 + t] = smax[t];
}

// ---------------- tail (merges pool partials, then MLP heads) ----------------
__global__ void __launch_bounds__(128) k_tail(
    const float* __restrict__ out_W, const float* __restrict__ out_b,
    const float* __restrict__ symfeat,
    const float* __restrict__ sym_W, const float* __restrict__ sym_b,
    const float* __restrict__ symf_W, const float* __restrict__ symf_b,
    const float* __restrict__ symf_g, const float* __restrict__ symf_beta,
    const float* __restrict__ fus_W, const float* __restrict__ fus_b,
    const float* __restrict__ fus_g, const float* __restrict__ fus_beta,
    const float* __restrict__ hW1, const float* __restrict__ hb1,
    const float* __restrict__ hW2, const float* __restrict__ hb2,
    float* __restrict__ outp)
{
    int b = blockIdx.x;
    int t = threadIdx.x;
    __shared__ float M[4], Dn[4];
    __shared__ float p[128];
    __shared__ float cat[256];
    __shared__ float buf[128];
    __shared__ float hh[192];
    __shared__ float ws[4], wq[4];

    if (t < 4) {
        float mm = -1e30f;
        for (int pp = 0; pp < SPLITS; ++pp)
            mm = fmaxf(mm, g_pm[(b * SPLITS + pp) * 4 + t]);
        M[t] = mm;
        float d = 0.f;
        for (int pp = 0; pp < SPLITS; ++pp) {
            float m = g_pm[(b * SPLITS + pp) * 4 + t];
            d += g_pd[(b * SPLITS + pp) * 4 + t] * expf(m - mm);
        }
        Dn[t] = d;
    }
    __syncthreads();
    {
        int h = t >> 5;
        float acc = 0.f;
        for (int pp = 0; pp < SPLITS; ++pp) {
            float m = g_pm[(b * SPLITS + pp) * 4 + h];
            acc += g_pp[(b * SPLITS + pp) * 128 + t] * expf(m - M[h]);
        }
        p[t] = (Dn[h] > 0.f) ? acc / Dn[h] : 0.f;
    }
    __syncthreads();
    {
        float acc = out_b[t];
        for (int k = 0; k < 128; ++k) acc = fmaf(out_W[t * 128 + k], p[k], acc);
        cat[t] = acc;
    }
    {
        int f = t >> 5, o = t & 31;
        const float* sf = symfeat + b * 64 + f * 16;
        const float* w  = sym_W + (f * 32 + o) * 16;
        float s = sym_b[f * 32 + o];
#pragma unroll
        for (int i = 0; i < 16; ++i) s = fmaf(w[i], sf[i], s);
        buf[t] = fmaxf(s, 0.f);
    }
    __syncthreads();
    {
        float s2 = symf_b[t];
        for (int k = 0; k < 128; ++k) s2 = fmaf(symf_W[t * 128 + k], buf[k], s2);
        s2 = fmaxf(s2, 0.f);
        float ssum = warp_sum(s2);
        float sq = warp_sum(s2 * s2);
        int wd = t >> 5, ln = t & 31;
        if (ln == 0) { ws[wd] = ssum; wq[wd] = sq; }
        __syncthreads();
        float ts = ws[0] + ws[1] + ws[2] + ws[3];
        float tq = wq[0] + wq[1] + wq[2] + wq[3];
        __syncthreads();
        float mean = ts * (1.f / 128.f);
        float var  = tq * (1.f / 128.f) - mean * mean;
        cat[128 + t] = (s2 - mean) * rsqrtf(var + 1e-5f) * symf_g[t] + symf_beta[t];
    }
    __syncthreads();
    {
        float f = fus_b[t];
        for (int k = 0; k < 256; ++k) f = fmaf(fus_W[t * 256 + k], cat[k], f);
        f = fmaxf(f, 0.f);
        float ssum = warp_sum(f);
        float sq = warp_sum(f * f);
        int wd = t >> 5, ln = t & 31;
        if (ln == 0) { ws[wd] = ssum; wq[wd] = sq; }
        __syncthreads();
        float ts = ws[0] + ws[1] + ws[2] + ws[3];
        float tq = wq[0] + wq[1] + wq[2] + wq[3];
        __syncthreads();
        float mean = ts * (1.f / 128.f);
        float var  = tq * (1.f / 128.f) - mean * mean;
        p[t] = (f - mean) * rsqrtf(var + 1e-5f) * fus_g[t] + fus_beta[t];
    }
    __syncthreads();
    for (int idx = t; idx < 192; idx += 128) {
        int k = idx >> 6, o = idx & 63;
        const float* w = hW1 + (size_t)(k * 64 + o) * 128;
        float acc = hb1[k * 64 + o];
        for (int j = 0; j < 128; ++j) acc = fmaf(w[j], p[j], acc);
        hh[idx] = fmaxf(acc, 0.f);
    }
    __syncthreads();
    if (t < 3) {
        float z = hb2[t];
        for (int o = 0; o < 64; ++o) z = fmaf(hW2[t * 64 + o], hh[t * 64 + o], z);
        outp[t * BB + b] = 1.f / (1.f + expf(-z));
    }
}

// ---------------- host ----------------
extern "C" void kernel_launch(void* const* d_in, const int* in_sizes, int n_in,
                              void* d_out, int out_size) {
    const float* nf = nullptr;
    const float* symf = nullptr;
    const int* ei = nullptr;
    const int* batch = nullptr;
    const float* P[26];
    int pi = 0;
    for (int i = 0; i < n_in; ++i) {
        int sz = in_sizes[i];
        if (sz == NN * HH)       nf    = (const float*)d_in[i];
        else if (sz == BB * 64)  symf  = (const float*)d_in[i];
        else if (sz == 2 * EE)   ei    = (const int*)d_in[i];
        else if (sz == NN)       batch = (const int*)d_in[i];
        else if (pi < 26)        P[pi++] = (const float*)d_in[i];
    }
    const float *W_in = P[0], *b_in = P[1], *sage_Wl = P[2], *sage_bl = P[3],
                *sage_Wr = P[4], *ln_g = P[5], *ln_b = P[6], *query = P[7],
                *in_proj_W = P[8], *in_proj_b = P[9], *out_W = P[10], *out_b = P[11],
                *sym_W = P[12], *sym_b = P[13], *symf_W = P[14], *symf_b = P[15],
                *symf_g = P[16], *symf_beta = P[17], *fus_W = P[18], *fus_b = P[19],
                *fus_g = P[20], *fus_beta = P[21], *hW1 = P[22], *hb1 = P[23],
                *hW2 = P[24], *hb2 = P[25];

    uint32_t *pxA, *pxB, *pag;
    float* pv;
    cudaGetSymbolAddress((void**)&pxA, g_xA);
    cudaGetSymbolAddress((void**)&pxB, g_xB);
    cudaGetSymbolAddress((void**)&pag, g_agg);
    cudaGetSymbolAddress((void**)&pv,  g_v);

    cudaFuncSetAttribute((const void*)k_mma<0>, cudaFuncAttributeMaxDynamicSharedMemorySize, SMEM_BYTES);
    cudaFuncSetAttribute((const void*)k_mma<1>, cudaFuncAttributeMaxDynamicSharedMemorySize, SMEM_BYTES);
    cudaFuncSetAttribute((const void*)k_mma<2>, cudaFuncAttributeMaxDynamicSharedMemorySize, SMEM_BYTES);

    // weight slots: 0=W_in, 1=Wl0, 2=Wr0, 3=Wl1, 4=Wr1, 5=Wl2, 6=Wr2, 7=Wv
    k_setup1<<<324, 256>>>(W_in,
                           sage_Wl + 0 * 16384, sage_Wr + 0 * 16384,
                           sage_Wl + 1 * 16384, sage_Wr + 1 * 16384,
                           sage_Wl + 2 * 16384, sage_Wr + 2 * 16384,
                           in_proj_W + 256 * 128);
    k_deg<<<(EE + 255) / 256, 256>>>(ei);
    k_setup2<<<2 + (NN + 1023) / 1024, 1024>>>(in_proj_W, in_proj_b, query, batch);
    // index 3: input-proj GEMM (profiled sample slot)
    k_mma<0><<<TILES64, 512, SMEM_BYTES>>>(nf, nullptr, nullptr, 0, b_in,
                                           nullptr, nullptr, pxA, nullptr, NN);
    k_fill<<<(EE + 255) / 256, 256>>>(ei);

    uint32_t *cur = pxA, *nxt = pxB;
    for (int l = 0; l < 3; ++l) {
        k_aggr<<<(NN * 32 + 255) / 256, 256>>>(cur);
        k_mma<1><<<TILES64, 512, SMEM_BYTES>>>(nullptr, pag, cur, 1 + 2 * l,
                                               sage_bl + l * 128,
                                               ln_g + l * 128, ln_b + l * 128,
                                               nxt, nullptr, NN);
        uint32_t* tmp = cur; cur = nxt; nxt = tmp;
    }

    // v = x @ Wv^T + bv (fp32) + fused attention scores
    k_mma<2><<<TILES64, 512, SMEM_BYTES>>>(nullptr, cur, nullptr, 7, in_proj_b + 256,
                                           nullptr, nullptr, nullptr, pv, NN);

    k_pool_part<<<BB * SPLITS, 128>>>();
    k_tail<<<BB, 128>>>(out_W, out_b, symf, sym_W, sym_b,
                        symf_W, symf_b, symf_g, symf_beta,
                        fus_W, fus_b, fus_g, fus_beta,
                        hW1, hb1, hW2, hb2, (float*)d_out);
    (void)out_size;
}